// round 2
// baseline (speedup 1.0000x reference)
#include <cuda_runtime.h>

#define NN   12288
#define DIN  512
#define DEMB 128
#define DOUT 64
#define NE   393216
#define TOTE (NE + NN)     // 405504
#define NEG  0.2f

// ---------------- scratch (device globals; no allocation) ----------------
__device__ float d_x1[NN * DEMB];       // relu(x W_s1^T + b)        6.3 MB
__device__ float d_g[NN * DOUT];        // x1 W_g^T                  3.1 MB
__device__ float d_scs[NN];
__device__ float d_scd[NN];
__device__ float d_h[NN * DOUT];        // GAT output                3.1 MB
__device__ float d_xtraw[DIN * DEMB];   // x^T W_a1^T (pre-relu/bias)
__device__ float d_xa[DIN * DOUT];
__device__ int   d_deg[NN];
__device__ int   d_off[NN + 1];
__device__ int   d_fill[NN];
__device__ int   d_csr[TOTE];
__device__ int   d_is64;                // edge_index dtype flag

// ---------------- small helpers ----------------
__device__ __forceinline__ float sigf(float v) {
    return 1.0f / (1.0f + __expf(-v));
}
__device__ __forceinline__ int clampn(int v) {
    v = v < 0 ? 0 : v;
    return v >= NN ? NN - 1 : v;
}

// ---------------- dtype probe: int64 edge data has zero odd words ----------------
__global__ void k_detect(const int* __restrict__ ei32) {
    __shared__ int any;
    if (threadIdx.x == 0) any = 0;
    __syncthreads();
    if (ei32[threadIdx.x * 2 + 1] != 0) any = 1;   // benign race
    __syncthreads();
    if (threadIdx.x == 0) d_is64 = (any == 0) ? 1 : 0;
}

// ---------------- init: zero xtraw, deg=1 (self loop) ----------------
__global__ void k_init() {
    int t = blockIdx.x * blockDim.x + threadIdx.x;
    if (t < DIN * DEMB) d_xtraw[t] = 0.0f;
    if (t < NN) d_deg[t] = 1;
}

// ---------------- edge degree count ----------------
__global__ void k_count(const void* __restrict__ ei) {
    int e = blockIdx.x * blockDim.x + threadIdx.x;
    if (e < NE) {
        int dst;
        if (d_is64) dst = (int)((const long long*)ei)[NE + e];
        else        dst = ((const int*)ei)[NE + e];
        atomicAdd(&d_deg[clampn(dst)], 1);
    }
}

// ---------------- exclusive scan of degrees (single block) ----------------
__global__ void k_scan() {
    __shared__ int sh[1024];
    int t = threadIdx.x;
    int base = t * 12;
    int loc[12];
    int s = 0;
#pragma unroll
    for (int i = 0; i < 12; i++) { loc[i] = d_deg[base + i]; s += loc[i]; }
    sh[t] = s;
    __syncthreads();
    for (int d = 1; d < 1024; d <<= 1) {
        int v = (t >= d) ? sh[t - d] : 0;
        __syncthreads();
        sh[t] += v;
        __syncthreads();
    }
    int run = sh[t] - s;  // exclusive prefix
#pragma unroll
    for (int i = 0; i < 12; i++) {
        d_off[base + i]  = run;
        d_fill[base + i] = run;
        run += loc[i];
    }
    if (t == 1023) d_off[NN] = sh[1023];
}

// ---------------- scatter edges into CSR (by dst) ----------------
__global__ void k_scatter(const void* __restrict__ ei) {
    int e = blockIdx.x * blockDim.x + threadIdx.x;
    if (e < NE) {
        int src, dst;
        if (d_is64) {
            src = (int)((const long long*)ei)[e];
            dst = (int)((const long long*)ei)[NE + e];
        } else {
            src = ((const int*)ei)[e];
            dst = ((const int*)ei)[NE + e];
        }
        int p = atomicAdd(&d_fill[clampn(dst)], 1);
        if (p < TOTE) d_csr[p] = clampn(src);
    } else if (e < TOTE) {
        int n = e - NE;                 // self loop
        int p = atomicAdd(&d_fill[n], 1);
        if (p < TOTE) d_csr[p] = n;
    }
}

// ---------------- x1 = relu(x @ W_s1^T + b_s1)  [12288,512]x[512,128] ----------------
// BM=64, BN=128(full), BK=32, 256 thr, micro 4x8
__global__ __launch_bounds__(256) void k_fc1(const float* __restrict__ x,
                                             const float* __restrict__ W,
                                             const float* __restrict__ b) {
    __shared__ float As[32][68];    // [k][m]
    __shared__ float Bs[32][132];   // [k][n]
    int m0 = blockIdx.x * 64;
    int tid = threadIdx.x;
    int tx = tid & 15, ty = tid >> 4;
    float acc[4][8];
#pragma unroll
    for (int i = 0; i < 4; i++)
#pragma unroll
        for (int j = 0; j < 8; j++) acc[i][j] = 0.0f;

    for (int k0 = 0; k0 < 512; k0 += 32) {
#pragma unroll
        for (int t = 0; t < 2; t++) {                 // A: 64x32
            int slot = tid + t * 256;
            int m = slot & 63, kq = slot >> 6;
            float4 v = *(const float4*)&x[(size_t)(m0 + m) * 512 + k0 + kq * 4];
            As[kq * 4 + 0][m] = v.x; As[kq * 4 + 1][m] = v.y;
            As[kq * 4 + 2][m] = v.z; As[kq * 4 + 3][m] = v.w;
        }
#pragma unroll
        for (int t = 0; t < 4; t++) {                 // B: 128x32, B[n,k]=W[n*512+k]
            int slot = tid + t * 256;
            int n = slot & 127, kq = slot >> 7;
            float4 v = *(const float4*)&W[(size_t)n * 512 + k0 + kq * 4];
            Bs[kq * 4 + 0][n] = v.x; Bs[kq * 4 + 1][n] = v.y;
            Bs[kq * 4 + 2][n] = v.z; Bs[kq * 4 + 3][n] = v.w;
        }
        __syncthreads();
#pragma unroll
        for (int kk = 0; kk < 32; kk++) {
            float4 av = *(const float4*)&As[kk][ty * 4];
            float4 b0 = *(const float4*)&Bs[kk][tx * 8];
            float4 b1 = *(const float4*)&Bs[kk][tx * 8 + 4];
            float a[4] = {av.x, av.y, av.z, av.w};
            float bb[8] = {b0.x, b0.y, b0.z, b0.w, b1.x, b1.y, b1.z, b1.w};
#pragma unroll
            for (int i = 0; i < 4; i++)
#pragma unroll
                for (int j = 0; j < 8; j++) acc[i][j] = fmaf(a[i], bb[j], acc[i][j]);
        }
        __syncthreads();
    }
#pragma unroll
    for (int i = 0; i < 4; i++) {
        int row = m0 + ty * 4 + i;
#pragma unroll
        for (int j = 0; j < 8; j++) {
            int col = tx * 8 + j;
            float v = acc[i][j] + b[col];
            d_x1[(size_t)row * 128 + col] = v > 0.0f ? v : 0.0f;
        }
    }
}

// ---------------- g = x1 @ W_g^T  [12288,128]x[128,64] ----------------
__global__ __launch_bounds__(256) void k_g(const float* __restrict__ Wg) {
    __shared__ float As[32][68];
    __shared__ float Bs[32][68];
    int m0 = blockIdx.x * 64;
    int tid = threadIdx.x;
    int tx = tid & 15, ty = tid >> 4;
    float acc[4][4];
#pragma unroll
    for (int i = 0; i < 4; i++)
#pragma unroll
        for (int j = 0; j < 4; j++) acc[i][j] = 0.0f;

    for (int k0 = 0; k0 < 128; k0 += 32) {
#pragma unroll
        for (int t = 0; t < 2; t++) {                 // A 64x32 from d_x1
            int slot = tid + t * 256;
            int m = slot & 63, kq = slot >> 6;
            float4 v = *(const float4*)&d_x1[(size_t)(m0 + m) * 128 + k0 + kq * 4];
            As[kq * 4 + 0][m] = v.x; As[kq * 4 + 1][m] = v.y;
            As[kq * 4 + 2][m] = v.z; As[kq * 4 + 3][m] = v.w;
        }
#pragma unroll
        for (int t = 0; t < 2; t++) {                 // B 64x32, B[n,k]=Wg[n*128+k]
            int slot = tid + t * 256;
            int n = slot & 63, kq = slot >> 6;
            float4 v = *(const float4*)&Wg[(size_t)n * 128 + k0 + kq * 4];
            Bs[kq * 4 + 0][n] = v.x; Bs[kq * 4 + 1][n] = v.y;
            Bs[kq * 4 + 2][n] = v.z; Bs[kq * 4 + 3][n] = v.w;
        }
        __syncthreads();
#pragma unroll
        for (int kk = 0; kk < 32; kk++) {
            float4 av = *(const float4*)&As[kk][ty * 4];
            float4 bv = *(const float4*)&Bs[kk][tx * 4];
            float a[4] = {av.x, av.y, av.z, av.w};
            float bb[4] = {bv.x, bv.y, bv.z, bv.w};
#pragma unroll
            for (int i = 0; i < 4; i++)
#pragma unroll
                for (int j = 0; j < 4; j++) acc[i][j] = fmaf(a[i], bb[j], acc[i][j]);
        }
        __syncthreads();
    }
#pragma unroll
    for (int i = 0; i < 4; i++)
#pragma unroll
        for (int j = 0; j < 4; j++)
            d_g[(size_t)(m0 + ty * 4 + i) * 64 + tx * 4 + j] = acc[i][j];
}

// ---------------- attention scores per node ----------------
__global__ void k_sc(const float* __restrict__ asrc, const float* __restrict__ adst) {
    int warp = (blockIdx.x * blockDim.x + threadIdx.x) >> 5;
    int lane = threadIdx.x & 31;
    if (warp >= NN) return;
    float g0 = d_g[(size_t)warp * 64 + lane];
    float g1 = d_g[(size_t)warp * 64 + 32 + lane];
    float vs = g0 * asrc[lane] + g1 * asrc[32 + lane];
    float vd = g0 * adst[lane] + g1 * adst[32 + lane];
#pragma unroll
    for (int o = 16; o; o >>= 1) {
        vs += __shfl_xor_sync(0xffffffffu, vs, o);
        vd += __shfl_xor_sync(0xffffffffu, vd, o);
    }
    if (lane == 0) { d_scs[warp] = vs; d_scd[warp] = vd; }
}

// ---------------- GAT aggregation: one warp per node ----------------
__global__ void k_gat(const float* __restrict__ bg) {
    int warp = (blockIdx.x * blockDim.x + threadIdx.x) >> 5;
    int lane = threadIdx.x & 31;
    if (warp >= NN) return;
    int s0 = d_off[warp], s1 = d_off[warp + 1];
    float scd = d_scd[warp];

    float mx = -1e30f;
    for (int j = s0 + lane; j < s1; j += 32) {
        int s = d_csr[j];
        float e = d_scs[s] + scd;
        e = e > 0.0f ? e : NEG * e;
        mx = fmaxf(mx, e);
    }
#pragma unroll
    for (int o = 16; o; o >>= 1) mx = fmaxf(mx, __shfl_xor_sync(0xffffffffu, mx, o));

    float sum = 0.0f;
    for (int j = s0 + lane; j < s1; j += 32) {
        int s = d_csr[j];
        float e = d_scs[s] + scd;
        e = e > 0.0f ? e : NEG * e;
        sum += __expf(e - mx);
    }
#pragma unroll
    for (int o = 16; o; o >>= 1) sum += __shfl_xor_sync(0xffffffffu, sum, o);
    float inv = 1.0f / sum;

    float a0 = 0.0f, a1 = 0.0f;
    for (int j = s0; j < s1; j++) {
        int s = d_csr[j];                    // broadcast load
        float e = d_scs[s] + scd;
        e = e > 0.0f ? e : NEG * e;
        float w = __expf(e - mx) * inv;
        a0 = fmaf(w, d_g[(size_t)s * 64 + lane], a0);
        a1 = fmaf(w, d_g[(size_t)s * 64 + 32 + lane], a1);
    }
    d_h[(size_t)warp * 64 + lane]      = a0 + bg[lane];
    d_h[(size_t)warp * 64 + 32 + lane] = a1 + bg[32 + lane];
}

// ---------------- s_ = sigmoid(h h^T): BM=BN=128, K=64, micro 8x8 ----------------
__global__ __launch_bounds__(256, 2) void k_s(float* __restrict__ out) {
    __shared__ float As[32][132];
    __shared__ float Bs[32][132];
    int i0 = blockIdx.y * 128;
    int j0 = blockIdx.x * 128;
    int tid = threadIdx.x;
    int tx = tid & 15, ty = tid >> 4;
    float acc[8][8];
#pragma unroll
    for (int i = 0; i < 8; i++)
#pragma unroll
        for (int j = 0; j < 8; j++) acc[i][j] = 0.0f;

    for (int k0 = 0; k0 < 64; k0 += 32) {
#pragma unroll
        for (int t = 0; t < 4; t++) {
            int slot = tid + t * 256;
            int m = slot & 127, kq = slot >> 7;
            float4 v = *(const float4*)&d_h[(size_t)(i0 + m) * 64 + k0 + kq * 4];
            As[kq * 4 + 0][m] = v.x; As[kq * 4 + 1][m] = v.y;
            As[kq * 4 + 2][m] = v.z; As[kq * 4 + 3][m] = v.w;
        }
#pragma unroll
        for (int t = 0; t < 4; t++) {
            int slot = tid + t * 256;
            int m = slot & 127, kq = slot >> 7;
            float4 v = *(const float4*)&d_h[(size_t)(j0 + m) * 64 + k0 + kq * 4];
            Bs[kq * 4 + 0][m] = v.x; Bs[kq * 4 + 1][m] = v.y;
            Bs[kq * 4 + 2][m] = v.z; Bs[kq * 4 + 3][m] = v.w;
        }
        __syncthreads();
#pragma unroll
        for (int kk = 0; kk < 32; kk++) {
            float4 a0 = *(const float4*)&As[kk][ty * 8];
            float4 a1 = *(const float4*)&As[kk][ty * 8 + 4];
            float4 b0 = *(const float4*)&Bs[kk][tx * 8];
            float4 b1 = *(const float4*)&Bs[kk][tx * 8 + 4];
            float a[8] = {a0.x, a0.y, a0.z, a0.w, a1.x, a1.y, a1.z, a1.w};
            float b[8] = {b0.x, b0.y, b0.z, b0.w, b1.x, b1.y, b1.z, b1.w};
#pragma unroll
            for (int i = 0; i < 8; i++)
#pragma unroll
                for (int j = 0; j < 8; j++) acc[i][j] = fmaf(a[i], b[j], acc[i][j]);
        }
        __syncthreads();
    }
#pragma unroll
    for (int i = 0; i < 8; i++) {
        size_t row = (size_t)(i0 + ty * 8 + i);
        float4 v0, v1;
        v0.x = sigf(acc[i][0]); v0.y = sigf(acc[i][1]);
        v0.z = sigf(acc[i][2]); v0.w = sigf(acc[i][3]);
        v1.x = sigf(acc[i][4]); v1.y = sigf(acc[i][5]);
        v1.z = sigf(acc[i][6]); v1.w = sigf(acc[i][7]);
        *(float4*)&out[row * NN + j0 + tx * 8]     = v0;
        *(float4*)&out[row * NN + j0 + tx * 8 + 4] = v1;
    }
}

// ---------------- xtraw[d,e] += sum_k x[k,d]*W_a1[e,k]  (split-K) ----------------
__global__ __launch_bounds__(256) void k_att1(const float* __restrict__ x,
                                              const float* __restrict__ W) {
    __shared__ float As[32][68];    // [k][d]
    __shared__ float Bs[32][132];   // [k][e]
    int d0 = blockIdx.x * 64;
    int kbase = blockIdx.y * 256;
    int tid = threadIdx.x;
    int tx = tid & 15, ty = tid >> 4;
    float acc[4][8];
#pragma unroll
    for (int i = 0; i < 4; i++)
#pragma unroll
        for (int j = 0; j < 8; j++) acc[i][j] = 0.0f;

    for (int kc = 0; kc < 256; kc += 32) {
        int k0 = kbase + kc;
#pragma unroll
        for (int t = 0; t < 2; t++) {                 // A[k,d] = x[k*512+d]
            int slot = tid + t * 256;
            int kk = slot >> 4, dq = slot & 15;
            float4 v = *(const float4*)&x[(size_t)(k0 + kk) * 512 + d0 + dq * 4];
            *(float4*)&As[kk][dq * 4] = v;
        }
#pragma unroll
        for (int t = 0; t < 4; t++) {                 // B[e,k] = W_a1[e*12288+k]
            int slot = tid + t * 256;
            int n = slot & 127, kq = slot >> 7;
            float4 v = *(const float4*)&W[(size_t)n * NN + k0 + kq * 4];
            Bs[kq * 4 + 0][n] = v.x; Bs[kq * 4 + 1][n] = v.y;
            Bs[kq * 4 + 2][n] = v.z; Bs[kq * 4 + 3][n] = v.w;
        }
        __syncthreads();
#pragma unroll
        for (int kk = 0; kk < 32; kk++) {
            float4 av = *(const float4*)&As[kk][ty * 4];
            float4 b0 = *(const float4*)&Bs[kk][tx * 8];
            float4 b1 = *(const float4*)&Bs[kk][tx * 8 + 4];
            float a[4] = {av.x, av.y, av.z, av.w};
            float bb[8] = {b0.x, b0.y, b0.z, b0.w, b1.x, b1.y, b1.z, b1.w};
#pragma unroll
            for (int i = 0; i < 4; i++)
#pragma unroll
                for (int j = 0; j < 8; j++) acc[i][j] = fmaf(a[i], bb[j], acc[i][j]);
        }
        __syncthreads();
    }
#pragma unroll
    for (int i = 0; i < 4; i++)
#pragma unroll
        for (int j = 0; j < 8; j++)
            atomicAdd(&d_xtraw[(size_t)(d0 + ty * 4 + i) * 128 + tx * 8 + j], acc[i][j]);
}

// ---------------- xa = relu(xtraw + b_a1) @ W_a2^T + b_a2 ----------------
__global__ void k_xa(const float* __restrict__ ba1, const float* __restrict__ W2,
                     const float* __restrict__ ba2) {
    int t = blockIdx.x * blockDim.x + threadIdx.x;
    if (t >= DIN * DOUT) return;
    int d = t >> 6, o = t & 63;
    float s = 0.0f;
#pragma unroll 4
    for (int e = 0; e < 128; e++) {
        float v = d_xtraw[(size_t)d * 128 + e] + ba1[e];
        v = v > 0.0f ? v : 0.0f;
        s = fmaf(v, W2[(size_t)o * 128 + e], s);
    }
    d_xa[t] = s + ba2[o];
}

// ---------------- x_ = h @ xa^T  [12288,64]x[64,512] ----------------
__global__ __launch_bounds__(256) void k_xout(float* __restrict__ out) {
    __shared__ float As[32][68];
    __shared__ float Bs[32][132];
    int m0 = blockIdx.x * 64;
    int d0 = blockIdx.y * 128;
    int tid = threadIdx.x;
    int tx = tid & 15, ty = tid >> 4;
    float acc[4][8];
#pragma unroll
    for (int i = 0; i < 4; i++)
#pragma unroll
        for (int j = 0; j < 8; j++) acc[i][j] = 0.0f;

    for (int k0 = 0; k0 < 64; k0 += 32) {
#pragma unroll
        for (int t = 0; t < 2; t++) {                 // A = h[m*64+k]
            int slot = tid + t * 256;
            int m = slot & 63, kq = slot >> 6;
            float4 v = *(const float4*)&d_h[(size_t)(m0 + m) * 64 + k0 + kq * 4];
            As[kq * 4 + 0][m] = v.x; As[kq * 4 + 1][m] = v.y;
            As[kq * 4 + 2][m] = v.z; As[kq * 4 + 3][m] = v.w;
        }
#pragma unroll
        for (int t = 0; t < 4; t++) {                 // B[d,k] = xa[d*64+k]
            int slot = tid + t * 256;
            int n = slot & 127, kq = slot >> 7;
            float4 v = *(const float4*)&d_xa[(size_t)(d0 + n) * 64 + k0 + kq * 4];
            Bs[kq * 4 + 0][n] = v.x; Bs[kq * 4 + 1][n] = v.y;
            Bs[kq * 4 + 2][n] = v.z; Bs[kq * 4 + 3][n] = v.w;
        }
        __syncthreads();
#pragma unroll
        for (int kk = 0; kk < 32; kk++) {
            float4 av = *(const float4*)&As[kk][ty * 4];
            float4 b0 = *(const float4*)&Bs[kk][tx * 8];
            float4 b1 = *(const float4*)&Bs[kk][tx * 8 + 4];
            float a[4] = {av.x, av.y, av.z, av.w};
            float bb[8] = {b0.x, b0.y, b0.z, b0.w, b1.x, b1.y, b1.z, b1.w};
#pragma unroll
            for (int i = 0; i < 4; i++)
#pragma unroll
                for (int j = 0; j < 8; j++) acc[i][j] = fmaf(a[i], bb[j], acc[i][j]);
        }
        __syncthreads();
    }
#pragma unroll
    for (int i = 0; i < 4; i++) {
        size_t row = (size_t)(m0 + ty * 4 + i);
        float4 v0 = {acc[i][0], acc[i][1], acc[i][2], acc[i][3]};
        float4 v1 = {acc[i][4], acc[i][5], acc[i][6], acc[i][7]};
        *(float4*)&out[row * 512 + d0 + tx * 8]     = v0;
        *(float4*)&out[row * 512 + d0 + tx * 8 + 4] = v1;
    }
}

// ---------------- launch ----------------
extern "C" void kernel_launch(void* const* d_in, const int* in_sizes, int n_in,
                              void* d_out, int out_size) {
    const float* x     = (const float*)d_in[0];
    const float* Ws1   = (const float*)d_in[1];
    const float* bs1   = (const float*)d_in[2];
    const float* Wg    = (const float*)d_in[3];
    const float* asrc  = (const float*)d_in[4];
    const float* adst  = (const float*)d_in[5];
    const float* bg    = (const float*)d_in[6];
    const float* Wa1   = (const float*)d_in[7];
    const float* ba1   = (const float*)d_in[8];
    const float* Wa2   = (const float*)d_in[9];
    const float* ba2   = (const float*)d_in[10];
    const void*  ei    = d_in[11];
    // d_in[12] = batch_size (== NN), unused

    float* out   = (float*)d_out;
    float* out_x = out;                          // [12288, 512]
    float* out_s = out + (size_t)NN * DIN;       // [12288, 12288]

    // CSR build for GAT
    k_detect<<<1, 256>>>((const int*)ei);
    k_init<<<256, 256>>>();
    k_count<<<NE / 256, 256>>>(ei);
    k_scan<<<1, 1024>>>();
    k_scatter<<<TOTE / 256, 256>>>(ei);

    // encoder + GAT
    k_fc1<<<NN / 64, 256>>>(x, Ws1, bs1);
    k_g<<<NN / 64, 256>>>(Wg);
    k_sc<<<NN / 8, 256>>>(asrc, adst);
    k_gat<<<NN / 8, 256>>>(bg);

    // structure decoder (dominant)
    k_s<<<dim3(NN / 128, NN / 128), 256>>>(out_s);

    // attribute decoder
    k_att1<<<dim3(DIN / 64, 48), 256>>>(x, Wa1);
    k_xa<<<(DIN * DOUT) / 256, 256>>>(ba1, Wa2, ba2);
    k_xout<<<dim3(NN / 64, DIN / 128), 256>>>(out_x);
}

// round 5
// speedup vs baseline: 1.3748x; 1.3748x over previous
#include <cuda_runtime.h>
#include <cuda_bf16.h>
#include <cstdint>

#define NN   12288
#define DIN  512
#define DEMB 128
#define DOUT 64
#define NE   393216
#define TOTE (NE + NN)     // 405504
#define NEG  0.2f

// ---------------- scratch (device globals; no allocation) ----------------
__device__ float d_x1[NN * DEMB];
__device__ float d_g[NN * DOUT];
__device__ float d_scs[NN];
__device__ float d_scd[NN];
__device__ float d_h[NN * DOUT];
__device__ __nv_bfloat16 d_hhi[NN * DOUT];
__device__ __nv_bfloat16 d_hlo[NN * DOUT];
__device__ float d_xtraw[DIN * DEMB];
__device__ float d_xa[DIN * DOUT];
__device__ int   d_deg[NN];
__device__ int   d_off[NN + 1];
__device__ int   d_fill[NN];
__device__ int   d_csr[TOTE];
__device__ int   d_is64;

// ---------------- helpers ----------------
__device__ __forceinline__ float sigf(float v) {
    return 1.0f / (1.0f + __expf(-v));
}
__device__ __forceinline__ int clampn(int v) {
    v = v < 0 ? 0 : v;
    return v >= NN ? NN - 1 : v;
}
__device__ __forceinline__ uint32_t smem_u32(const void* p) {
    return (uint32_t)__cvta_generic_to_shared(p);
}
__device__ __forceinline__ void ldm_x4(uint32_t& r0, uint32_t& r1, uint32_t& r2,
                                       uint32_t& r3, uint32_t addr) {
    asm volatile("ldmatrix.sync.aligned.m8n8.x4.shared.b16 {%0,%1,%2,%3}, [%4];"
                 : "=r"(r0), "=r"(r1), "=r"(r2), "=r"(r3) : "r"(addr));
}
__device__ __forceinline__ void mma_bf16(float* c, const uint32_t* a, const uint32_t* b) {
    asm volatile(
        "mma.sync.aligned.m16n8k16.row.col.f32.bf16.bf16.f32 "
        "{%0,%1,%2,%3}, {%4,%5,%6,%7}, {%8,%9}, {%0,%1,%2,%3};"
        : "+f"(c[0]), "+f"(c[1]), "+f"(c[2]), "+f"(c[3])
        : "r"(a[0]), "r"(a[1]), "r"(a[2]), "r"(a[3]), "r"(b[0]), "r"(b[1]));
}

// ---------------- dtype probe ----------------
__global__ void k_detect(const int* __restrict__ ei32) {
    __shared__ int any;
    if (threadIdx.x == 0) any = 0;
    __syncthreads();
    if (ei32[threadIdx.x * 2 + 1] != 0) any = 1;
    __syncthreads();
    if (threadIdx.x == 0) d_is64 = (any == 0) ? 1 : 0;
}

__global__ void k_init() {
    int t = blockIdx.x * blockDim.x + threadIdx.x;
    if (t < DIN * DEMB) d_xtraw[t] = 0.0f;
    if (t < NN) d_deg[t] = 1;
}

__global__ void k_count(const void* __restrict__ ei) {
    int e = blockIdx.x * blockDim.x + threadIdx.x;
    if (e < NE) {
        int dst;
        if (d_is64) dst = (int)((const long long*)ei)[NE + e];
        else        dst = ((const int*)ei)[NE + e];
        atomicAdd(&d_deg[clampn(dst)], 1);
    }
}

// warp-shuffle scan (12 values/thread, 1024 threads)
__global__ void k_scan() {
    __shared__ int wsum[32];
    int t = threadIdx.x, lane = t & 31, w = t >> 5;
    int base = t * 12;
    int loc[12];
    int s = 0;
#pragma unroll
    for (int i = 0; i < 12; i++) { loc[i] = d_deg[base + i]; s += loc[i]; }
    int pre = s;
#pragma unroll
    for (int o = 1; o < 32; o <<= 1) {
        int v = __shfl_up_sync(0xffffffffu, pre, o);
        if (lane >= o) pre += v;
    }
    if (lane == 31) wsum[w] = pre;
    __syncthreads();
    if (w == 0) {
        int v = wsum[lane];
#pragma unroll
        for (int o = 1; o < 32; o <<= 1) {
            int u = __shfl_up_sync(0xffffffffu, v, o);
            if (lane >= o) v += u;
        }
        wsum[lane] = v;
    }
    __syncthreads();
    int run = pre - s + (w ? wsum[w - 1] : 0);
#pragma unroll
    for (int i = 0; i < 12; i++) {
        d_off[base + i]  = run;
        d_fill[base + i] = run;
        run += loc[i];
    }
    if (t == 1023) d_off[NN] = run;
}

__global__ void k_scatter(const void* __restrict__ ei) {
    int e = blockIdx.x * blockDim.x + threadIdx.x;
    if (e < NE) {
        int src, dst;
        if (d_is64) {
            src = (int)((const long long*)ei)[e];
            dst = (int)((const long long*)ei)[NE + e];
        } else {
            src = ((const int*)ei)[e];
            dst = ((const int*)ei)[NE + e];
        }
        int p = atomicAdd(&d_fill[clampn(dst)], 1);
        if (p < TOTE) d_csr[p] = clampn(src);
    } else if (e < TOTE) {
        int n = e - NE;
        int p = atomicAdd(&d_fill[n], 1);
        if (p < TOTE) d_csr[p] = n;
    }
}

// ---------------- x1 = relu(x @ W_s1^T + b_s1) ----------------
__global__ __launch_bounds__(256) void k_fc1(const float* __restrict__ x,
                                             const float* __restrict__ W,
                                             const float* __restrict__ b) {
    __shared__ float As[32][68];
    __shared__ float Bs[32][132];
    int m0 = blockIdx.x * 64;
    int tid = threadIdx.x;
    int tx = tid & 15, ty = tid >> 4;
    float acc[4][8];
#pragma unroll
    for (int i = 0; i < 4; i++)
#pragma unroll
        for (int j = 0; j < 8; j++) acc[i][j] = 0.0f;

    for (int k0 = 0; k0 < 512; k0 += 32) {
#pragma unroll
        for (int t = 0; t < 2; t++) {
            int slot = tid + t * 256;
            int m = slot & 63, kq = slot >> 6;
            float4 v = *(const float4*)&x[(size_t)(m0 + m) * 512 + k0 + kq * 4];
            As[kq * 4 + 0][m] = v.x; As[kq * 4 + 1][m] = v.y;
            As[kq * 4 + 2][m] = v.z; As[kq * 4 + 3][m] = v.w;
        }
#pragma unroll
        for (int t = 0; t < 4; t++) {
            int slot = tid + t * 256;
            int n = slot & 127, kq = slot >> 7;
            float4 v = *(const float4*)&W[(size_t)n * 512 + k0 + kq * 4];
            Bs[kq * 4 + 0][n] = v.x; Bs[kq * 4 + 1][n] = v.y;
            Bs[kq * 4 + 2][n] = v.z; Bs[kq * 4 + 3][n] = v.w;
        }
        __syncthreads();
#pragma unroll
        for (int kk = 0; kk < 32; kk++) {
            float4 av = *(const float4*)&As[kk][ty * 4];
            float4 b0 = *(const float4*)&Bs[kk][tx * 8];
            float4 b1 = *(const float4*)&Bs[kk][tx * 8 + 4];
            float a[4] = {av.x, av.y, av.z, av.w};
            float bb[8] = {b0.x, b0.y, b0.z, b0.w, b1.x, b1.y, b1.z, b1.w};
#pragma unroll
            for (int i = 0; i < 4; i++)
#pragma unroll
                for (int j = 0; j < 8; j++) acc[i][j] = fmaf(a[i], bb[j], acc[i][j]);
        }
        __syncthreads();
    }
#pragma unroll
    for (int i = 0; i < 4; i++) {
        int row = m0 + ty * 4 + i;
#pragma unroll
        for (int j = 0; j < 8; j++) {
            int col = tx * 8 + j;
            float v = acc[i][j] + b[col];
            d_x1[(size_t)row * 128 + col] = v > 0.0f ? v : 0.0f;
        }
    }
}

// ---------------- g = x1 @ W_g^T ----------------
__global__ __launch_bounds__(256) void k_g(const float* __restrict__ Wg) {
    __shared__ float As[32][68];
    __shared__ float Bs[32][68];
    int m0 = blockIdx.x * 64;
    int tid = threadIdx.x;
    int tx = tid & 15, ty = tid >> 4;
    float acc[4][4];
#pragma unroll
    for (int i = 0; i < 4; i++)
#pragma unroll
        for (int j = 0; j < 4; j++) acc[i][j] = 0.0f;

    for (int k0 = 0; k0 < 128; k0 += 32) {
#pragma unroll
        for (int t = 0; t < 2; t++) {
            int slot = tid + t * 256;
            int m = slot & 63, kq = slot >> 6;
            float4 v = *(const float4*)&d_x1[(size_t)(m0 + m) * 128 + k0 + kq * 4];
            As[kq * 4 + 0][m] = v.x; As[kq * 4 + 1][m] = v.y;
            As[kq * 4 + 2][m] = v.z; As[kq * 4 + 3][m] = v.w;
        }
#pragma unroll
        for (int t = 0; t < 2; t++) {
            int slot = tid + t * 256;
            int n = slot & 63, kq = slot >> 6;
            float4 v = *(const float4*)&Wg[(size_t)n * 128 + k0 + kq * 4];
            Bs[kq * 4 + 0][n] = v.x; Bs[kq * 4 + 1][n] = v.y;
            Bs[kq * 4 + 2][n] = v.z; Bs[kq * 4 + 3][n] = v.w;
        }
        __syncthreads();
#pragma unroll
        for (int kk = 0; kk < 32; kk++) {
            float4 av = *(const float4*)&As[kk][ty * 4];
            float4 bv = *(const float4*)&Bs[kk][tx * 4];
            float a[4] = {av.x, av.y, av.z, av.w};
            float bb[4] = {bv.x, bv.y, bv.z, bv.w};
#pragma unroll
            for (int i = 0; i < 4; i++)
#pragma unroll
                for (int j = 0; j < 4; j++) acc[i][j] = fmaf(a[i], bb[j], acc[i][j]);
        }
        __syncthreads();
    }
#pragma unroll
    for (int i = 0; i < 4; i++)
#pragma unroll
        for (int j = 0; j < 4; j++)
            d_g[(size_t)(m0 + ty * 4 + i) * 64 + tx * 4 + j] = acc[i][j];
}

// ---------------- attention scores ----------------
__global__ void k_sc(const float* __restrict__ asrc, const float* __restrict__ adst) {
    int warp = (blockIdx.x * blockDim.x + threadIdx.x) >> 5;
    int lane = threadIdx.x & 31;
    if (warp >= NN) return;
    float g0 = d_g[(size_t)warp * 64 + lane];
    float g1 = d_g[(size_t)warp * 64 + 32 + lane];
    float vs = g0 * asrc[lane] + g1 * asrc[32 + lane];
    float vd = g0 * adst[lane] + g1 * adst[32 + lane];
#pragma unroll
    for (int o = 16; o; o >>= 1) {
        vs += __shfl_xor_sync(0xffffffffu, vs, o);
        vd += __shfl_xor_sync(0xffffffffu, vd, o);
    }
    if (lane == 0) { d_scs[warp] = vs; d_scd[warp] = vd; }
}

// ---------------- GAT aggregation ----------------
__global__ void k_gat(const float* __restrict__ bg) {
    int warp = (blockIdx.x * blockDim.x + threadIdx.x) >> 5;
    int lane = threadIdx.x & 31;
    if (warp >= NN) return;
    int s0 = d_off[warp], s1 = d_off[warp + 1];
    float scd = d_scd[warp];

    float mx = -1e30f;
    for (int j = s0 + lane; j < s1; j += 32) {
        int s = d_csr[j];
        float e = d_scs[s] + scd;
        e = e > 0.0f ? e : NEG * e;
        mx = fmaxf(mx, e);
    }
#pragma unroll
    for (int o = 16; o; o >>= 1) mx = fmaxf(mx, __shfl_xor_sync(0xffffffffu, mx, o));

    float sum = 0.0f;
    for (int j = s0 + lane; j < s1; j += 32) {
        int s = d_csr[j];
        float e = d_scs[s] + scd;
        e = e > 0.0f ? e : NEG * e;
        sum += __expf(e - mx);
    }
#pragma unroll
    for (int o = 16; o; o >>= 1) sum += __shfl_xor_sync(0xffffffffu, sum, o);
    float inv = 1.0f / sum;

    float a0 = 0.0f, a1 = 0.0f;
    for (int j = s0; j < s1; j++) {
        int s = d_csr[j];
        float e = d_scs[s] + scd;
        e = e > 0.0f ? e : NEG * e;
        float w = __expf(e - mx) * inv;
        a0 = fmaf(w, d_g[(size_t)s * 64 + lane], a0);
        a1 = fmaf(w, d_g[(size_t)s * 64 + 32 + lane], a1);
    }
    d_h[(size_t)warp * 64 + lane]      = a0 + bg[lane];
    d_h[(size_t)warp * 64 + 32 + lane] = a1 + bg[32 + lane];
}

// ---------------- split h into bf16 hi/lo ----------------
__global__ void k_split() {
    int t = blockIdx.x * blockDim.x + threadIdx.x;
    float h = d_h[t];
    __nv_bfloat16 hi = __float2bfloat16(h);
    d_hhi[t] = hi;
    d_hlo[t] = __float2bfloat16(h - __bfloat162float(hi));
}

// ---------------- s_ = sigmoid(h h^T) via bf16 mma + symmetry ----------------
// Tile 128(m) x 64(n), 8 warps (2m x 4n), warp tile 64x16.
// Compute only tiles with jt >= 2*it; mirror tiles with jt >= 2*it+2.
// Operands read DIRECTLY from device globals d_hhi/d_hlo (NOT via host-cast args).
#define PITCH 72   // halves
#define CP    68   // floats, Cs pitch
__global__ __launch_bounds__(256) void k_s_tc(float* __restrict__ out) {
    int it = blockIdx.y, jt = blockIdx.x;
    if (jt < 2 * it) return;
    extern __shared__ __nv_bfloat16 sm[];
    __nv_bfloat16* sAh = sm;                 // 128*72
    __nv_bfloat16* sAl = sm + 9216;
    __nv_bfloat16* sBh = sm + 18432;         // 64*72
    __nv_bfloat16* sBl = sm + 23040;
    float* Cs = (float*)sm;                  // reused after compute, [128][CP]

    int i0 = it * 128, j0 = jt * 64;
    int tid = threadIdx.x;

#pragma unroll
    for (int r = 0; r < 4; r++) {
        int idx = tid + r * 256;
        int row = idx >> 3, ch = idx & 7;
        *(uint4*)&sAh[row * PITCH + ch * 8] =
            ((const uint4*)(d_hhi + (size_t)(i0 + row) * 64))[ch];
        *(uint4*)&sAl[row * PITCH + ch * 8] =
            ((const uint4*)(d_hlo + (size_t)(i0 + row) * 64))[ch];
    }
#pragma unroll
    for (int r = 0; r < 2; r++) {
        int idx = tid + r * 256;
        int row = idx >> 3, ch = idx & 7;
        *(uint4*)&sBh[row * PITCH + ch * 8] =
            ((const uint4*)(d_hhi + (size_t)(j0 + row) * 64))[ch];
        *(uint4*)&sBl[row * PITCH + ch * 8] =
            ((const uint4*)(d_hlo + (size_t)(j0 + row) * 64))[ch];
    }
    __syncthreads();

    int wid = tid >> 5, lane = tid & 31;
    int warp_m = (wid >> 2) * 64;
    int warp_n = (wid & 3) * 16;

    float acc[4][2][4];
#pragma unroll
    for (int a = 0; a < 4; a++)
#pragma unroll
        for (int b = 0; b < 2; b++)
#pragma unroll
            for (int c = 0; c < 4; c++) acc[a][b][c] = 0.0f;

    int a_row = lane & 15;
    int a_kc  = (lane >> 4) << 3;
    int b_row = (lane & 7) + (((lane >> 4) & 1) << 3);
    int b_kc  = (((lane >> 3) & 1) << 3);

#pragma unroll
    for (int ks = 0; ks < 4; ks++) {
        int k0 = ks * 16;
        uint32_t Ah[4][4], Bh[4], Bl[4];
#pragma unroll
        for (int mt = 0; mt < 4; mt++)
            ldm_x4(Ah[mt][0], Ah[mt][1], Ah[mt][2], Ah[mt][3],
                   smem_u32(&sAh[(warp_m + mt * 16 + a_row) * PITCH + k0 + a_kc]));
        ldm_x4(Bh[0], Bh[1], Bh[2], Bh[3],
               smem_u32(&sBh[(warp_n + b_row) * PITCH + k0 + b_kc]));
        ldm_x4(Bl[0], Bl[1], Bl[2], Bl[3],
               smem_u32(&sBl[(warp_n + b_row) * PITCH + k0 + b_kc]));
#pragma unroll
        for (int mt = 0; mt < 4; mt++) {
            mma_bf16(acc[mt][0], Ah[mt], &Bh[0]);   // hi*hi
            mma_bf16(acc[mt][1], Ah[mt], &Bh[2]);
            mma_bf16(acc[mt][0], Ah[mt], &Bl[0]);   // hi*lo
            mma_bf16(acc[mt][1], Ah[mt], &Bl[2]);
        }
#pragma unroll
        for (int mt = 0; mt < 4; mt++) {
            uint32_t Al[4];
            ldm_x4(Al[0], Al[1], Al[2], Al[3],
                   smem_u32(&sAl[(warp_m + mt * 16 + a_row) * PITCH + k0 + a_kc]));
            mma_bf16(acc[mt][0], Al, &Bh[0]);       // lo*hi
            mma_bf16(acc[mt][1], Al, &Bh[2]);
        }
    }
    __syncthreads();   // done with operand smem

    // stage sigmoid(acc) into Cs [128][CP]
#pragma unroll
    for (int mt = 0; mt < 4; mt++) {
        int r0 = warp_m + mt * 16 + (lane >> 2);
#pragma unroll
        for (int nt = 0; nt < 2; nt++) {
            int c0 = warp_n + nt * 8 + ((lane & 3) << 1);
            Cs[r0 * CP + c0]           = sigf(acc[mt][nt][0]);
            Cs[r0 * CP + c0 + 1]       = sigf(acc[mt][nt][1]);
            Cs[(r0 + 8) * CP + c0]     = sigf(acc[mt][nt][2]);
            Cs[(r0 + 8) * CP + c0 + 1] = sigf(acc[mt][nt][3]);
        }
    }
    __syncthreads();

    // direct write (i0.., j0..): 128 x 64
    {
        int row = tid >> 1, half = tid & 1;
        float* dst = out + (size_t)(i0 + row) * NN + j0 + half * 32;
        const float* src = &Cs[row * CP + half * 32];
#pragma unroll
        for (int q = 0; q < 8; q++)
            ((float4*)dst)[q] = ((const float4*)src)[q];
    }
    // mirror write (j0.., i0..): 64 x 128 (skip diagonal-band tiles)
    if (jt >= 2 * it + 2) {
        int c = tid >> 2, q = tid & 3;
        float* dst = out + (size_t)(j0 + c) * NN + i0 + q * 32;
#pragma unroll
        for (int g = 0; g < 8; g++) {
            int r = q * 32 + g * 4;
            float4 v;
            v.x = Cs[(r + 0) * CP + c];
            v.y = Cs[(r + 1) * CP + c];
            v.z = Cs[(r + 2) * CP + c];
            v.w = Cs[(r + 3) * CP + c];
            ((float4*)dst)[g] = v;
        }
    }
}

// ---------------- xtraw split-K ----------------
__global__ __launch_bounds__(256) void k_att1(const float* __restrict__ x,
                                              const float* __restrict__ W) {
    __shared__ float As[32][68];
    __shared__ float Bs[32][132];
    int d0 = blockIdx.x * 64;
    int kbase = blockIdx.y * 256;
    int tid = threadIdx.x;
    int tx = tid & 15, ty = tid >> 4;
    float acc[4][8];
#pragma unroll
    for (int i = 0; i < 4; i++)
#pragma unroll
        for (int j = 0; j < 8; j++) acc[i][j] = 0.0f;

    for (int kc = 0; kc < 256; kc += 32) {
        int k0 = kbase + kc;
#pragma unroll
        for (int t = 0; t < 2; t++) {
            int slot = tid + t * 256;
            int kk = slot >> 4, dq = slot & 15;
            float4 v = *(const float4*)&x[(size_t)(k0 + kk) * 512 + d0 + dq * 4];
            *(float4*)&As[kk][dq * 4] = v;
        }
#pragma unroll
        for (int t = 0; t < 4; t++) {
            int slot = tid + t * 256;
            int n = slot & 127, kq = slot >> 7;
            float4 v = *(const float4*)&W[(size_t)n * NN + k0 + kq * 4];
            Bs[kq * 4 + 0][n] = v.x; Bs[kq * 4 + 1][n] = v.y;
            Bs[kq * 4 + 2][n] = v.z; Bs[kq * 4 + 3][n] = v.w;
        }
        __syncthreads();
#pragma unroll
        for (int kk = 0; kk < 32; kk++) {
            float4 av = *(const float4*)&As[kk][ty * 4];
            float4 b0 = *(const float4*)&Bs[kk][tx * 8];
            float4 b1 = *(const float4*)&Bs[kk][tx * 8 + 4];
            float a[4] = {av.x, av.y, av.z, av.w};
            float bb[8] = {b0.x, b0.y, b0.z, b0.w, b1.x, b1.y, b1.z, b1.w};
#pragma unroll
            for (int i = 0; i < 4; i++)
#pragma unroll
                for (int j = 0; j < 8; j++) acc[i][j] = fmaf(a[i], bb[j], acc[i][j]);
        }
        __syncthreads();
    }
#pragma unroll
    for (int i = 0; i < 4; i++)
#pragma unroll
        for (int j = 0; j < 8; j++)
            atomicAdd(&d_xtraw[(size_t)(d0 + ty * 4 + i) * 128 + tx * 8 + j], acc[i][j]);
}

__global__ void k_xa(const float* __restrict__ ba1, const float* __restrict__ W2,
                     const float* __restrict__ ba2) {
    int t = blockIdx.x * blockDim.x + threadIdx.x;
    if (t >= DIN * DOUT) return;
    int d = t >> 6, o = t & 63;
    float s = 0.0f;
#pragma unroll 4
    for (int e = 0; e < 128; e++) {
        float v = d_xtraw[(size_t)d * 128 + e] + ba1[e];
        v = v > 0.0f ? v : 0.0f;
        s = fmaf(v, W2[(size_t)o * 128 + e], s);
    }
    d_xa[t] = s + ba2[o];
}

// ---------------- x_ = h @ xa^T ----------------
__global__ __launch_bounds__(256) void k_xout(float* __restrict__ out) {
    __shared__ float As[32][68];
    __shared__ float Bs[32][132];
    int m0 = blockIdx.x * 64;
    int d0 = blockIdx.y * 128;
    int tid = threadIdx.x;
    int tx = tid & 15, ty = tid >> 4;
    float acc[4][8];
#pragma unroll
    for (int i = 0; i < 4; i++)
#pragma unroll
        for (int j = 0; j < 8; j++) acc[i][j] = 0.0f;

    for (int k0 = 0; k0 < 64; k0 += 32) {
#pragma unroll
        for (int t = 0; t < 2; t++) {
            int slot = tid + t * 256;
            int m = slot & 63, kq = slot >> 6;
            float4 v = *(const float4*)&d_h[(size_t)(m0 + m) * 64 + k0 + kq * 4];
            As[kq * 4 + 0][m] = v.x; As[kq * 4 + 1][m] = v.y;
            As[kq * 4 + 2][m] = v.z; As[kq * 4 + 3][m] = v.w;
        }
#pragma unroll
        for (int t = 0; t < 4; t++) {
            int slot = tid + t * 256;
            int n = slot & 127, kq = slot >> 7;
            float4 v = *(const float4*)&d_xa[(size_t)(d0 + n) * 64 + k0 + kq * 4];
            Bs[kq * 4 + 0][n] = v.x; Bs[kq * 4 + 1][n] = v.y;
            Bs[kq * 4 + 2][n] = v.z; Bs[kq * 4 + 3][n] = v.w;
        }
        __syncthreads();
#pragma unroll
        for (int kk = 0; kk < 32; kk++) {
            float4 av = *(const float4*)&As[kk][ty * 4];
            float4 b0 = *(const float4*)&Bs[kk][tx * 8];
            float4 b1 = *(const float4*)&Bs[kk][tx * 8 + 4];
            float a[4] = {av.x, av.y, av.z, av.w};
            float bb[8] = {b0.x, b0.y, b0.z, b0.w, b1.x, b1.y, b1.z, b1.w};
#pragma unroll
            for (int i = 0; i < 4; i++)
#pragma unroll
                for (int j = 0; j < 8; j++) acc[i][j] = fmaf(a[i], bb[j], acc[i][j]);
        }
        __syncthreads();
    }
#pragma unroll
    for (int i = 0; i < 4; i++) {
        size_t row = (size_t)(m0 + ty * 4 + i);
        float4 v0 = {acc[i][0], acc[i][1], acc[i][2], acc[i][3]};
        float4 v1 = {acc[i][4], acc[i][5], acc[i][6], acc[i][7]};
        *(float4*)&out[row * 512 + d0 + tx * 8]     = v0;
        *(float4*)&out[row * 512 + d0 + tx * 8 + 4] = v1;
    }
}

// ---------------- launch ----------------
extern "C" void kernel_launch(void* const* d_in, const int* in_sizes, int n_in,
                              void* d_out, int out_size) {
    const float* x     = (const float*)d_in[0];
    const float* Ws1   = (const float*)d_in[1];
    const float* bs1   = (const float*)d_in[2];
    const float* Wg    = (const float*)d_in[3];
    const float* asrc  = (const float*)d_in[4];
    const float* adst  = (const float*)d_in[5];
    const float* bg    = (const float*)d_in[6];
    const float* Wa1   = (const float*)d_in[7];
    const float* ba1   = (const float*)d_in[8];
    const float* Wa2   = (const float*)d_in[9];
    const float* ba2   = (const float*)d_in[10];
    const void*  ei    = d_in[11];

    float* out   = (float*)d_out;
    float* out_x = out;                          // [12288, 512]
    float* out_s = out + (size_t)NN * DIN;       // [12288, 12288]

    const int SMEM_TC = 55296;
    static int smem_set = 0;
    if (!smem_set) {
        cudaFuncSetAttribute(k_s_tc, cudaFuncAttributeMaxDynamicSharedMemorySize, SMEM_TC);
        smem_set = 1;
    }

    // CSR build
    k_detect<<<1, 256>>>((const int*)ei);
    k_init<<<256, 256>>>();
    k_count<<<NE / 256, 256>>>(ei);
    k_scan<<<1, 1024>>>();
    k_scatter<<<TOTE / 256, 256>>>(ei);

    // encoder + GAT
    k_fc1<<<NN / 64, 256>>>(x, Ws1, bs1);
    k_g<<<NN / 64, 256>>>(Wg);
    k_sc<<<NN / 8, 256>>>(asrc, adst);
    k_gat<<<NN / 8, 256>>>(bg);

    // structure decoder (tensor cores, symmetric)
    k_split<<<NN * DOUT / 256, 256>>>();
    k_s_tc<<<dim3(NN / 64, NN / 128), 256, SMEM_TC>>>(out_s);

    // attribute decoder
    k_att1<<<dim3(DIN / 64, 48), 256>>>(x, Wa1);
    k_xa<<<(DIN * DOUT) / 256, 256>>>(ba1, Wa2, ba2);
    k_xout<<<dim3(NN / 64, DIN / 128), 256>>>(out_x);
}

// round 6
// speedup vs baseline: 1.5795x; 1.1489x over previous
#include <cuda_runtime.h>
#include <cuda_bf16.h>
#include <cstdint>

#define NN   12288
#define DIN  512
#define DEMB 128
#define DOUT 64
#define NE   393216
#define TOTE (NE + NN)     // 405504
#define NEG  0.2f

// ---------------- scratch (device globals; no allocation) ----------------
__device__ float d_x1[NN * DEMB];
__device__ float d_g[NN * DOUT];
__device__ float d_scs[NN];
__device__ float d_scd[NN];
__device__ float d_h[NN * DOUT];
__device__ __nv_bfloat16 d_hhi[NN * DOUT];
__device__ __nv_bfloat16 d_hlo[NN * DOUT];
__device__ __nv_bfloat16 d_xhi[NN * DIN];
__device__ __nv_bfloat16 d_xlo[NN * DIN];
__device__ __nv_bfloat16 d_w1hi[DEMB * DIN];
__device__ __nv_bfloat16 d_w1lo[DEMB * DIN];
__device__ float d_xtraw[DIN * DEMB];
__device__ float d_xa[DIN * DOUT];
__device__ int   d_deg[NN];
__device__ int   d_off[NN + 1];
__device__ int   d_fill[NN];
__device__ int   d_csr[TOTE];
__device__ int   d_is64;

// ---------------- helpers ----------------
__device__ __forceinline__ float sigf(float v) {
    return 1.0f / (1.0f + __expf(-v));
}
__device__ __forceinline__ int clampn(int v) {
    v = v < 0 ? 0 : v;
    return v >= NN ? NN - 1 : v;
}
__device__ __forceinline__ uint32_t smem_u32(const void* p) {
    return (uint32_t)__cvta_generic_to_shared(p);
}
__device__ __forceinline__ void ldm_x4(uint32_t& r0, uint32_t& r1, uint32_t& r2,
                                       uint32_t& r3, uint32_t addr) {
    asm volatile("ldmatrix.sync.aligned.m8n8.x4.shared.b16 {%0,%1,%2,%3}, [%4];"
                 : "=r"(r0), "=r"(r1), "=r"(r2), "=r"(r3) : "r"(addr));
}
__device__ __forceinline__ void mma_bf16(float* c, const uint32_t* a, const uint32_t* b) {
    asm volatile(
        "mma.sync.aligned.m16n8k16.row.col.f32.bf16.bf16.f32 "
        "{%0,%1,%2,%3}, {%4,%5,%6,%7}, {%8,%9}, {%0,%1,%2,%3};"
        : "+f"(c[0]), "+f"(c[1]), "+f"(c[2]), "+f"(c[3])
        : "r"(a[0]), "r"(a[1]), "r"(a[2]), "r"(a[3]), "r"(b[0]), "r"(b[1]));
}

// ---------------- dtype probe ----------------
__global__ void k_detect(const int* __restrict__ ei32) {
    __shared__ int any;
    if (threadIdx.x == 0) any = 0;
    __syncthreads();
    if (ei32[threadIdx.x * 2 + 1] != 0) any = 1;
    __syncthreads();
    if (threadIdx.x == 0) d_is64 = (any == 0) ? 1 : 0;
}

__global__ void k_init() {
    int t = blockIdx.x * blockDim.x + threadIdx.x;
    if (t < DIN * DEMB) d_xtraw[t] = 0.0f;
    if (t < NN) d_deg[t] = 1;
}

__global__ void k_count(const void* __restrict__ ei) {
    int e = blockIdx.x * blockDim.x + threadIdx.x;
    if (e < NE) {
        int dst;
        if (d_is64) dst = (int)((const long long*)ei)[NE + e];
        else        dst = ((const int*)ei)[NE + e];
        atomicAdd(&d_deg[clampn(dst)], 1);
    }
}

// warp-shuffle scan (12 values/thread, 1024 threads)
__global__ void k_scan() {
    __shared__ int wsum[32];
    int t = threadIdx.x, lane = t & 31, w = t >> 5;
    int base = t * 12;
    int loc[12];
    int s = 0;
#pragma unroll
    for (int i = 0; i < 12; i++) { loc[i] = d_deg[base + i]; s += loc[i]; }
    int pre = s;
#pragma unroll
    for (int o = 1; o < 32; o <<= 1) {
        int v = __shfl_up_sync(0xffffffffu, pre, o);
        if (lane >= o) pre += v;
    }
    if (lane == 31) wsum[w] = pre;
    __syncthreads();
    if (w == 0) {
        int v = wsum[lane];
#pragma unroll
        for (int o = 1; o < 32; o <<= 1) {
            int u = __shfl_up_sync(0xffffffffu, v, o);
            if (lane >= o) v += u;
        }
        wsum[lane] = v;
    }
    __syncthreads();
    int run = pre - s + (w ? wsum[w - 1] : 0);
#pragma unroll
    for (int i = 0; i < 12; i++) {
        d_off[base + i]  = run;
        d_fill[base + i] = run;
        run += loc[i];
    }
    if (t == 1023) d_off[NN] = run;
}

__global__ void k_scatter(const void* __restrict__ ei) {
    int e = blockIdx.x * blockDim.x + threadIdx.x;
    if (e < NE) {
        int src, dst;
        if (d_is64) {
            src = (int)((const long long*)ei)[e];
            dst = (int)((const long long*)ei)[NE + e];
        } else {
            src = ((const int*)ei)[e];
            dst = ((const int*)ei)[NE + e];
        }
        int p = atomicAdd(&d_fill[clampn(dst)], 1);
        if (p < TOTE) d_csr[p] = clampn(src);
    } else if (e < TOTE) {
        int n = e - NE;
        int p = atomicAdd(&d_fill[n], 1);
        if (p < TOTE) d_csr[p] = n;
    }
}

// ---------------- split kernels ----------------
__global__ void k_splitx(const float* __restrict__ x) {
    int t = blockIdx.x * blockDim.x + threadIdx.x;
    float v = x[t];
    __nv_bfloat16 hi = __float2bfloat16(v);
    d_xhi[t] = hi;
    d_xlo[t] = __float2bfloat16(v - __bfloat162float(hi));
}
__global__ void k_splitw1(const float* __restrict__ W) {
    int t = blockIdx.x * blockDim.x + threadIdx.x;
    float v = W[t];
    __nv_bfloat16 hi = __float2bfloat16(v);
    d_w1hi[t] = hi;
    d_w1lo[t] = __float2bfloat16(v - __bfloat162float(hi));
}
__global__ void k_split() {
    int t = blockIdx.x * blockDim.x + threadIdx.x;
    float h = d_h[t];
    __nv_bfloat16 hi = __float2bfloat16(h);
    d_hhi[t] = hi;
    d_hlo[t] = __float2bfloat16(h - __bfloat162float(hi));
}

#define SP 72    // operand smem pitch (halves)

// ---------------- x1 = relu(x @ W_s1^T + b) via bf16-split mma ----------------
// BM=128, BN=128(full), BK=64 (8 chunks). 8 warps: 2(m)x4(n), warp 64x32.
__global__ __launch_bounds__(256) void k_fc1_tc(const float* __restrict__ b) {
    extern __shared__ __nv_bfloat16 sm[];
    __nv_bfloat16* sAh = sm;            // 128*72
    __nv_bfloat16* sAl = sm + 9216;
    __nv_bfloat16* sBh = sm + 18432;
    __nv_bfloat16* sBl = sm + 27648;

    int m0 = blockIdx.x * 128;
    int tid = threadIdx.x;
    int wid = tid >> 5, lane = tid & 31;
    int warp_m = (wid & 1) * 64;
    int warp_n = (wid >> 1) * 32;

    float acc[4][4][4];
#pragma unroll
    for (int i = 0; i < 4; i++)
#pragma unroll
        for (int j = 0; j < 4; j++)
#pragma unroll
            for (int c = 0; c < 4; c++) acc[i][j][c] = 0.0f;

    int a_row = lane & 15, a_kc = (lane >> 4) << 3;
    int b_row = (lane & 7) + (((lane >> 4) & 1) << 3);
    int b_kc  = (((lane >> 3) & 1) << 3);

    for (int kc = 0; kc < 512; kc += 64) {
#pragma unroll
        for (int r = 0; r < 4; r++) {
            int idx = tid + r * 256;
            int row = idx >> 3, ch = idx & 7;
            *(uint4*)&sAh[row * SP + ch * 8] =
                ((const uint4*)(d_xhi + (size_t)(m0 + row) * 512 + kc))[ch];
            *(uint4*)&sAl[row * SP + ch * 8] =
                ((const uint4*)(d_xlo + (size_t)(m0 + row) * 512 + kc))[ch];
            *(uint4*)&sBh[row * SP + ch * 8] =
                ((const uint4*)(d_w1hi + (size_t)row * 512 + kc))[ch];
            *(uint4*)&sBl[row * SP + ch * 8] =
                ((const uint4*)(d_w1lo + (size_t)row * 512 + kc))[ch];
        }
        __syncthreads();
#pragma unroll
        for (int ks = 0; ks < 4; ks++) {
            int k0 = ks * 16;
            uint32_t Bh[2][4], Bl[2][4];
#pragma unroll
            for (int nb = 0; nb < 2; nb++) {
                ldm_x4(Bh[nb][0], Bh[nb][1], Bh[nb][2], Bh[nb][3],
                       smem_u32(&sBh[(warp_n + nb * 16 + b_row) * SP + k0 + b_kc]));
                ldm_x4(Bl[nb][0], Bl[nb][1], Bl[nb][2], Bl[nb][3],
                       smem_u32(&sBl[(warp_n + nb * 16 + b_row) * SP + k0 + b_kc]));
            }
#pragma unroll
            for (int mt = 0; mt < 4; mt++) {
                uint32_t Ah[4], Al[4];
                ldm_x4(Ah[0], Ah[1], Ah[2], Ah[3],
                       smem_u32(&sAh[(warp_m + mt * 16 + a_row) * SP + k0 + a_kc]));
#pragma unroll
                for (int nt = 0; nt < 4; nt++)
                    mma_bf16(acc[mt][nt], Ah, &Bh[nt >> 1][(nt & 1) * 2]);
#pragma unroll
                for (int nt = 0; nt < 4; nt++)
                    mma_bf16(acc[mt][nt], Ah, &Bl[nt >> 1][(nt & 1) * 2]);
                ldm_x4(Al[0], Al[1], Al[2], Al[3],
                       smem_u32(&sAl[(warp_m + mt * 16 + a_row) * SP + k0 + a_kc]));
#pragma unroll
                for (int nt = 0; nt < 4; nt++)
                    mma_bf16(acc[mt][nt], Al, &Bh[nt >> 1][(nt & 1) * 2]);
            }
        }
        __syncthreads();
    }
    // epilogue: bias + relu, direct store
#pragma unroll
    for (int mt = 0; mt < 4; mt++) {
        int r0 = m0 + warp_m + mt * 16 + (lane >> 2);
#pragma unroll
        for (int nt = 0; nt < 4; nt++) {
            int c = warp_n + nt * 8 + ((lane & 3) << 1);
            float b0 = b[c], b1 = b[c + 1];
            float2 v0, v1;
            v0.x = fmaxf(acc[mt][nt][0] + b0, 0.0f);
            v0.y = fmaxf(acc[mt][nt][1] + b1, 0.0f);
            v1.x = fmaxf(acc[mt][nt][2] + b0, 0.0f);
            v1.y = fmaxf(acc[mt][nt][3] + b1, 0.0f);
            *(float2*)&d_x1[(size_t)r0 * 128 + c]       = v0;
            *(float2*)&d_x1[(size_t)(r0 + 8) * 128 + c] = v1;
        }
    }
}

// ---------------- g = x1 @ W_g^T ----------------
__global__ __launch_bounds__(256) void k_g(const float* __restrict__ Wg) {
    __shared__ float As[32][68];
    __shared__ float Bs[32][68];
    int m0 = blockIdx.x * 64;
    int tid = threadIdx.x;
    int tx = tid & 15, ty = tid >> 4;
    float acc[4][4];
#pragma unroll
    for (int i = 0; i < 4; i++)
#pragma unroll
        for (int j = 0; j < 4; j++) acc[i][j] = 0.0f;

    for (int k0 = 0; k0 < 128; k0 += 32) {
#pragma unroll
        for (int t = 0; t < 2; t++) {
            int slot = tid + t * 256;
            int m = slot & 63, kq = slot >> 6;
            float4 v = *(const float4*)&d_x1[(size_t)(m0 + m) * 128 + k0 + kq * 4];
            As[kq * 4 + 0][m] = v.x; As[kq * 4 + 1][m] = v.y;
            As[kq * 4 + 2][m] = v.z; As[kq * 4 + 3][m] = v.w;
        }
#pragma unroll
        for (int t = 0; t < 2; t++) {
            int slot = tid + t * 256;
            int n = slot & 63, kq = slot >> 6;
            float4 v = *(const float4*)&Wg[(size_t)n * 128 + k0 + kq * 4];
            Bs[kq * 4 + 0][n] = v.x; Bs[kq * 4 + 1][n] = v.y;
            Bs[kq * 4 + 2][n] = v.z; Bs[kq * 4 + 3][n] = v.w;
        }
        __syncthreads();
#pragma unroll
        for (int kk = 0; kk < 32; kk++) {
            float4 av = *(const float4*)&As[kk][ty * 4];
            float4 bv = *(const float4*)&Bs[kk][tx * 4];
            float a[4] = {av.x, av.y, av.z, av.w};
            float bb[4] = {bv.x, bv.y, bv.z, bv.w};
#pragma unroll
            for (int i = 0; i < 4; i++)
#pragma unroll
                for (int j = 0; j < 4; j++) acc[i][j] = fmaf(a[i], bb[j], acc[i][j]);
        }
        __syncthreads();
    }
#pragma unroll
    for (int i = 0; i < 4; i++)
#pragma unroll
        for (int j = 0; j < 4; j++)
            d_g[(size_t)(m0 + ty * 4 + i) * 64 + tx * 4 + j] = acc[i][j];
}

// ---------------- attention scores ----------------
__global__ void k_sc(const float* __restrict__ asrc, const float* __restrict__ adst) {
    int warp = (blockIdx.x * blockDim.x + threadIdx.x) >> 5;
    int lane = threadIdx.x & 31;
    if (warp >= NN) return;
    float g0 = d_g[(size_t)warp * 64 + lane];
    float g1 = d_g[(size_t)warp * 64 + 32 + lane];
    float vs = g0 * asrc[lane] + g1 * asrc[32 + lane];
    float vd = g0 * adst[lane] + g1 * adst[32 + lane];
#pragma unroll
    for (int o = 16; o; o >>= 1) {
        vs += __shfl_xor_sync(0xffffffffu, vs, o);
        vd += __shfl_xor_sync(0xffffffffu, vd, o);
    }
    if (lane == 0) { d_scs[warp] = vs; d_scd[warp] = vd; }
}

// ---------------- GAT aggregation ----------------
__global__ void k_gat(const float* __restrict__ bg) {
    int warp = (blockIdx.x * blockDim.x + threadIdx.x) >> 5;
    int lane = threadIdx.x & 31;
    if (warp >= NN) return;
    int s0 = d_off[warp], s1 = d_off[warp + 1];
    float scd = d_scd[warp];

    float mx = -1e30f;
    for (int j = s0 + lane; j < s1; j += 32) {
        int s = d_csr[j];
        float e = d_scs[s] + scd;
        e = e > 0.0f ? e : NEG * e;
        mx = fmaxf(mx, e);
    }
#pragma unroll
    for (int o = 16; o; o >>= 1) mx = fmaxf(mx, __shfl_xor_sync(0xffffffffu, mx, o));

    float sum = 0.0f;
    for (int j = s0 + lane; j < s1; j += 32) {
        int s = d_csr[j];
        float e = d_scs[s] + scd;
        e = e > 0.0f ? e : NEG * e;
        sum += __expf(e - mx);
    }
#pragma unroll
    for (int o = 16; o; o >>= 1) sum += __shfl_xor_sync(0xffffffffu, sum, o);
    float inv = 1.0f / sum;

    float a0 = 0.0f, a1 = 0.0f;
    for (int j = s0; j < s1; j++) {
        int s = d_csr[j];
        float e = d_scs[s] + scd;
        e = e > 0.0f ? e : NEG * e;
        float w = __expf(e - mx) * inv;
        a0 = fmaf(w, d_g[(size_t)s * 64 + lane], a0);
        a1 = fmaf(w, d_g[(size_t)s * 64 + 32 + lane], a1);
    }
    d_h[(size_t)warp * 64 + lane]      = a0 + bg[lane];
    d_h[(size_t)warp * 64 + 32 + lane] = a1 + bg[32 + lane];
}

// ---------------- s_ = sigmoid(h h^T): full-square 128x128 bf16-split mma ----------------
// grid (96, 96); 8 warps 2(m)x4(n), warp 64x32; K=64 in one smem load.
#define CP2 132
__global__ __launch_bounds__(256) void k_s_tc(float* __restrict__ out) {
    extern __shared__ __nv_bfloat16 sm[];
    __nv_bfloat16* sAh = sm;            // 128*72
    __nv_bfloat16* sAl = sm + 9216;
    __nv_bfloat16* sBh = sm + 18432;
    __nv_bfloat16* sBl = sm + 27648;
    float* Cs = (float*)sm;             // [128][CP2] after compute

    int i0 = blockIdx.y * 128, j0 = blockIdx.x * 128;
    int tid = threadIdx.x;

#pragma unroll
    for (int r = 0; r < 4; r++) {
        int idx = tid + r * 256;
        int row = idx >> 3, ch = idx & 7;
        *(uint4*)&sAh[row * SP + ch * 8] =
            ((const uint4*)(d_hhi + (size_t)(i0 + row) * 64))[ch];
        *(uint4*)&sAl[row * SP + ch * 8] =
            ((const uint4*)(d_hlo + (size_t)(i0 + row) * 64))[ch];
        *(uint4*)&sBh[row * SP + ch * 8] =
            ((const uint4*)(d_hhi + (size_t)(j0 + row) * 64))[ch];
        *(uint4*)&sBl[row * SP + ch * 8] =
            ((const uint4*)(d_hlo + (size_t)(j0 + row) * 64))[ch];
    }
    __syncthreads();

    int wid = tid >> 5, lane = tid & 31;
    int warp_m = (wid & 1) * 64;
    int warp_n = (wid >> 1) * 32;

    float acc[4][4][4];
#pragma unroll
    for (int i = 0; i < 4; i++)
#pragma unroll
        for (int j = 0; j < 4; j++)
#pragma unroll
            for (int c = 0; c < 4; c++) acc[i][j][c] = 0.0f;

    int a_row = lane & 15, a_kc = (lane >> 4) << 3;
    int b_row = (lane & 7) + (((lane >> 4) & 1) << 3);
    int b_kc  = (((lane >> 3) & 1) << 3);

#pragma unroll
    for (int ks = 0; ks < 4; ks++) {
        int k0 = ks * 16;
        uint32_t Bh[2][4], Bl[2][4];
#pragma unroll
        for (int nb = 0; nb < 2; nb++) {
            ldm_x4(Bh[nb][0], Bh[nb][1], Bh[nb][2], Bh[nb][3],
                   smem_u32(&sBh[(warp_n + nb * 16 + b_row) * SP + k0 + b_kc]));
            ldm_x4(Bl[nb][0], Bl[nb][1], Bl[nb][2], Bl[nb][3],
                   smem_u32(&sBl[(warp_n + nb * 16 + b_row) * SP + k0 + b_kc]));
        }
#pragma unroll
        for (int mt = 0; mt < 4; mt++) {
            uint32_t Ah[4], Al[4];
            ldm_x4(Ah[0], Ah[1], Ah[2], Ah[3],
                   smem_u32(&sAh[(warp_m + mt * 16 + a_row) * SP + k0 + a_kc]));
#pragma unroll
            for (int nt = 0; nt < 4; nt++)
                mma_bf16(acc[mt][nt], Ah, &Bh[nt >> 1][(nt & 1) * 2]);
#pragma unroll
            for (int nt = 0; nt < 4; nt++)
                mma_bf16(acc[mt][nt], Ah, &Bl[nt >> 1][(nt & 1) * 2]);
            ldm_x4(Al[0], Al[1], Al[2], Al[3],
                   smem_u32(&sAl[(warp_m + mt * 16 + a_row) * SP + k0 + a_kc]));
#pragma unroll
            for (int nt = 0; nt < 4; nt++)
                mma_bf16(acc[mt][nt], Al, &Bh[nt >> 1][(nt & 1) * 2]);
        }
    }
    __syncthreads();   // operands dead; reuse smem as Cs

    // stage sigmoid into Cs
#pragma unroll
    for (int mt = 0; mt < 4; mt++) {
        int r0 = warp_m + mt * 16 + (lane >> 2);
#pragma unroll
        for (int nt = 0; nt < 4; nt++) {
            int c0 = warp_n + nt * 8 + ((lane & 3) << 1);
            Cs[r0 * CP2 + c0]           = sigf(acc[mt][nt][0]);
            Cs[r0 * CP2 + c0 + 1]       = sigf(acc[mt][nt][1]);
            Cs[(r0 + 8) * CP2 + c0]     = sigf(acc[mt][nt][2]);
            Cs[(r0 + 8) * CP2 + c0 + 1] = sigf(acc[mt][nt][3]);
        }
    }
    __syncthreads();

    // coalesced store: each warp writes one full row per iteration
#pragma unroll
    for (int itr = 0; itr < 16; itr++) {
        int slot = tid + itr * 256;
        int row = slot >> 5, c4 = slot & 31;
        float4 v = *(const float4*)&Cs[row * CP2 + c4 * 4];
        *(float4*)&out[(size_t)(i0 + row) * NN + j0 + c4 * 4] = v;
    }
}

// ---------------- xtraw split-K (fp32) ----------------
__global__ __launch_bounds__(256) void k_att1(const float* __restrict__ x,
                                              const float* __restrict__ W) {
    __shared__ float As[32][68];
    __shared__ float Bs[32][132];
    int d0 = blockIdx.x * 64;
    int kbase = blockIdx.y * 256;
    int tid = threadIdx.x;
    int tx = tid & 15, ty = tid >> 4;
    float acc[4][8];
#pragma unroll
    for (int i = 0; i < 4; i++)
#pragma unroll
        for (int j = 0; j < 8; j++) acc[i][j] = 0.0f;

    for (int kc = 0; kc < 256; kc += 32) {
        int k0 = kbase + kc;
#pragma unroll
        for (int t = 0; t < 2; t++) {
            int slot = tid + t * 256;
            int kk = slot >> 4, dq = slot & 15;
            float4 v = *(const float4*)&x[(size_t)(k0 + kk) * 512 + d0 + dq * 4];
            *(float4*)&As[kk][dq * 4] = v;
        }
#pragma unroll
        for (int t = 0; t < 4; t++) {
            int slot = tid + t * 256;
            int n = slot & 127, kq = slot >> 7;
            float4 v = *(const float4*)&W[(size_t)n * NN + k0 + kq * 4];
            Bs[kq * 4 + 0][n] = v.x; Bs[kq * 4 + 1][n] = v.y;
            Bs[kq * 4 + 2][n] = v.z; Bs[kq * 4 + 3][n] = v.w;
        }
        __syncthreads();
#pragma unroll
        for (int kk = 0; kk < 32; kk++) {
            float4 av = *(const float4*)&As[kk][ty * 4];
            float4 b0 = *(const float4*)&Bs[kk][tx * 8];
            float4 b1 = *(const float4*)&Bs[kk][tx * 8 + 4];
            float a[4] = {av.x, av.y, av.z, av.w};
            float bb[8] = {b0.x, b0.y, b0.z, b0.w, b1.x, b1.y, b1.z, b1.w};
#pragma unroll
            for (int i = 0; i < 4; i++)
#pragma unroll
                for (int j = 0; j < 8; j++) acc[i][j] = fmaf(a[i], bb[j], acc[i][j]);
        }
        __syncthreads();
    }
#pragma unroll
    for (int i = 0; i < 4; i++)
#pragma unroll
        for (int j = 0; j < 8; j++)
            atomicAdd(&d_xtraw[(size_t)(d0 + ty * 4 + i) * 128 + tx * 8 + j], acc[i][j]);
}

__global__ void k_xa(const float* __restrict__ ba1, const float* __restrict__ W2,
                     const float* __restrict__ ba2) {
    int t = blockIdx.x * blockDim.x + threadIdx.x;
    if (t >= DIN * DOUT) return;
    int d = t >> 6, o = t & 63;
    float s = 0.0f;
#pragma unroll 4
    for (int e = 0; e < 128; e++) {
        float v = d_xtraw[(size_t)d * 128 + e] + ba1[e];
        v = v > 0.0f ? v : 0.0f;
        s = fmaf(v, W2[(size_t)o * 128 + e], s);
    }
    d_xa[t] = s + ba2[o];
}

// ---------------- x_ = h @ xa^T ----------------
__global__ __launch_bounds__(256) void k_xout(float* __restrict__ out) {
    __shared__ float As[32][68];
    __shared__ float Bs[32][132];
    int m0 = blockIdx.x * 64;
    int d0 = blockIdx.y * 128;
    int tid = threadIdx.x;
    int tx = tid & 15, ty = tid >> 4;
    float acc[4][8];
#pragma unroll
    for (int i = 0; i < 4; i++)
#pragma unroll
        for (int j = 0; j < 8; j++) acc[i][j] = 0.0f;

    for (int k0 = 0; k0 < 64; k0 += 32) {
#pragma unroll
        for (int t = 0; t < 2; t++) {
            int slot = tid + t * 256;
            int m = slot & 63, kq = slot >> 6;
            float4 v = *(const float4*)&d_h[(size_t)(m0 + m) * 64 + k0 + kq * 4];
            As[kq * 4 + 0][m] = v.x; As[kq * 4 + 1][m] = v.y;
            As[kq * 4 + 2][m] = v.z; As[kq * 4 + 3][m] = v.w;
        }
#pragma unroll
        for (int t = 0; t < 4; t++) {
            int slot = tid + t * 256;
            int n = slot & 127, kq = slot >> 7;
            float4 v = *(const float4*)&d_xa[(size_t)(d0 + n) * 64 + k0 + kq * 4];
            Bs[kq * 4 + 0][n] = v.x; Bs[kq * 4 + 1][n] = v.y;
            Bs[kq * 4 + 2][n] = v.z; Bs[kq * 4 + 3][n] = v.w;
        }
        __syncthreads();
#pragma unroll
        for (int kk = 0; kk < 32; kk++) {
            float4 av = *(const float4*)&As[kk][ty * 4];
            float4 b0 = *(const float4*)&Bs[kk][tx * 8];
            float4 b1 = *(const float4*)&Bs[kk][tx * 8 + 4];
            float a[4] = {av.x, av.y, av.z, av.w};
            float bb[8] = {b0.x, b0.y, b0.z, b0.w, b1.x, b1.y, b1.z, b1.w};
#pragma unroll
            for (int i = 0; i < 4; i++)
#pragma unroll
                for (int j = 0; j < 8; j++) acc[i][j] = fmaf(a[i], bb[j], acc[i][j]);
        }
        __syncthreads();
    }
#pragma unroll
    for (int i = 0; i < 4; i++) {
        size_t row = (size_t)(m0 + ty * 4 + i);
        float4 v0 = {acc[i][0], acc[i][1], acc[i][2], acc[i][3]};
        float4 v1 = {acc[i][4], acc[i][5], acc[i][6], acc[i][7]};
        *(float4*)&out[row * 512 + d0 + tx * 8]     = v0;
        *(float4*)&out[row * 512 + d0 + tx * 8 + 4] = v1;
    }
}

// ---------------- launch ----------------
extern "C" void kernel_launch(void* const* d_in, const int* in_sizes, int n_in,
                              void* d_out, int out_size) {
    const float* x     = (const float*)d_in[0];
    const float* Ws1   = (const float*)d_in[1];
    const float* bs1   = (const float*)d_in[2];
    const float* Wg    = (const float*)d_in[3];
    const float* asrc  = (const float*)d_in[4];
    const float* adst  = (const float*)d_in[5];
    const float* bg    = (const float*)d_in[6];
    const float* Wa1   = (const float*)d_in[7];
    const float* ba1   = (const float*)d_in[8];
    const float* Wa2   = (const float*)d_in[9];
    const float* ba2   = (const float*)d_in[10];
    const void*  ei    = d_in[11];

    float* out   = (float*)d_out;
    float* out_x = out;                          // [12288, 512]
    float* out_s = out + (size_t)NN * DIN;       // [12288, 12288]

    const int SMEM_TC = 73728;
    static int smem_set = 0;
    if (!smem_set) {
        cudaFuncSetAttribute(k_s_tc, cudaFuncAttributeMaxDynamicSharedMemorySize, SMEM_TC);
        cudaFuncSetAttribute(k_fc1_tc, cudaFuncAttributeMaxDynamicSharedMemorySize, SMEM_TC);
        smem_set = 1;
    }

    // CSR build + input splits
    k_detect<<<1, 256>>>((const int*)ei);
    k_init<<<256, 256>>>();
    k_count<<<NE / 256, 256>>>(ei);
    k_splitx<<<NN * DIN / 256, 256>>>(x);
    k_splitw1<<<DEMB * DIN / 256, 256>>>(Ws1);
    k_scan<<<1, 1024>>>();
    k_scatter<<<TOTE / 256, 256>>>(ei);

    // encoder + GAT
    k_fc1_tc<<<NN / 128, 256, SMEM_TC>>>(bs1);
    k_g<<<NN / 64, 256>>>(Wg);
    k_sc<<<NN / 8, 256>>>(asrc, adst);
    k_gat<<<NN / 8, 256>>>(bg);

    // structure decoder (tensor cores, full square)
    k_split<<<NN * DOUT / 256, 256>>>();
    k_s_tc<<<dim3(NN / 128, NN / 128), 256, SMEM_TC>>>(out_s);

    // attribute decoder
    k_att1<<<dim3(DIN / 64, 48), 256>>>(x, Wa1);
    k_xa<<<(DIN * DOUT) / 256, 256>>>(ba1, Wa2, ba2);
    k_xout<<<dim3(NN / 64, DIN / 128), 256>>>(out_x);
}

// round 11
// speedup vs baseline: 1.6856x; 1.0672x over previous
#include <cuda_runtime.h>
#include <cuda_bf16.h>
#include <cstdint>

#define NN   12288
#define DIN  512
#define DEMB 128
#define DOUT 64
#define NE   393216
#define TOTE (NE + NN)     // 405504
#define NEG  0.2f

// ---------------- scratch (device globals; no allocation) ----------------
__device__ __nv_bfloat16 d_x1hi[NN * DEMB];
__device__ __nv_bfloat16 d_x1lo[NN * DEMB];
__device__ float d_g[NN * DOUT];
__device__ float d_scs[NN];
__device__ float d_scd[NN];
__device__ float d_h[NN * DOUT];
__device__ __nv_bfloat16 d_hhi[NN * DOUT];
__device__ __nv_bfloat16 d_hlo[NN * DOUT];
__device__ __nv_bfloat16 d_xhi[NN * DIN];
__device__ __nv_bfloat16 d_xlo[NN * DIN];
__device__ __nv_bfloat16 d_xThi[DIN * NN];   // x^T, bf16 hi
__device__ __nv_bfloat16 d_xTlo[DIN * NN];
__device__ __nv_bfloat16 d_w1hi[DEMB * DIN];
__device__ __nv_bfloat16 d_w1lo[DEMB * DIN];
__device__ __nv_bfloat16 d_wa1hi[DEMB * NN];
__device__ __nv_bfloat16 d_wa1lo[DEMB * NN];
__device__ __nv_bfloat16 d_wghi[DOUT * DEMB];
__device__ __nv_bfloat16 d_wglo[DOUT * DEMB];
__device__ float d_xtraw[DIN * DEMB];
__device__ float d_xa[DIN * DOUT];
__device__ int   d_deg[NN];
__device__ int   d_off[NN + 1];
__device__ int   d_fill[NN];
__device__ int   d_csr[TOTE];
__device__ int   d_is64;

// ---------------- helpers ----------------
__device__ __forceinline__ float sigf(float v) {
    return 1.0f / (1.0f + __expf(-v));
}
__device__ __forceinline__ int clampn(int v) {
    v = v < 0 ? 0 : v;
    return v >= NN ? NN - 1 : v;
}
__device__ __forceinline__ uint32_t smem_u32(const void* p) {
    return (uint32_t)__cvta_generic_to_shared(p);
}
__device__ __forceinline__ void ldm_x4(uint32_t& r0, uint32_t& r1, uint32_t& r2,
                                       uint32_t& r3, uint32_t addr) {
    asm volatile("ldmatrix.sync.aligned.m8n8.x4.shared.b16 {%0,%1,%2,%3}, [%4];"
                 : "=r"(r0), "=r"(r1), "=r"(r2), "=r"(r3) : "r"(addr));
}
__device__ __forceinline__ void mma_bf16(float* c, const uint32_t* a, const uint32_t* b) {
    asm volatile(
        "mma.sync.aligned.m16n8k16.row.col.f32.bf16.bf16.f32 "
        "{%0,%1,%2,%3}, {%4,%5,%6,%7}, {%8,%9}, {%0,%1,%2,%3};"
        : "+f"(c[0]), "+f"(c[1]), "+f"(c[2]), "+f"(c[3])
        : "r"(a[0]), "r"(a[1]), "r"(a[2]), "r"(a[3]), "r"(b[0]), "r"(b[1]));
}

// ---------------- dtype probe ----------------
__global__ void k_detect(const int* __restrict__ ei32) {
    __shared__ int any;
    if (threadIdx.x == 0) any = 0;
    __syncthreads();
    if (ei32[threadIdx.x * 2 + 1] != 0) any = 1;
    __syncthreads();
    if (threadIdx.x == 0) d_is64 = (any == 0) ? 1 : 0;
}

__global__ void k_init() {
    int t = blockIdx.x * blockDim.x + threadIdx.x;
    if (t < DIN * DEMB) d_xtraw[t] = 0.0f;
    if (t < NN) d_deg[t] = 1;
}

__global__ void k_count(const void* __restrict__ ei) {
    int e = blockIdx.x * blockDim.x + threadIdx.x;
    if (e < NE) {
        int dst;
        if (d_is64) dst = (int)((const long long*)ei)[NE + e];
        else        dst = ((const int*)ei)[NE + e];
        atomicAdd(&d_deg[clampn(dst)], 1);
    }
}

// warp-shuffle scan (12 values/thread, 1024 threads)
__global__ void k_scan() {
    __shared__ int wsum[32];
    int t = threadIdx.x, lane = t & 31, w = t >> 5;
    int base = t * 12;
    int loc[12];
    int s = 0;
#pragma unroll
    for (int i = 0; i < 12; i++) { loc[i] = d_deg[base + i]; s += loc[i]; }
    int pre = s;
#pragma unroll
    for (int o = 1; o < 32; o <<= 1) {
        int v = __shfl_up_sync(0xffffffffu, pre, o);
        if (lane >= o) pre += v;
    }
    if (lane == 31) wsum[w] = pre;
    __syncthreads();
    if (w == 0) {
        int v = wsum[lane];
#pragma unroll
        for (int o = 1; o < 32; o <<= 1) {
            int u = __shfl_up_sync(0xffffffffu, v, o);
            if (lane >= o) v += u;
        }
        wsum[lane] = v;
    }
    __syncthreads();
    int run = pre - s + (w ? wsum[w - 1] : 0);
#pragma unroll
    for (int i = 0; i < 12; i++) {
        d_off[base + i]  = run;
        d_fill[base + i] = run;
        run += loc[i];
    }
    if (t == 1023) d_off[NN] = run;
}

__global__ void k_scatter(const void* __restrict__ ei) {
    int e = blockIdx.x * blockDim.x + threadIdx.x;
    if (e < NE) {
        int src, dst;
        if (d_is64) {
            src = (int)((const long long*)ei)[e];
            dst = (int)((const long long*)ei)[NE + e];
        } else {
            src = ((const int*)ei)[e];
            dst = ((const int*)ei)[NE + e];
        }
        int p = atomicAdd(&d_fill[clampn(dst)], 1);
        if (p < TOTE) d_csr[p] = clampn(src);
    } else if (e < TOTE) {
        int n = e - NE;
        int p = atomicAdd(&d_fill[n], 1);
        if (p < TOTE) d_csr[p] = n;
    }
}

// ---------------- split kernels (vectorized: 8 elems/thread) ----------------
__device__ __forceinline__ void split8(const float* __restrict__ src,
                                       __nv_bfloat16* __restrict__ hi,
                                       __nv_bfloat16* __restrict__ lo, size_t base) {
    float4 v0 = *(const float4*)&src[base];
    float4 v1 = *(const float4*)&src[base + 4];
    float f[8] = {v0.x, v0.y, v0.z, v0.w, v1.x, v1.y, v1.z, v1.w};
    __nv_bfloat16 h[8], l[8];
#pragma unroll
    for (int i = 0; i < 8; i++) {
        h[i] = __float2bfloat16(f[i]);
        l[i] = __float2bfloat16(f[i] - __bfloat162float(h[i]));
    }
    *(uint4*)&hi[base] = *(uint4*)h;
    *(uint4*)&lo[base] = *(uint4*)l;
}
__global__ void k_splitx(const float* __restrict__ x) {
    size_t base = (size_t)(blockIdx.x * blockDim.x + threadIdx.x) * 8;
    split8(x, d_xhi, d_xlo, base);
}
__global__ void k_splitw1(const float* __restrict__ W) {
    size_t base = (size_t)(blockIdx.x * blockDim.x + threadIdx.x) * 8;
    split8(W, d_w1hi, d_w1lo, base);
}
__global__ void k_splitwa1(const float* __restrict__ W) {
    size_t base = (size_t)(blockIdx.x * blockDim.x + threadIdx.x) * 8;
    split8(W, d_wa1hi, d_wa1lo, base);
}
__global__ void k_splitwg(const float* __restrict__ W) {
    size_t base = (size_t)(blockIdx.x * blockDim.x + threadIdx.x) * 8;
    split8(W, d_wghi, d_wglo, base);
}
__global__ void k_split() {
    size_t base = (size_t)(blockIdx.x * blockDim.x + threadIdx.x) * 8;
    split8(d_h, d_hhi, d_hlo, base);
}

// ---------------- transpose+split x: [k][d] fp32 -> x^T [d][k] bf16 hi/lo ----------------
__global__ __launch_bounds__(256) void k_tsplit(const float* __restrict__ x) {
    __shared__ __nv_bfloat16 shhi[64 * 68];
    __shared__ __nv_bfloat16 shlo[64 * 68];
    int k0 = blockIdx.x * 64, d0 = blockIdx.y * 64;
    int tid = threadIdx.x;
#pragma unroll
    for (int i = 0; i < 4; i++) {
        int slot = tid + i * 256;          // 1024 float4 slots
        int kk = slot >> 4, q = slot & 15;
        float4 v = *(const float4*)&x[(size_t)(k0 + kk) * 512 + d0 + q * 4];
        __nv_bfloat16 h[4], l[4];
        float f[4] = {v.x, v.y, v.z, v.w};
#pragma unroll
        for (int u = 0; u < 4; u++) {
            h[u] = __float2bfloat16(f[u]);
            l[u] = __float2bfloat16(f[u] - __bfloat162float(h[u]));
        }
        *(uint2*)&shhi[kk * 68 + q * 4] = *(uint2*)h;
        *(uint2*)&shlo[kk * 68 + q * 4] = *(uint2*)l;
    }
    __syncthreads();
#pragma unroll
    for (int i = 0; i < 4; i++) {
        int slot = tid + i * 256;          // 1024 = 2 arrays x 512 uint4
        int arr = slot >> 9;
        int s2 = slot & 511;
        int dd = s2 >> 3, qc = s2 & 7;
        const __nv_bfloat16* sh = arr ? shlo : shhi;
        __nv_bfloat16 vals[8];
#pragma unroll
        for (int u = 0; u < 8; u++) vals[u] = sh[(qc * 8 + u) * 68 + dd];
        __nv_bfloat16* dst = arr ? d_xTlo : d_xThi;
        *(uint4*)&dst[(size_t)(d0 + dd) * NN + k0 + qc * 8] = *(uint4*)vals;
    }
}

#define SP 72    // operand smem pitch (halves)

// ---------------- x1 = relu(x @ W_s1^T + b) via bf16-split mma (outputs bf16 hi/lo) ----------------
__global__ __launch_bounds__(256) void k_fc1_tc(const float* __restrict__ b) {
    extern __shared__ __nv_bfloat16 sm[];
    __nv_bfloat16* sAh = sm;            // 128*72
    __nv_bfloat16* sAl = sm + 9216;
    __nv_bfloat16* sBh = sm + 18432;
    __nv_bfloat16* sBl = sm + 27648;

    int m0 = blockIdx.x * 128;
    int tid = threadIdx.x;
    int wid = tid >> 5, lane = tid & 31;
    int warp_m = (wid & 1) * 64;
    int warp_n = (wid >> 1) * 32;

    float acc[4][4][4];
#pragma unroll
    for (int i = 0; i < 4; i++)
#pragma unroll
        for (int j = 0; j < 4; j++)
#pragma unroll
            for (int c = 0; c < 4; c++) acc[i][j][c] = 0.0f;

    int a_row = lane & 15, a_kc = (lane >> 4) << 3;
    int b_row = (lane & 7) + (((lane >> 4) & 1) << 3);
    int b_kc  = (((lane >> 3) & 1) << 3);

    for (int kc = 0; kc < 512; kc += 64) {
#pragma unroll
        for (int r = 0; r < 4; r++) {
            int idx = tid + r * 256;
            int row = idx >> 3, ch = idx & 7;
            *(uint4*)&sAh[row * SP + ch * 8] =
                ((const uint4*)(d_xhi + (size_t)(m0 + row) * 512 + kc))[ch];
            *(uint4*)&sAl[row * SP + ch * 8] =
                ((const uint4*)(d_xlo + (size_t)(m0 + row) * 512 + kc))[ch];
            *(uint4*)&sBh[row * SP + ch * 8] =
                ((const uint4*)(d_w1hi + (size_t)row * 512 + kc))[ch];
            *(uint4*)&sBl[row * SP + ch * 8] =
                ((const uint4*)(d_w1lo + (size_t)row * 512 + kc))[ch];
        }
        __syncthreads();
#pragma unroll
        for (int ks = 0; ks < 4; ks++) {
            int k0 = ks * 16;
            uint32_t Bh[2][4], Bl[2][4];
#pragma unroll
            for (int nb = 0; nb < 2; nb++) {
                ldm_x4(Bh[nb][0], Bh[nb][1], Bh[nb][2], Bh[nb][3],
                       smem_u32(&sBh[(warp_n + nb * 16 + b_row) * SP + k0 + b_kc]));
                ldm_x4(Bl[nb][0], Bl[nb][1], Bl[nb][2], Bl[nb][3],
                       smem_u32(&sBl[(warp_n + nb * 16 + b_row) * SP + k0 + b_kc]));
            }
#pragma unroll
            for (int mt = 0; mt < 4; mt++) {
                uint32_t Ah[4], Al[4];
                ldm_x4(Ah[0], Ah[1], Ah[2], Ah[3],
                       smem_u32(&sAh[(warp_m + mt * 16 + a_row) * SP + k0 + a_kc]));
#pragma unroll
                for (int nt = 0; nt < 4; nt++)
                    mma_bf16(acc[mt][nt], Ah, &Bh[nt >> 1][(nt & 1) * 2]);
#pragma unroll
                for (int nt = 0; nt < 4; nt++)
                    mma_bf16(acc[mt][nt], Ah, &Bl[nt >> 1][(nt & 1) * 2]);
                ldm_x4(Al[0], Al[1], Al[2], Al[3],
                       smem_u32(&sAl[(warp_m + mt * 16 + a_row) * SP + k0 + a_kc]));
#pragma unroll
                for (int nt = 0; nt < 4; nt++)
                    mma_bf16(acc[mt][nt], Al, &Bh[nt >> 1][(nt & 1) * 2]);
            }
        }
        __syncthreads();
    }
    // epilogue: bias + relu, split to bf16 hi/lo
#pragma unroll
    for (int mt = 0; mt < 4; mt++) {
        int r0 = m0 + warp_m + mt * 16 + (lane >> 2);
#pragma unroll
        for (int nt = 0; nt < 4; nt++) {
            int c = warp_n + nt * 8 + ((lane & 3) << 1);
            float b0 = b[c], b1 = b[c + 1];
            float v00 = fmaxf(acc[mt][nt][0] + b0, 0.0f);
            float v01 = fmaxf(acc[mt][nt][1] + b1, 0.0f);
            float v10 = fmaxf(acc[mt][nt][2] + b0, 0.0f);
            float v11 = fmaxf(acc[mt][nt][3] + b1, 0.0f);
            __nv_bfloat16 h00 = __float2bfloat16(v00), h01 = __float2bfloat16(v01);
            __nv_bfloat16 h10 = __float2bfloat16(v10), h11 = __float2bfloat16(v11);
            __nv_bfloat162 p;
            p.x = h00; p.y = h01;
            *(__nv_bfloat162*)&d_x1hi[(size_t)r0 * 128 + c] = p;
            p.x = __float2bfloat16(v00 - __bfloat162float(h00));
            p.y = __float2bfloat16(v01 - __bfloat162float(h01));
            *(__nv_bfloat162*)&d_x1lo[(size_t)r0 * 128 + c] = p;
            p.x = h10; p.y = h11;
            *(__nv_bfloat162*)&d_x1hi[(size_t)(r0 + 8) * 128 + c] = p;
            p.x = __float2bfloat16(v10 - __bfloat162float(h10));
            p.y = __float2bfloat16(v11 - __bfloat162float(h11));
            *(__nv_bfloat162*)&d_x1lo[(size_t)(r0 + 8) * 128 + c] = p;
        }
    }
}

// ---------------- g = x1 @ W_g^T via bf16-split mma (128x64 tile, R5-validated fragments) ----------------
__global__ __launch_bounds__(256) void k_g_tc() {
    extern __shared__ __nv_bfloat16 sm[];
    __nv_bfloat16* sAh = sm;            // 128*72
    __nv_bfloat16* sAl = sm + 9216;
    __nv_bfloat16* sBh = sm + 18432;    // 64*72
    __nv_bfloat16* sBl = sm + 23040;

    int m0 = blockIdx.x * 128;
    int tid = threadIdx.x;
    int wid = tid >> 5, lane = tid & 31;
    int warp_m = (wid >> 2) * 64;
    int warp_n = (wid & 3) * 16;

    float acc[4][2][4];
#pragma unroll
    for (int a = 0; a < 4; a++)
#pragma unroll
        for (int b = 0; b < 2; b++)
#pragma unroll
            for (int c = 0; c < 4; c++) acc[a][b][c] = 0.0f;

    int a_row = lane & 15, a_kc = (lane >> 4) << 3;
    int b_row = (lane & 7) + (((lane >> 4) & 1) << 3);
    int b_kc  = (((lane >> 3) & 1) << 3);

    for (int kc = 0; kc < 128; kc += 64) {
#pragma unroll
        for (int r = 0; r < 4; r++) {
            int idx = tid + r * 256;
            int row = idx >> 3, ch = idx & 7;
            *(uint4*)&sAh[row * SP + ch * 8] =
                ((const uint4*)(d_x1hi + (size_t)(m0 + row) * 128 + kc))[ch];
            *(uint4*)&sAl[row * SP + ch * 8] =
                ((const uint4*)(d_x1lo + (size_t)(m0 + row) * 128 + kc))[ch];
        }
#pragma unroll
        for (int r = 0; r < 2; r++) {
            int idx = tid + r * 256;
            int row = idx >> 3, ch = idx & 7;
            *(uint4*)&sBh[row * SP + ch * 8] =
                ((const uint4*)(d_wghi + (size_t)row * 128 + kc))[ch];
            *(uint4*)&sBl[row * SP + ch * 8] =
                ((const uint4*)(d_wglo + (size_t)row * 128 + kc))[ch];
        }
        __syncthreads();
#pragma unroll
        for (int ks = 0; ks < 4; ks++) {
            int k0 = ks * 16;
            uint32_t Bh[4], Bl[4];
            ldm_x4(Bh[0], Bh[1], Bh[2], Bh[3],
                   smem_u32(&sBh[(warp_n + b_row) * SP + k0 + b_kc]));
            ldm_x4(Bl[0], Bl[1], Bl[2], Bl[3],
                   smem_u32(&sBl[(warp_n + b_row) * SP + k0 + b_kc]));
#pragma unroll
            for (int mt = 0; mt < 4; mt++) {
                uint32_t Ah[4], Al[4];
                ldm_x4(Ah[0], Ah[1], Ah[2], Ah[3],
                       smem_u32(&sAh[(warp_m + mt * 16 + a_row) * SP + k0 + a_kc]));
                mma_bf16(acc[mt][0], Ah, &Bh[0]);
                mma_bf16(acc[mt][1], Ah, &Bh[2]);
                mma_bf16(acc[mt][0], Ah, &Bl[0]);
                mma_bf16(acc[mt][1], Ah, &Bl[2]);
                ldm_x4(Al[0], Al[1], Al[2], Al[3],
                       smem_u32(&sAl[(warp_m + mt * 16 + a_row) * SP + k0 + a_kc]));
                mma_bf16(acc[mt][0], Al, &Bh[0]);
                mma_bf16(acc[mt][1], Al, &Bh[2]);
            }
        }
        __syncthreads();
    }
#pragma unroll
    for (int mt = 0; mt < 4; mt++) {
        int r0 = m0 + warp_m + mt * 16 + (lane >> 2);
#pragma unroll
        for (int nt = 0; nt < 2; nt++) {
            int c0 = warp_n + nt * 8 + ((lane & 3) << 1);
            d_g[(size_t)r0 * 64 + c0]           = acc[mt][nt][0];
            d_g[(size_t)r0 * 64 + c0 + 1]       = acc[mt][nt][1];
            d_g[(size_t)(r0 + 8) * 64 + c0]     = acc[mt][nt][2];
            d_g[(size_t)(r0 + 8) * 64 + c0 + 1] = acc[mt][nt][3];
        }
    }
}

// ---------------- attention scores ----------------
__global__ void k_sc(const float* __restrict__ asrc, const float* __restrict__ adst) {
    int warp = (blockIdx.x * blockDim.x + threadIdx.x) >> 5;
    int lane = threadIdx.x & 31;
    if (warp >= NN) return;
    float g0 = d_g[(size_t)warp * 64 + lane];
    float g1 = d_g[(size_t)warp * 64 + 32 + lane];
    float vs = g0 * asrc[lane] + g1 * asrc[32 + lane];
    float vd = g0 * adst[lane] + g1 * adst[32 + lane];
#pragma unroll
    for (int o = 16; o; o >>= 1) {
        vs += __shfl_xor_sync(0xffffffffu, vs, o);
        vd += __shfl_xor_sync(0xffffffffu, vd, o);
    }
    if (lane == 0) { d_scs[warp] = vs; d_scd[warp] = vd; }
}

// ---------------- GAT aggregation ----------------
__global__ void k_gat(const float* __restrict__ bg) {
    int warp = (blockIdx.x * blockDim.x + threadIdx.x) >> 5;
    int lane = threadIdx.x & 31;
    if (warp >= NN) return;
    int s0 = d_off[warp], s1 = d_off[warp + 1];
    float scd = d_scd[warp];

    float mx = -1e30f;
    for (int j = s0 + lane; j < s1; j += 32) {
        int s = d_csr[j];
        float e = d_scs[s] + scd;
        e = e > 0.0f ? e : NEG * e;
        mx = fmaxf(mx, e);
    }
#pragma unroll
    for (int o = 16; o; o >>= 1) mx = fmaxf(mx, __shfl_xor_sync(0xffffffffu, mx, o));

    float sum = 0.0f;
    for (int j = s0 + lane; j < s1; j += 32) {
        int s = d_csr[j];
        float e = d_scs[s] + scd;
        e = e > 0.0f ? e : NEG * e;
        sum += __expf(e - mx);
    }
#pragma unroll
    for (int o = 16; o; o >>= 1) sum += __shfl_xor_sync(0xffffffffu, sum, o);
    float inv = 1.0f / sum;

    float a0 = 0.0f, a1 = 0.0f;
    for (int j = s0; j < s1; j++) {
        int s = d_csr[j];
        float e = d_scs[s] + scd;
        e = e > 0.0f ? e : NEG * e;
        float w = __expf(e - mx) * inv;
        a0 = fmaf(w, d_g[(size_t)s * 64 + lane], a0);
        a1 = fmaf(w, d_g[(size_t)s * 64 + 32 + lane], a1);
    }
    d_h[(size_t)warp * 64 + lane]      = a0 + bg[lane];
    d_h[(size_t)warp * 64 + 32 + lane] = a1 + bg[32 + lane];
}

// ---------------- s_ = sigmoid(h h^T): full-square 128x128 bf16-split mma ----------------
#define CP2 132
__global__ __launch_bounds__(256) void k_s_tc(float* __restrict__ out) {
    extern __shared__ __nv_bfloat16 sm[];
    __nv_bfloat16* sAh = sm;            // 128*72
    __nv_bfloat16* sAl = sm + 9216;
    __nv_bfloat16* sBh = sm + 18432;
    __nv_bfloat16* sBl = sm + 27648;
    float* Cs = (float*)sm;             // [128][CP2] after compute

    int i0 = blockIdx.y * 128, j0 = blockIdx.x * 128;
    int tid = threadIdx.x;

#pragma unroll
    for (int r = 0; r < 4; r++) {
        int idx = tid + r * 256;
        int row = idx >> 3, ch = idx & 7;
        *(uint4*)&sAh[row * SP + ch * 8] =
            ((const uint4*)(d_hhi + (size_t)(i0 + row) * 64))[ch];
        *(uint4*)&sAl[row * SP + ch * 8] =
            ((const uint4*)(d_hlo + (size_t)(i0 + row) * 64))[ch];
        *(uint4*)&sBh[row * SP + ch * 8] =
            ((const uint4*)(d_hhi + (size_t)(j0 + row) * 64))[ch];
        *(uint4*)&sBl[row * SP + ch * 8] =
            ((const uint4*)(d_hlo + (size_t)(j0 + row) * 64))[ch];
    }
    __syncthreads();

    int wid = tid >> 5, lane = tid & 31;
    int warp_m = (wid & 1) * 64;
    int warp_n = (wid >> 1) * 32;

    float acc[4][4][4];
#pragma unroll
    for (int i = 0; i < 4; i++)
#pragma unroll
        for (int j = 0; j < 4; j++)
#pragma unroll
            for (int c = 0; c < 4; c++) acc[i][j][c] = 0.0f;

    int a_row = lane & 15, a_kc = (lane >> 4) << 3;
    int b_row = (lane & 7) + (((lane >> 4) & 1) << 3);
    int b_kc  = (((lane >> 3) & 1) << 3);

#pragma unroll
    for (int ks = 0; ks < 4; ks++) {
        int k0 = ks * 16;
        uint32_t Bh[2][4], Bl[2][4];
#pragma unroll
        for (int nb = 0; nb < 2; nb++) {
            ldm_x4(Bh[nb][0], Bh[nb][1], Bh[nb][2], Bh[nb][3],
                   smem_u32(&sBh[(warp_n + nb * 16 + b_row) * SP + k0 + b_kc]));
            ldm_x4(Bl[nb][0], Bl[nb][1], Bl[nb][2], Bl[nb][3],
                   smem_u32(&sBl[(warp_n + nb * 16 + b_row) * SP + k0 + b_kc]));
        }
#pragma unroll
        for (int mt = 0; mt < 4; mt++) {
            uint32_t Ah[4], Al[4];
            ldm_x4(Ah[0], Ah[1], Ah[2], Ah[3],
                   smem_u32(&sAh[(warp_m + mt * 16 + a_row) * SP + k0 + a_kc]));
#pragma unroll
            for (int nt = 0; nt < 4; nt++)
                mma_bf16(acc[mt][nt], Ah, &Bh[nt >> 1][(nt & 1) * 2]);
#pragma unroll
            for (int nt = 0; nt < 4; nt++)
                mma_bf16(acc[mt][nt], Ah, &Bl[nt >> 1][(nt & 1) * 2]);
            ldm_x4(Al[0], Al[1], Al[2], Al[3],
                   smem_u32(&sAl[(warp_m + mt * 16 + a_row) * SP + k0 + a_kc]));
#pragma unroll
            for (int nt = 0; nt < 4; nt++)
                mma_bf16(acc[mt][nt], Al, &Bh[nt >> 1][(nt & 1) * 2]);
        }
    }
    __syncthreads();   // operands dead; reuse smem as Cs

#pragma unroll
    for (int mt = 0; mt < 4; mt++) {
        int r0 = warp_m + mt * 16 + (lane >> 2);
#pragma unroll
        for (int nt = 0; nt < 4; nt++) {
            int c0 = warp_n + nt * 8 + ((lane & 3) << 1);
            Cs[r0 * CP2 + c0]           = sigf(acc[mt][nt][0]);
            Cs[r0 * CP2 + c0 + 1]       = sigf(acc[mt][nt][1]);
            Cs[(r0 + 8) * CP2 + c0]     = sigf(acc[mt][nt][2]);
            Cs[(r0 + 8) * CP2 + c0 + 1] = sigf(acc[mt][nt][3]);
        }
    }
    __syncthreads();

#pragma unroll
    for (int itr = 0; itr < 16; itr++) {
        int slot = tid + itr * 256;
        int row = slot >> 5, c4 = slot & 31;
        float4 v = *(const float4*)&Cs[row * CP2 + c4 * 4];
        *(float4*)&out[(size_t)(i0 + row) * NN + j0 + c4 * 4] = v;
    }
}

// ---------------- xtraw = x^T @ W_a1^T via bf16-split mma (split-K, atomic accum) ----------------
// A = x^T [512 d][12288 k] (d_xThi/lo), B = W_a1 [128 e][12288 k] (d_wa1hi/lo)
// grid (4 m-blocks, 24 k-slabs of 512)
__global__ __launch_bounds__(256) void k_att1_tc() {
    extern __shared__ __nv_bfloat16 sm[];
    __nv_bfloat16* sAh = sm;            // 128*72
    __nv_bfloat16* sAl = sm + 9216;
    __nv_bfloat16* sBh = sm + 18432;
    __nv_bfloat16* sBl = sm + 27648;

    int m0 = blockIdx.x * 128;
    int kbase = blockIdx.y * 512;
    int tid = threadIdx.x;
    int wid = tid >> 5, lane = tid & 31;
    int warp_m = (wid & 1) * 64;
    int warp_n = (wid >> 1) * 32;

    float acc[4][4][4];
#pragma unroll
    for (int i = 0; i < 4; i++)
#pragma unroll
        for (int j = 0; j < 4; j++)
#pragma unroll
            for (int c = 0; c < 4; c++) acc[i][j][c] = 0.0f;

    int a_row = lane & 15, a_kc = (lane >> 4) << 3;
    int b_row = (lane & 7) + (((lane >> 4) & 1) << 3);
    int b_kc  = (((lane >> 3) & 1) << 3);

    for (int kc = 0; kc < 512; kc += 64) {
        int kk = kbase + kc;
#pragma unroll
        for (int r = 0; r < 4; r++) {
            int idx = tid + r * 256;
            int row = idx >> 3, ch = idx & 7;
            *(uint4*)&sAh[row * SP + ch * 8] =
                ((const uint4*)(d_xThi + (size_t)(m0 + row) * NN + kk))[ch];
            *(uint4*)&sAl[row * SP + ch * 8] =
                ((const uint4*)(d_xTlo + (size_t)(m0 + row) * NN + kk))[ch];
            *(uint4*)&sBh[row * SP + ch * 8] =
                ((const uint4*)(d_wa1hi + (size_t)row * NN + kk))[ch];
            *(uint4*)&sBl[row * SP + ch * 8] =
                ((const uint4*)(d_wa1lo + (size_t)row * NN + kk))[ch];
        }
        __syncthreads();
#pragma unroll
        for (int ks = 0; ks < 4; ks++) {
            int k0 = ks * 16;
            uint32_t Bh[2][4], Bl[2][4];
#pragma unroll
            for (int nb = 0; nb < 2; nb++) {
                ldm_x4(Bh[nb][0], Bh[nb][1], Bh[nb][2], Bh[nb][3],
                       smem_u32(&sBh[(warp_n + nb * 16 + b_row) * SP + k0 + b_kc]));
                ldm_x4(Bl[nb][0], Bl[nb][1], Bl[nb][2], Bl[nb][3],
                       smem_u32(&sBl[(warp_n + nb * 16 + b_row) * SP + k0 + b_kc]));
            }
#pragma unroll
            for (int mt = 0; mt < 4; mt++) {
                uint32_t Ah[4], Al[4];
                ldm_x4(Ah[0], Ah[1], Ah[2], Ah[3],
                       smem_u32(&sAh[(warp_m + mt * 16 + a_row) * SP + k0 + a_kc]));
#pragma unroll
                for (int nt = 0; nt < 4; nt++)
                    mma_bf16(acc[mt][nt], Ah, &Bh[nt >> 1][(nt & 1) * 2]);
#pragma unroll
                for (int nt = 0; nt < 4; nt++)
                    mma_bf16(acc[mt][nt], Ah, &Bl[nt >> 1][(nt & 1) * 2]);
                ldm_x4(Al[0], Al[1], Al[2], Al[3],
                       smem_u32(&sAl[(warp_m + mt * 16 + a_row) * SP + k0 + a_kc]));
#pragma unroll
                for (int nt = 0; nt < 4; nt++)
                    mma_bf16(acc[mt][nt], Al, &Bh[nt >> 1][(nt & 1) * 2]);
            }
        }
        __syncthreads();
    }
#pragma unroll
    for (int mt = 0; mt < 4; mt++) {
        int r0 = m0 + warp_m + mt * 16 + (lane >> 2);
#pragma unroll
        for (int nt = 0; nt < 4; nt++) {
            int c = warp_n + nt * 8 + ((lane & 3) << 1);
            atomicAdd(&d_xtraw[(size_t)r0 * 128 + c],           acc[mt][nt][0]);
            atomicAdd(&d_xtraw[(size_t)r0 * 128 + c + 1],       acc[mt][nt][1]);
            atomicAdd(&d_xtraw[(size_t)(r0 + 8) * 128 + c],     acc[mt][nt][2]);
            atomicAdd(&d_xtraw[(size_t)(r0 + 8) * 128 + c + 1], acc[mt][nt][3]);
        }
    }
}

__global__ void k_xa(const float* __restrict__ ba1, const float* __restrict__ W2,
                     const float* __restrict__ ba2) {
    int t = blockIdx.x * blockDim.x + threadIdx.x;
    if (t >= DIN * DOUT) return;
    int d = t >> 6, o = t & 63;
    float s = 0.0f;
#pragma unroll 4
    for (int e = 0; e < 128; e++) {
        float v = d_xtraw[(size_t)d * 128 + e] + ba1[e];
        v = v > 0.0f ? v : 0.0f;
        s = fmaf(v, W2[(size_t)o * 128 + e], s);
    }
    d_xa[t] = s + ba2[o];
}

// ---------------- x_ = h @ xa^T ----------------
__global__ __launch_bounds__(256) void k_xout(float* __restrict__ out) {
    __shared__ float As[32][68];
    __shared__ float Bs[32][132];
    int m0 = blockIdx.x * 64;
    int d0 = blockIdx.y * 128;
    int tid = threadIdx.x;
    int tx = tid & 15, ty = tid >> 4;
    float acc[4][8];
#pragma unroll
    for (int i = 0; i < 4; i++)
#pragma unroll
        for (int j = 0; j < 8; j++) acc[i][j] = 0.0f;

    for (int k0 = 0; k0 < 64; k0 += 32) {
#pragma unroll
        for (int t = 0; t < 2; t++) {
            int slot = tid + t * 256;
            int m = slot & 63, kq = slot >> 6;
            float4 v = *(const float4*)&d_h[(size_t)(m0 + m) * 64 + k0 + kq * 4];
            As[kq * 4 + 0][m] = v.x; As[kq * 4 + 1][m] = v.y;
            As[kq * 4 + 2][m] = v.z; As[kq * 4 + 3][m] = v.w;
        }
#pragma unroll
        for (int t = 0; t < 4; t++) {
            int slot = tid + t * 256;
            int n = slot & 127, kq = slot >> 7;
            float4 v = *(const float4*)&d_xa[(size_t)(d0 + n) * 64 + k0 + kq * 4];
            Bs[kq * 4 + 0][n] = v.x; Bs[kq * 4 + 1][n] = v.y;
            Bs[kq * 4 + 2][n] = v.z; Bs[kq * 4 + 3][n] = v.w;
        }
        __syncthreads();
#pragma unroll
        for (int kk = 0; kk < 32; kk++) {
            float4 av = *(const float4*)&As[kk][ty * 4];
            float4 b0 = *(const float4*)&Bs[kk][tx * 8];
            float4 b1 = *(const float4*)&Bs[kk][tx * 8 + 4];
            float a[4] = {av.x, av.y, av.z, av.w};
            float bb[8] = {b0.x, b0.y, b0.z, b0.w, b1.x, b1.y, b1.z, b1.w};
#pragma unroll
            for (int i = 0; i < 4; i++)
#pragma unroll
                for (int j = 0; j < 8; j++) acc[i][j] = fmaf(a[i], bb[j], acc[i][j]);
        }
        __syncthreads();
    }
#pragma unroll
    for (int i = 0; i < 4; i++) {
        size_t row = (size_t)(m0 + ty * 4 + i);
        float4 v0 = {acc[i][0], acc[i][1], acc[i][2], acc[i][3]};
        float4 v1 = {acc[i][4], acc[i][5], acc[i][6], acc[i][7]};
        *(float4*)&out[row * 512 + d0 + tx * 8]     = v0;
        *(float4*)&out[row * 512 + d0 + tx * 8 + 4] = v1;
    }
}

// ---------------- launch ----------------
extern "C" void kernel_launch(void* const* d_in, const int* in_sizes, int n_in,
                              void* d_out, int out_size) {
    const float* x     = (const float*)d_in[0];
    const float* Ws1   = (const float*)d_in[1];
    const float* bs1   = (const float*)d_in[2];
    const float* Wg    = (const float*)d_in[3];
    const float* asrc  = (const float*)d_in[4];
    const float* adst  = (const float*)d_in[5];
    const float* bg    = (const float*)d_in[6];
    const float* Wa1   = (const float*)d_in[7];
    const float* ba1   = (const float*)d_in[8];
    const float* Wa2   = (const float*)d_in[9];
    const float* ba2   = (const float*)d_in[10];
    const void*  ei    = d_in[11];

    float* out   = (float*)d_out;
    float* out_x = out;                          // [12288, 512]
    float* out_s = out + (size_t)NN * DIN;       // [12288, 12288]

    const int SMEM_BIG = 73728;
    const int SMEM_G   = 55296;
    static int smem_set = 0;
    if (!smem_set) {
        cudaFuncSetAttribute(k_fc1_tc,  cudaFuncAttributeMaxDynamicSharedMemorySize, SMEM_BIG);
        cudaFuncSetAttribute(k_s_tc,    cudaFuncAttributeMaxDynamicSharedMemorySize, SMEM_BIG);
        cudaFuncSetAttribute(k_att1_tc, cudaFuncAttributeMaxDynamicSharedMemorySize, SMEM_BIG);
        cudaFuncSetAttribute(k_g_tc,    cudaFuncAttributeMaxDynamicSharedMemorySize, SMEM_G);
        smem_set = 1;
    }

    // CSR build + input splits
    k_detect<<<1, 256>>>((const int*)ei);
    k_init<<<256, 256>>>();
    k_count<<<NE / 256, 256>>>(ei);
    k_splitx<<<NN * DIN / 2048, 256>>>(x);
    k_splitw1<<<DEMB * DIN / 2048, 256>>>(Ws1);
    k_splitwa1<<<DEMB * NN / 2048, 256>>>(Wa1);
    k_splitwg<<<DOUT * DEMB / 2048, 256>>>(Wg);
    k_tsplit<<<dim3(NN / 64, DIN / 64), 256>>>(x);
    k_scan<<<1, 1024>>>();
    k_scatter<<<TOTE / 256, 256>>>(ei);

    // encoder + GAT
    k_fc1_tc<<<NN / 128, 256, SMEM_BIG>>>(bs1);
    k_g_tc<<<NN / 128, 256, SMEM_G>>>();
    k_sc<<<NN / 8, 256>>>(asrc, adst);
    k_gat<<<NN / 8, 256>>>(bg);

    // structure decoder (tensor cores, full square)
    k_split<<<NN * DOUT / 2048, 256>>>();
    k_s_tc<<<dim3(NN / 128, NN / 128), 256, SMEM_BIG>>>(out_s);

    // attribute decoder (tensor cores, split-K)
    k_att1_tc<<<dim3(DIN / 128, 24), 256, SMEM_BIG>>>();
    k_xa<<<(DIN * DOUT) / 256, 256>>>(ba1, Wa2, ba2);
    k_xout<<<dim3(NN / 64, DIN / 128), 256>>>(out_x);
}

// round 13
// speedup vs baseline: 2.4830x; 1.4731x over previous
#include <cuda_runtime.h>
#include <cuda_bf16.h>
#include <cstdint>

#define NN   12288
#define DIN  512
#define DEMB 128
#define DOUT 64
#define NE   393216
#define TOTE (NE + NN)     // 405504
#define NEG  0.2f

// ---------------- scratch (device globals; no allocation) ----------------
__device__ __nv_bfloat16 d_x1hi[NN * DEMB];
__device__ __nv_bfloat16 d_x1lo[NN * DEMB];
__device__ float d_g[NN * DOUT];
__device__ float d_scs[NN];
__device__ float d_scd[NN];
__device__ float d_h[NN * DOUT];
__device__ __nv_bfloat16 d_hhi[NN * DOUT];
__device__ __nv_bfloat16 d_hlo[NN * DOUT];
__device__ __nv_bfloat16 d_xhi[NN * DIN];
__device__ __nv_bfloat16 d_xlo[NN * DIN];
__device__ __nv_bfloat16 d_xThi[DIN * NN];   // x^T, bf16 hi
__device__ __nv_bfloat16 d_xTlo[DIN * NN];
__device__ __nv_bfloat16 d_w1hi[DEMB * DIN];
__device__ __nv_bfloat16 d_w1lo[DEMB * DIN];
__device__ __nv_bfloat16 d_wa1hi[DEMB * NN];
__device__ __nv_bfloat16 d_wa1lo[DEMB * NN];
__device__ __nv_bfloat16 d_wghi[DOUT * DEMB];
__device__ __nv_bfloat16 d_wglo[DOUT * DEMB];
__device__ __nv_bfloat16 d_xahi[DIN * DOUT];
__device__ __nv_bfloat16 d_xalo[DIN * DOUT];
__device__ float d_xtraw[DIN * DEMB];
__device__ float d_xa[DIN * DOUT];
__device__ int   d_deg[NN];
__device__ int   d_off[NN + 1];
__device__ int   d_fill[NN];
__device__ int   d_csr[TOTE];
__device__ int   d_is64;

// ---------------- helpers ----------------
__device__ __forceinline__ float sigf(float v) {
    return __fdividef(1.0f, 1.0f + __expf(-v));
}
__device__ __forceinline__ int clampn(int v) {
    v = v < 0 ? 0 : v;
    return v >= NN ? NN - 1 : v;
}
__device__ __forceinline__ uint32_t smem_u32(const void* p) {
    return (uint32_t)__cvta_generic_to_shared(p);
}
__device__ __forceinline__ void ldm_x4(uint32_t& r0, uint32_t& r1, uint32_t& r2,
                                       uint32_t& r3, uint32_t addr) {
    asm volatile("ldmatrix.sync.aligned.m8n8.x4.shared.b16 {%0,%1,%2,%3}, [%4];"
                 : "=r"(r0), "=r"(r1), "=r"(r2), "=r"(r3) : "r"(addr));
}
__device__ __forceinline__ void mma_bf16(float* c, const uint32_t* a, const uint32_t* b) {
    asm volatile(
        "mma.sync.aligned.m16n8k16.row.col.f32.bf16.bf16.f32 "
        "{%0,%1,%2,%3}, {%4,%5,%6,%7}, {%8,%9}, {%0,%1,%2,%3};"
        : "+f"(c[0]), "+f"(c[1]), "+f"(c[2]), "+f"(c[3])
        : "r"(a[0]), "r"(a[1]), "r"(a[2]), "r"(a[3]), "r"(b[0]), "r"(b[1]));
}

// ---------------- dtype probe ----------------
__global__ void k_detect(const int* __restrict__ ei32) {
    __shared__ int any;
    if (threadIdx.x == 0) any = 0;
    __syncthreads();
    if (ei32[threadIdx.x * 2 + 1] != 0) any = 1;
    __syncthreads();
    if (threadIdx.x == 0) d_is64 = (any == 0) ? 1 : 0;
}

__global__ void k_init() {
    int t = blockIdx.x * blockDim.x + threadIdx.x;
    if (t < DIN * DEMB) d_xtraw[t] = 0.0f;
    if (t < NN) d_deg[t] = 1;
}

__global__ void k_count(const void* __restrict__ ei) {
    int e = blockIdx.x * blockDim.x + threadIdx.x;
    if (e < NE) {
        int dst;
        if (d_is64) dst = (int)((const long long*)ei)[NE + e];
        else        dst = ((const int*)ei)[NE + e];
        atomicAdd(&d_deg[clampn(dst)], 1);
    }
}

// warp-shuffle scan (12 values/thread, 1024 threads)
__global__ void k_scan() {
    __shared__ int wsum[32];
    int t = threadIdx.x, lane = t & 31, w = t >> 5;
    int base = t * 12;
    int loc[12];
    int s = 0;
#pragma unroll
    for (int i = 0; i < 12; i++) { loc[i] = d_deg[base + i]; s += loc[i]; }
    int pre = s;
#pragma unroll
    for (int o = 1; o < 32; o <<= 1) {
        int v = __shfl_up_sync(0xffffffffu, pre, o);
        if (lane >= o) pre += v;
    }
    if (lane == 31) wsum[w] = pre;
    __syncthreads();
    if (w == 0) {
        int v = wsum[lane];
#pragma unroll
        for (int o = 1; o < 32; o <<= 1) {
            int u = __shfl_up_sync(0xffffffffu, v, o);
            if (lane >= o) v += u;
        }
        wsum[lane] = v;
    }
    __syncthreads();
    int run = pre - s + (w ? wsum[w - 1] : 0);
#pragma unroll
    for (int i = 0; i < 12; i++) {
        d_off[base + i]  = run;
        d_fill[base + i] = run;
        run += loc[i];
    }
    if (t == 1023) d_off[NN] = run;
}

__global__ void k_scatter(const void* __restrict__ ei) {
    int e = blockIdx.x * blockDim.x + threadIdx.x;
    if (e < NE) {
        int src, dst;
        if (d_is64) {
            src = (int)((const long long*)ei)[e];
            dst = (int)((const long long*)ei)[NE + e];
        } else {
            src = ((const int*)ei)[e];
            dst = ((const int*)ei)[NE + e];
        }
        int p = atomicAdd(&d_fill[clampn(dst)], 1);
        if (p < TOTE) d_csr[p] = clampn(src);
    } else if (e < TOTE) {
        int n = e - NE;
        int p = atomicAdd(&d_fill[n], 1);
        if (p < TOTE) d_csr[p] = n;
    }
}

// ---------------- split kernels (vectorized: 8 elems/thread) ----------------
__device__ __forceinline__ void split8(const float* __restrict__ src,
                                       __nv_bfloat16* __restrict__ hi,
                                       __nv_bfloat16* __restrict__ lo, size_t base) {
    float4 v0 = *(const float4*)&src[base];
    float4 v1 = *(const float4*)&src[base + 4];
    float f[8] = {v0.x, v0.y, v0.z, v0.w, v1.x, v1.y, v1.z, v1.w};
    __nv_bfloat16 h[8], l[8];
#pragma unroll
    for (int i = 0; i < 8; i++) {
        h[i] = __float2bfloat16(f[i]);
        l[i] = __float2bfloat16(f[i] - __bfloat162float(h[i]));
    }
    *(uint4*)&hi[base] = *(uint4*)h;
    *(uint4*)&lo[base] = *(uint4*)l;
}
__global__ void k_splitx(const float* __restrict__ x) {
    size_t base = (size_t)(blockIdx.x * blockDim.x + threadIdx.x) * 8;
    split8(x, d_xhi, d_xlo, base);
}
__global__ void k_splitw1(const float* __restrict__ W) {
    size_t base = (size_t)(blockIdx.x * blockDim.x + threadIdx.x) * 8;
    split8(W, d_w1hi, d_w1lo, base);
}
__global__ void k_splitwa1(const float* __restrict__ W) {
    size_t base = (size_t)(blockIdx.x * blockDim.x + threadIdx.x) * 8;
    split8(W, d_wa1hi, d_wa1lo, base);
}
__global__ void k_splitwg(const float* __restrict__ W) {
    size_t base = (size_t)(blockIdx.x * blockDim.x + threadIdx.x) * 8;
    split8(W, d_wghi, d_wglo, base);
}
__global__ void k_split() {
    size_t base = (size_t)(blockIdx.x * blockDim.x + threadIdx.x) * 8;
    split8(d_h, d_hhi, d_hlo, base);
}
__global__ void k_splitxa() {
    size_t base = (size_t)(blockIdx.x * blockDim.x + threadIdx.x) * 8;
    split8(d_xa, d_xahi, d_xalo, base);
}

// ---------------- transpose+split x: [k][d] fp32 -> x^T [d][k] bf16 hi/lo ----------------
__global__ __launch_bounds__(256) void k_tsplit(const float* __restrict__ x) {
    __shared__ __nv_bfloat16 shhi[64 * 68];
    __shared__ __nv_bfloat16 shlo[64 * 68];
    int k0 = blockIdx.x * 64, d0 = blockIdx.y * 64;
    int tid = threadIdx.x;
#pragma unroll
    for (int i = 0; i < 4; i++) {
        int slot = tid + i * 256;
        int kk = slot >> 4, q = slot & 15;
        float4 v = *(const float4*)&x[(size_t)(k0 + kk) * 512 + d0 + q * 4];
        __nv_bfloat16 h[4], l[4];
        float f[4] = {v.x, v.y, v.z, v.w};
#pragma unroll
        for (int u = 0; u < 4; u++) {
            h[u] = __float2bfloat16(f[u]);
            l[u] = __float2bfloat16(f[u] - __bfloat162float(h[u]));
        }
        *(uint2*)&shhi[kk * 68 + q * 4] = *(uint2*)h;
        *(uint2*)&shlo[kk * 68 + q * 4] = *(uint2*)l;
    }
    __syncthreads();
#pragma unroll
    for (int i = 0; i < 4; i++) {
        int slot = tid + i * 256;
        int arr = slot >> 9;
        int s2 = slot & 511;
        int dd = s2 >> 3, qc = s2 & 7;
        const __nv_bfloat16* sh = arr ? shlo : shhi;
        __nv_bfloat16 vals[8];
#pragma unroll
        for (int u = 0; u < 8; u++) vals[u] = sh[(qc * 8 + u) * 68 + dd];
        __nv_bfloat16* dst = arr ? d_xTlo : d_xThi;
        *(uint4*)&dst[(size_t)(d0 + dd) * NN + k0 + qc * 8] = *(uint4*)vals;
    }
}

#define SP 72    // operand smem pitch (halves)

// ---------------- x1 = relu(x @ W_s1^T + b) via bf16-split mma (outputs bf16 hi/lo) ----------------
__global__ __launch_bounds__(256) void k_fc1_tc(const float* __restrict__ b) {
    extern __shared__ __nv_bfloat16 sm[];
    __nv_bfloat16* sAh = sm;
    __nv_bfloat16* sAl = sm + 9216;
    __nv_bfloat16* sBh = sm + 18432;
    __nv_bfloat16* sBl = sm + 27648;

    int m0 = blockIdx.x * 128;
    int tid = threadIdx.x;
    int wid = tid >> 5, lane = tid & 31;
    int warp_m = (wid & 1) * 64;
    int warp_n = (wid >> 1) * 32;

    float acc[4][4][4];
#pragma unroll
    for (int i = 0; i < 4; i++)
#pragma unroll
        for (int j = 0; j < 4; j++)
#pragma unroll
            for (int c = 0; c < 4; c++) acc[i][j][c] = 0.0f;

    int a_row = lane & 15, a_kc = (lane >> 4) << 3;
    int b_row = (lane & 7) + (((lane >> 4) & 1) << 3);
    int b_kc  = (((lane >> 3) & 1) << 3);

    for (int kc = 0; kc < 512; kc += 64) {
#pragma unroll
        for (int r = 0; r < 4; r++) {
            int idx = tid + r * 256;
            int row = idx >> 3, ch = idx & 7;
            *(uint4*)&sAh[row * SP + ch * 8] =
                ((const uint4*)(d_xhi + (size_t)(m0 + row) * 512 + kc))[ch];
            *(uint4*)&sAl[row * SP + ch * 8] =
                ((const uint4*)(d_xlo + (size_t)(m0 + row) * 512 + kc))[ch];
            *(uint4*)&sBh[row * SP + ch * 8] =
                ((const uint4*)(d_w1hi + (size_t)row * 512 + kc))[ch];
            *(uint4*)&sBl[row * SP + ch * 8] =
                ((const uint4*)(d_w1lo + (size_t)row * 512 + kc))[ch];
        }
        __syncthreads();
#pragma unroll
        for (int ks = 0; ks < 4; ks++) {
            int k0 = ks * 16;
            uint32_t Bh[2][4], Bl[2][4];
#pragma unroll
            for (int nb = 0; nb < 2; nb++) {
                ldm_x4(Bh[nb][0], Bh[nb][1], Bh[nb][2], Bh[nb][3],
                       smem_u32(&sBh[(warp_n + nb * 16 + b_row) * SP + k0 + b_kc]));
                ldm_x4(Bl[nb][0], Bl[nb][1], Bl[nb][2], Bl[nb][3],
                       smem_u32(&sBl[(warp_n + nb * 16 + b_row) * SP + k0 + b_kc]));
            }
#pragma unroll
            for (int mt = 0; mt < 4; mt++) {
                uint32_t Ah[4], Al[4];
                ldm_x4(Ah[0], Ah[1], Ah[2], Ah[3],
                       smem_u32(&sAh[(warp_m + mt * 16 + a_row) * SP + k0 + a_kc]));
#pragma unroll
                for (int nt = 0; nt < 4; nt++)
                    mma_bf16(acc[mt][nt], Ah, &Bh[nt >> 1][(nt & 1) * 2]);
#pragma unroll
                for (int nt = 0; nt < 4; nt++)
                    mma_bf16(acc[mt][nt], Ah, &Bl[nt >> 1][(nt & 1) * 2]);
                ldm_x4(Al[0], Al[1], Al[2], Al[3],
                       smem_u32(&sAl[(warp_m + mt * 16 + a_row) * SP + k0 + a_kc]));
#pragma unroll
                for (int nt = 0; nt < 4; nt++)
                    mma_bf16(acc[mt][nt], Al, &Bh[nt >> 1][(nt & 1) * 2]);
            }
        }
        __syncthreads();
    }
#pragma unroll
    for (int mt = 0; mt < 4; mt++) {
        int r0 = m0 + warp_m + mt * 16 + (lane >> 2);
#pragma unroll
        for (int nt = 0; nt < 4; nt++) {
            int c = warp_n + nt * 8 + ((lane & 3) << 1);
            float b0 = b[c], b1 = b[c + 1];
            float v00 = fmaxf(acc[mt][nt][0] + b0, 0.0f);
            float v01 = fmaxf(acc[mt][nt][1] + b1, 0.0f);
            float v10 = fmaxf(acc[mt][nt][2] + b0, 0.0f);
            float v11 = fmaxf(acc[mt][nt][3] + b1, 0.0f);
            __nv_bfloat16 h00 = __float2bfloat16(v00), h01 = __float2bfloat16(v01);
            __nv_bfloat16 h10 = __float2bfloat16(v10), h11 = __float2bfloat16(v11);
            __nv_bfloat162 p;
            p.x = h00; p.y = h01;
            *(__nv_bfloat162*)&d_x1hi[(size_t)r0 * 128 + c] = p;
            p.x = __float2bfloat16(v00 - __bfloat162float(h00));
            p.y = __float2bfloat16(v01 - __bfloat162float(h01));
            *(__nv_bfloat162*)&d_x1lo[(size_t)r0 * 128 + c] = p;
            p.x = h10; p.y = h11;
            *(__nv_bfloat162*)&d_x1hi[(size_t)(r0 + 8) * 128 + c] = p;
            p.x = __float2bfloat16(v10 - __bfloat162float(h10));
            p.y = __float2bfloat16(v11 - __bfloat162float(h11));
            *(__nv_bfloat162*)&d_x1lo[(size_t)(r0 + 8) * 128 + c] = p;
        }
    }
}

// ---------------- g = x1 @ W_g^T via bf16-split mma (128x64 tile) ----------------
__global__ __launch_bounds__(256) void k_g_tc() {
    extern __shared__ __nv_bfloat16 sm[];
    __nv_bfloat16* sAh = sm;
    __nv_bfloat16* sAl = sm + 9216;
    __nv_bfloat16* sBh = sm + 18432;
    __nv_bfloat16* sBl = sm + 23040;

    int m0 = blockIdx.x * 128;
    int tid = threadIdx.x;
    int wid = tid >> 5, lane = tid & 31;
    int warp_m = (wid >> 2) * 64;
    int warp_n = (wid & 3) * 16;

    float acc[4][2][4];
#pragma unroll
    for (int a = 0; a < 4; a++)
#pragma unroll
        for (int b = 0; b < 2; b++)
#pragma unroll
            for (int c = 0; c < 4; c++) acc[a][b][c] = 0.0f;

    int a_row = lane & 15, a_kc = (lane >> 4) << 3;
    int b_row = (lane & 7) + (((lane >> 4) & 1) << 3);
    int b_kc  = (((lane >> 3) & 1) << 3);

    for (int kc = 0; kc < 128; kc += 64) {
#pragma unroll
        for (int r = 0; r < 4; r++) {
            int idx = tid + r * 256;
            int row = idx >> 3, ch = idx & 7;
            *(uint4*)&sAh[row * SP + ch * 8] =
                ((const uint4*)(d_x1hi + (size_t)(m0 + row) * 128 + kc))[ch];
            *(uint4*)&sAl[row * SP + ch * 8] =
                ((const uint4*)(d_x1lo + (size_t)(m0 + row) * 128 + kc))[ch];
        }
#pragma unroll
        for (int r = 0; r < 2; r++) {
            int idx = tid + r * 256;
            int row = idx >> 3, ch = idx & 7;
            *(uint4*)&sBh[row * SP + ch * 8] =
                ((const uint4*)(d_wghi + (size_t)row * 128 + kc))[ch];
            *(uint4*)&sBl[row * SP + ch * 8] =
                ((const uint4*)(d_wglo + (size_t)row * 128 + kc))[ch];
        }
        __syncthreads();
#pragma unroll
        for (int ks = 0; ks < 4; ks++) {
            int k0 = ks * 16;
            uint32_t Bh[4], Bl[4];
            ldm_x4(Bh[0], Bh[1], Bh[2], Bh[3],
                   smem_u32(&sBh[(warp_n + b_row) * SP + k0 + b_kc]));
            ldm_x4(Bl[0], Bl[1], Bl[2], Bl[3],
                   smem_u32(&sBl[(warp_n + b_row) * SP + k0 + b_kc]));
#pragma unroll
            for (int mt = 0; mt < 4; mt++) {
                uint32_t Ah[4], Al[4];
                ldm_x4(Ah[0], Ah[1], Ah[2], Ah[3],
                       smem_u32(&sAh[(warp_m + mt * 16 + a_row) * SP + k0 + a_kc]));
                mma_bf16(acc[mt][0], Ah, &Bh[0]);
                mma_bf16(acc[mt][1], Ah, &Bh[2]);
                mma_bf16(acc[mt][0], Ah, &Bl[0]);
                mma_bf16(acc[mt][1], Ah, &Bl[2]);
                ldm_x4(Al[0], Al[1], Al[2], Al[3],
                       smem_u32(&sAl[(warp_m + mt * 16 + a_row) * SP + k0 + a_kc]));
                mma_bf16(acc[mt][0], Al, &Bh[0]);
                mma_bf16(acc[mt][1], Al, &Bh[2]);
            }
        }
        __syncthreads();
    }
#pragma unroll
    for (int mt = 0; mt < 4; mt++) {
        int r0 = m0 + warp_m + mt * 16 + (lane >> 2);
#pragma unroll
        for (int nt = 0; nt < 2; nt++) {
            int c0 = warp_n + nt * 8 + ((lane & 3) << 1);
            d_g[(size_t)r0 * 64 + c0]           = acc[mt][nt][0];
            d_g[(size_t)r0 * 64 + c0 + 1]       = acc[mt][nt][1];
            d_g[(size_t)(r0 + 8) * 64 + c0]     = acc[mt][nt][2];
            d_g[(size_t)(r0 + 8) * 64 + c0 + 1] = acc[mt][nt][3];
        }
    }
}

// ---------------- attention scores ----------------
__global__ void k_sc(const float* __restrict__ asrc, const float* __restrict__ adst) {
    int warp = (blockIdx.x * blockDim.x + threadIdx.x) >> 5;
    int lane = threadIdx.x & 31;
    if (warp >= NN) return;
    float g0 = d_g[(size_t)warp * 64 + lane];
    float g1 = d_g[(size_t)warp * 64 + 32 + lane];
    float vs = g0 * asrc[lane] + g1 * asrc[32 + lane];
    float vd = g0 * adst[lane] + g1 * adst[32 + lane];
#pragma unroll
    for (int o = 16; o; o >>= 1) {
        vs += __shfl_xor_sync(0xffffffffu, vs, o);
        vd += __shfl_xor_sync(0xffffffffu, vd, o);
    }
    if (lane == 0) { d_scs[warp] = vs; d_scd[warp] = vd; }
}

// ---------------- GAT aggregation ----------------
__global__ void k_gat(const float* __restrict__ bg) {
    int warp = (blockIdx.x * blockDim.x + threadIdx.x) >> 5;
    int lane = threadIdx.x & 31;
    if (warp >= NN) return;
    int s0 = d_off[warp], s1 = d_off[warp + 1];
    float scd = d_scd[warp];

    float mx = -1e30f;
    for (int j = s0 + lane; j < s1; j += 32) {
        int s = d_csr[j];
        float e = d_scs[s] + scd;
        e = e > 0.0f ? e : NEG * e;
        mx = fmaxf(mx, e);
    }
#pragma unroll
    for (int o = 16; o; o >>= 1) mx = fmaxf(mx, __shfl_xor_sync(0xffffffffu, mx, o));

    float sum = 0.0f;
    for (int j = s0 + lane; j < s1; j += 32) {
        int s = d_csr[j];
        float e = d_scs[s] + scd;
        e = e > 0.0f ? e : NEG * e;
        sum += __expf(e - mx);
    }
#pragma unroll
    for (int o = 16; o; o >>= 1) sum += __shfl_xor_sync(0xffffffffu, sum, o);
    float inv = __fdividef(1.0f, sum);

    float a0 = 0.0f, a1 = 0.0f;
    for (int j = s0; j < s1; j++) {
        int s = d_csr[j];
        float e = d_scs[s] + scd;
        e = e > 0.0f ? e : NEG * e;
        float w = __expf(e - mx) * inv;
        a0 = fmaf(w, d_g[(size_t)s * 64 + lane], a0);
        a1 = fmaf(w, d_g[(size_t)s * 64 + 32 + lane], a1);
    }
    d_h[(size_t)warp * 64 + lane]      = a0 + bg[lane];
    d_h[(size_t)warp * 64 + 32 + lane] = a1 + bg[32 + lane];
}

// ---------------- common bf16-split 128x128xK=64 mma body ----------------
__device__ __forceinline__ void mma_tile_128x128_k64(
    const __nv_bfloat16* pAh, const __nv_bfloat16* pAl,
    const __nv_bfloat16* pBh, const __nv_bfloat16* pBl,
    int i0, int j0, float acc[4][4][4],
    __nv_bfloat16* sAh, __nv_bfloat16* sAl, __nv_bfloat16* sBh, __nv_bfloat16* sBl,
    int tid, int warp_m, int warp_n, int lane)
{
#pragma unroll
    for (int r = 0; r < 4; r++) {
        int idx = tid + r * 256;
        int row = idx >> 3, ch = idx & 7;
        *(uint4*)&sAh[row * SP + ch * 8] = ((const uint4*)(pAh + (size_t)(i0 + row) * 64))[ch];
        *(uint4*)&sAl[row * SP + ch * 8] = ((const uint4*)(pAl + (size_t)(i0 + row) * 64))[ch];
        *(uint4*)&sBh[row * SP + ch * 8] = ((const uint4*)(pBh + (size_t)(j0 + row) * 64))[ch];
        *(uint4*)&sBl[row * SP + ch * 8] = ((const uint4*)(pBl + (size_t)(j0 + row) * 64))[ch];
    }
    __syncthreads();

    int a_row = lane & 15, a_kc = (lane >> 4) << 3;
    int b_row = (lane & 7) + (((lane >> 4) & 1) << 3);
    int b_kc  = (((lane >> 3) & 1) << 3);

#pragma unroll
    for (int ks = 0; ks < 4; ks++) {
        int k0 = ks * 16;
        uint32_t Bh[2][4], Bl[2][4];
#pragma unroll
        for (int nb = 0; nb < 2; nb++) {
            ldm_x4(Bh[nb][0], Bh[nb][1], Bh[nb][2], Bh[nb][3],
                   smem_u32(&sBh[(warp_n + nb * 16 + b_row) * SP + k0 + b_kc]));
            ldm_x4(Bl[nb][0], Bl[nb][1], Bl[nb][2], Bl[nb][3],
                   smem_u32(&sBl[(warp_n + nb * 16 + b_row) * SP + k0 + b_kc]));
        }
#pragma unroll
        for (int mt = 0; mt < 4; mt++) {
            uint32_t Ah[4], Al[4];
            ldm_x4(Ah[0], Ah[1], Ah[2], Ah[3],
                   smem_u32(&sAh[(warp_m + mt * 16 + a_row) * SP + k0 + a_kc]));
#pragma unroll
            for (int nt = 0; nt < 4; nt++)
                mma_bf16(acc[mt][nt], Ah, &Bh[nt >> 1][(nt & 1) * 2]);
#pragma unroll
            for (int nt = 0; nt < 4; nt++)
                mma_bf16(acc[mt][nt], Ah, &Bl[nt >> 1][(nt & 1) * 2]);
            ldm_x4(Al[0], Al[1], Al[2], Al[3],
                   smem_u32(&sAl[(warp_m + mt * 16 + a_row) * SP + k0 + a_kc]));
#pragma unroll
            for (int nt = 0; nt < 4; nt++)
                mma_bf16(acc[mt][nt], Al, &Bh[nt >> 1][(nt & 1) * 2]);
        }
    }
    __syncthreads();   // operand smem dead after this
}

// ---------------- s_ = sigmoid(h h^T): SYMMETRIC 128x128 bf16-split mma ----------------
// grid (96, 96), compute only jt >= it.
// Cs pitch 129 (129 mod 32 == 1): bank = (r + c) mod 32 -> conflict-free for BOTH
// the row-major pass and the transposed mirror pass. 128*129*4 = 66048 B.
#define CP3 129
__global__ __launch_bounds__(256) void k_s_sym(float* __restrict__ out) {
    int it = blockIdx.y, jt = blockIdx.x;
    if (jt < it) return;
    extern __shared__ __nv_bfloat16 sm[];
    __nv_bfloat16* sAh = sm;
    __nv_bfloat16* sAl = sm + 9216;
    __nv_bfloat16* sBh = sm + 18432;
    __nv_bfloat16* sBl = sm + 27648;
    float* Cs = (float*)sm;             // [128][129] after compute

    int i0 = it * 128, j0 = jt * 128;
    int tid = threadIdx.x;
    int wid = tid >> 5, lane = tid & 31;
    int warp_m = (wid & 1) * 64;
    int warp_n = (wid >> 1) * 32;

    float acc[4][4][4];
#pragma unroll
    for (int i = 0; i < 4; i++)
#pragma unroll
        for (int j = 0; j < 4; j++)
#pragma unroll
            for (int c = 0; c < 4; c++) acc[i][j][c] = 0.0f;

    mma_tile_128x128_k64(d_hhi, d_hlo, d_hhi, d_hlo, i0, j0, acc,
                         sAh, sAl, sBh, sBl, tid, warp_m, warp_n, lane);

    // stage sigmoid into Cs
#pragma unroll
    for (int mt = 0; mt < 4; mt++) {
        int r0 = warp_m + mt * 16 + (lane >> 2);
#pragma unroll
        for (int nt = 0; nt < 4; nt++) {
            int c0 = warp_n + nt * 8 + ((lane & 3) << 1);
            Cs[r0 * CP3 + c0]           = sigf(acc[mt][nt][0]);
            Cs[r0 * CP3 + c0 + 1]       = sigf(acc[mt][nt][1]);
            Cs[(r0 + 8) * CP3 + c0]     = sigf(acc[mt][nt][2]);
            Cs[(r0 + 8) * CP3 + c0 + 1] = sigf(acc[mt][nt][3]);
        }
    }
    __syncthreads();

    // direct pass: conflict-free LDS, coalesced STG
#pragma unroll 4
    for (int itr = 0; itr < 64; itr++) {
        int slot = tid + itr * 256;
        int row = slot >> 7, col = slot & 127;
        out[(size_t)(i0 + row) * NN + j0 + col] = Cs[row * CP3 + col];
    }
    // mirror pass (transposed): conflict-free (stride 129 == 1 mod 32), coalesced STG
    if (jt > it) {
#pragma unroll 4
        for (int itr = 0; itr < 64; itr++) {
            int slot = tid + itr * 256;
            int c = slot >> 7, r = slot & 127;
            out[(size_t)(j0 + c) * NN + i0 + r] = Cs[r * CP3 + c];
        }
    }
}

// ---------------- x_ = h @ xa^T via bf16-split mma ----------------
__global__ __launch_bounds__(256) void k_xout_tc(float* __restrict__ out) {
    extern __shared__ __nv_bfloat16 sm[];
    __nv_bfloat16* sAh = sm;
    __nv_bfloat16* sAl = sm + 9216;
    __nv_bfloat16* sBh = sm + 18432;
    __nv_bfloat16* sBl = sm + 27648;
    float* Cs = (float*)sm;

    int i0 = blockIdx.y * 128, j0 = blockIdx.x * 128;
    int tid = threadIdx.x;
    int wid = tid >> 5, lane = tid & 31;
    int warp_m = (wid & 1) * 64;
    int warp_n = (wid >> 1) * 32;

    float acc[4][4][4];
#pragma unroll
    for (int i = 0; i < 4; i++)
#pragma unroll
        for (int j = 0; j < 4; j++)
#pragma unroll
            for (int c = 0; c < 4; c++) acc[i][j][c] = 0.0f;

    mma_tile_128x128_k64(d_hhi, d_hlo, d_xahi, d_xalo, i0, j0, acc,
                         sAh, sAl, sBh, sBl, tid, warp_m, warp_n, lane);

#pragma unroll
    for (int mt = 0; mt < 4; mt++) {
        int r0 = warp_m + mt * 16 + (lane >> 2);
#pragma unroll
        for (int nt = 0; nt < 4; nt++) {
            int c0 = warp_n + nt * 8 + ((lane & 3) << 1);
            Cs[r0 * CP3 + c0]           = acc[mt][nt][0];
            Cs[r0 * CP3 + c0 + 1]       = acc[mt][nt][1];
            Cs[(r0 + 8) * CP3 + c0]     = acc[mt][nt][2];
            Cs[(r0 + 8) * CP3 + c0 + 1] = acc[mt][nt][3];
        }
    }
    __syncthreads();
#pragma unroll 4
    for (int itr = 0; itr < 64; itr++) {
        int slot = tid + itr * 256;
        int row = slot >> 7, col = slot & 127;
        out[(size_t)(i0 + row) * 512 + j0 + col] = Cs[row * CP3 + col];
    }
}

// ---------------- xtraw = x^T @ W_a1^T via bf16-split mma (split-K, atomic accum) ----------------
__global__ __launch_bounds__(256) void k_att1_tc() {
    extern __shared__ __nv_bfloat16 sm[];
    __nv_bfloat16* sAh = sm;
    __nv_bfloat16* sAl = sm + 9216;
    __nv_bfloat16* sBh = sm + 18432;
    __nv_bfloat16* sBl = sm + 27648;

    int m0 = blockIdx.x * 128;
    int kbase = blockIdx.y * 512;
    int tid = threadIdx.x;
    int wid = tid >> 5, lane = tid & 31;
    int warp_m = (wid & 1) * 64;
    int warp_n = (wid >> 1) * 32;

    float acc[4][4][4];
#pragma unroll
    for (int i = 0; i < 4; i++)
#pragma unroll
        for (int j = 0; j < 4; j++)
#pragma unroll
            for (int c = 0; c < 4; c++) acc[i][j][c] = 0.0f;

    int a_row = lane & 15, a_kc = (lane >> 4) << 3;
    int b_row = (lane & 7) + (((lane >> 4) & 1) << 3);
    int b_kc  = (((lane >> 3) & 1) << 3);

    for (int kc = 0; kc < 512; kc += 64) {
        int kk = kbase + kc;
#pragma unroll
        for (int r = 0; r < 4; r++) {
            int idx = tid + r * 256;
            int row = idx >> 3, ch = idx & 7;
            *(uint4*)&sAh[row * SP + ch * 8] =
                ((const uint4*)(d_xThi + (size_t)(m0 + row) * NN + kk))[ch];
            *(uint4*)&sAl[row * SP + ch * 8] =
                ((const uint4*)(d_xTlo + (size_t)(m0 + row) * NN + kk))[ch];
            *(uint4*)&sBh[row * SP + ch * 8] =
                ((const uint4*)(d_wa1hi + (size_t)row * NN + kk))[ch];
            *(uint4*)&sBl[row * SP + ch * 8] =
                ((const uint4*)(d_wa1lo + (size_t)row * NN + kk))[ch];
        }
        __syncthreads();
#pragma unroll
        for (int ks = 0; ks < 4; ks++) {
            int k0 = ks * 16;
            uint32_t Bh[2][4], Bl[2][4];
#pragma unroll
            for (int nb = 0; nb < 2; nb++) {
                ldm_x4(Bh[nb][0], Bh[nb][1], Bh[nb][2], Bh[nb][3],
                       smem_u32(&sBh[(warp_n + nb * 16 + b_row) * SP + k0 + b_kc]));
                ldm_x4(Bl[nb][0], Bl[nb][1], Bl[nb][2], Bl[nb][3],
                       smem_u32(&sBl[(warp_n + nb * 16 + b_row) * SP + k0 + b_kc]));
            }
#pragma unroll
            for (int mt = 0; mt < 4; mt++) {
                uint32_t Ah[4], Al[4];
                ldm_x4(Ah[0], Ah[1], Ah[2], Ah[3],
                       smem_u32(&sAh[(warp_m + mt * 16 + a_row) * SP + k0 + a_kc]));
#pragma unroll
                for (int nt = 0; nt < 4; nt++)
                    mma_bf16(acc[mt][nt], Ah, &Bh[nt >> 1][(nt & 1) * 2]);
#pragma unroll
                for (int nt = 0; nt < 4; nt++)
                    mma_bf16(acc[mt][nt], Ah, &Bl[nt >> 1][(nt & 1) * 2]);
                ldm_x4(Al[0], Al[1], Al[2], Al[3],
                       smem_u32(&sAl[(warp_m + mt * 16 + a_row) * SP + k0 + a_kc]));
#pragma unroll
                for (int nt = 0; nt < 4; nt++)
                    mma_bf16(acc[mt][nt], Al, &Bh[nt >> 1][(nt & 1) * 2]);
            }
        }
        __syncthreads();
    }
#pragma unroll
    for (int mt = 0; mt < 4; mt++) {
        int r0 = m0 + warp_m + mt * 16 + (lane >> 2);
#pragma unroll
        for (int nt = 0; nt < 4; nt++) {
            int c = warp_n + nt * 8 + ((lane & 3) << 1);
            atomicAdd(&d_xtraw[(size_t)r0 * 128 + c],           acc[mt][nt][0]);
            atomicAdd(&d_xtraw[(size_t)r0 * 128 + c + 1],       acc[mt][nt][1]);
            atomicAdd(&d_xtraw[(size_t)(r0 + 8) * 128 + c],     acc[mt][nt][2]);
            atomicAdd(&d_xtraw[(size_t)(r0 + 8) * 128 + c + 1], acc[mt][nt][3]);
        }
    }
}

__global__ void k_xa(const float* __restrict__ ba1, const float* __restrict__ W2,
                     const float* __restrict__ ba2) {
    int t = blockIdx.x * blockDim.x + threadIdx.x;
    if (t >= DIN * DOUT) return;
    int d = t >> 6, o = t & 63;
    float s = 0.0f;
#pragma unroll 4
    for (int e = 0; e < 128; e++) {
        float v = d_xtraw[(size_t)d * 128 + e] + ba1[e];
        v = v > 0.0f ? v : 0.0f;
        s = fmaf(v, W2[(size_t)o * 128 + e], s);
    }
    d_xa[t] = s + ba2[o];
}

// ---------------- launch ----------------
extern "C" void kernel_launch(void* const* d_in, const int* in_sizes, int n_in,
                              void* d_out, int out_size) {
    const float* x     = (const float*)d_in[0];
    const float* Ws1   = (const float*)d_in[1];
    const float* bs1   = (const float*)d_in[2];
    const float* Wg    = (const float*)d_in[3];
    const float* asrc  = (const float*)d_in[4];
    const float* adst  = (const float*)d_in[5];
    const float* bg    = (const float*)d_in[6];
    const float* Wa1   = (const float*)d_in[7];
    const float* ba1   = (const float*)d_in[8];
    const float* Wa2   = (const float*)d_in[9];
    const float* ba2   = (const float*)d_in[10];
    const void*  ei    = d_in[11];

    float* out   = (float*)d_out;
    float* out_x = out;                          // [12288, 512]
    float* out_s = out + (size_t)NN * DIN;       // [12288, 12288]

    const int SMEM_BIG = 73728;
    const int SMEM_G   = 55296;
    static int smem_set = 0;
    if (!smem_set) {
        cudaFuncSetAttribute(k_fc1_tc,  cudaFuncAttributeMaxDynamicSharedMemorySize, SMEM_BIG);
        cudaFuncSetAttribute(k_s_sym,   cudaFuncAttributeMaxDynamicSharedMemorySize, SMEM_BIG);
        cudaFuncSetAttribute(k_att1_tc, cudaFuncAttributeMaxDynamicSharedMemorySize, SMEM_BIG);
        cudaFuncSetAttribute(k_xout_tc, cudaFuncAttributeMaxDynamicSharedMemorySize, SMEM_BIG);
        cudaFuncSetAttribute(k_g_tc,    cudaFuncAttributeMaxDynamicSharedMemorySize, SMEM_G);
        smem_set = 1;
    }

    // CSR build + input splits
    k_detect<<<1, 256>>>((const int*)ei);
    k_init<<<256, 256>>>();
    k_count<<<NE / 256, 256>>>(ei);
    k_splitx<<<NN * DIN / 2048, 256>>>(x);
    k_splitw1<<<DEMB * DIN / 2048, 256>>>(Ws1);
    k_splitwa1<<<DEMB * NN / 2048, 256>>>(Wa1);
    k_splitwg<<<DOUT * DEMB / 2048, 256>>>(Wg);
    k_tsplit<<<dim3(NN / 64, DIN / 64), 256>>>(x);
    k_scan<<<1, 1024>>>();
    k_scatter<<<TOTE / 256, 256>>>(ei);

    // encoder + GAT
    k_fc1_tc<<<NN / 128, 256, SMEM_BIG>>>(bs1);
    k_g_tc<<<NN / 128, 256, SMEM_G>>>();
    k_sc<<<NN / 8, 256>>>(asrc, adst);
    k_gat<<<NN / 8, 256>>>(bg);

    // structure decoder (tensor cores, symmetric)
    k_split<<<NN * DOUT / 2048, 256>>>();
    k_s_sym<<<dim3(NN / 128, NN / 128), 256, SMEM_BIG>>>(out_s);

    // attribute decoder (tensor cores)
    k_att1_tc<<<dim3(DIN / 128, 24), 256, SMEM_BIG>>>();
    k_xa<<<(DIN * DOUT) / 256, 256>>>(ba1, Wa2, ba2);
    k_splitxa<<<DIN * DOUT / 2048, 256>>>();
    k_xout_tc<<<dim3(DIN / 128, NN / 128), 256, SMEM_BIG>>>(out_x);
}

// round 14
// speedup vs baseline: 2.5696x; 1.0349x over previous
#include <cuda_runtime.h>
#include <cuda_bf16.h>
#include <cstdint>

#define NN   12288
#define DIN  512
#define DEMB 128
#define DOUT 64
#define NE   393216
#define TOTE (NE + NN)     // 405504
#define NEG  0.2f

// ---------------- scratch (device globals; no allocation) ----------------
__device__ __nv_bfloat16 d_x1hi[NN * DEMB];
__device__ __nv_bfloat16 d_x1lo[NN * DEMB];
__device__ float d_g[NN * DOUT];
__device__ float d_scs[NN];
__device__ float d_scd[NN];
__device__ float d_h[NN * DOUT];
__device__ __nv_bfloat16 d_hhi[NN * DOUT];
__device__ __nv_bfloat16 d_hlo[NN * DOUT];
__device__ __nv_bfloat16 d_xhi[NN * DIN];
__device__ __nv_bfloat16 d_xlo[NN * DIN];
__device__ __nv_bfloat16 d_xThi[DIN * NN];   // x^T, bf16 hi
__device__ __nv_bfloat16 d_xTlo[DIN * NN];
__device__ __nv_bfloat16 d_w1hi[DEMB * DIN];
__device__ __nv_bfloat16 d_w1lo[DEMB * DIN];
__device__ __nv_bfloat16 d_wa1hi[DEMB * NN];
__device__ __nv_bfloat16 d_wa1lo[DEMB * NN];
__device__ __nv_bfloat16 d_wghi[DOUT * DEMB];
__device__ __nv_bfloat16 d_wglo[DOUT * DEMB];
__device__ __nv_bfloat16 d_xahi[DIN * DOUT];
__device__ __nv_bfloat16 d_xalo[DIN * DOUT];
__device__ float d_xtraw[DIN * DEMB];
__device__ float d_xa[DIN * DOUT];
__device__ int   d_deg[NN];
__device__ int   d_off[NN + 1];
__device__ int   d_fill[NN];
__device__ int   d_csr[TOTE];
__device__ int   d_is64;

// ---------------- helpers ----------------
__device__ __forceinline__ float sigf(float v) {
    return __fdividef(1.0f, 1.0f + __expf(-v));
}
__device__ __forceinline__ int clampn(int v) {
    v = v < 0 ? 0 : v;
    return v >= NN ? NN - 1 : v;
}
__device__ __forceinline__ uint32_t smem_u32(const void* p) {
    return (uint32_t)__cvta_generic_to_shared(p);
}
__device__ __forceinline__ void ldm_x4(uint32_t& r0, uint32_t& r1, uint32_t& r2,
                                       uint32_t& r3, uint32_t addr) {
    asm volatile("ldmatrix.sync.aligned.m8n8.x4.shared.b16 {%0,%1,%2,%3}, [%4];"
                 : "=r"(r0), "=r"(r1), "=r"(r2), "=r"(r3) : "r"(addr));
}
__device__ __forceinline__ void mma_bf16(float* c, const uint32_t* a, const uint32_t* b) {
    asm volatile(
        "mma.sync.aligned.m16n8k16.row.col.f32.bf16.bf16.f32 "
        "{%0,%1,%2,%3}, {%4,%5,%6,%7}, {%8,%9}, {%0,%1,%2,%3};"
        : "+f"(c[0]), "+f"(c[1]), "+f"(c[2]), "+f"(c[3])
        : "r"(a[0]), "r"(a[1]), "r"(a[2]), "r"(a[3]), "r"(b[0]), "r"(b[1]));
}

// ---------------- dtype probe ----------------
__global__ void k_detect(const int* __restrict__ ei32) {
    __shared__ int any;
    if (threadIdx.x == 0) any = 0;
    __syncthreads();
    if (ei32[threadIdx.x * 2 + 1] != 0) any = 1;
    __syncthreads();
    if (threadIdx.x == 0) d_is64 = (any == 0) ? 1 : 0;
}

__global__ void k_init() {
    int t = blockIdx.x * blockDim.x + threadIdx.x;
    if (t < DIN * DEMB) d_xtraw[t] = 0.0f;
    if (t < NN) d_deg[t] = 1;
}

__global__ void k_count(const void* __restrict__ ei) {
    int e = blockIdx.x * blockDim.x + threadIdx.x;
    if (e < NE) {
        int dst;
        if (d_is64) dst = (int)((const long long*)ei)[NE + e];
        else        dst = ((const int*)ei)[NE + e];
        atomicAdd(&d_deg[clampn(dst)], 1);
    }
}

// warp-shuffle scan (12 values/thread via 3x int4, 1024 threads)
__global__ void k_scan() {
    __shared__ int wsum[32];
    int t = threadIdx.x, lane = t & 31, w = t >> 5;
    int base = t * 12;
    int loc[12];
#pragma unroll
    for (int q = 0; q < 3; q++) {
        int4 v = *(const int4*)&d_deg[base + q * 4];
        loc[q * 4 + 0] = v.x; loc[q * 4 + 1] = v.y;
        loc[q * 4 + 2] = v.z; loc[q * 4 + 3] = v.w;
    }
    int s = 0;
#pragma unroll
    for (int i = 0; i < 12; i++) s += loc[i];
    int pre = s;
#pragma unroll
    for (int o = 1; o < 32; o <<= 1) {
        int v = __shfl_up_sync(0xffffffffu, pre, o);
        if (lane >= o) pre += v;
    }
    if (lane == 31) wsum[w] = pre;
    __syncthreads();
    if (w == 0) {
        int v = wsum[lane];
#pragma unroll
        for (int o = 1; o < 32; o <<= 1) {
            int u = __shfl_up_sync(0xffffffffu, v, o);
            if (lane >= o) v += u;
        }
        wsum[lane] = v;
    }
    __syncthreads();
    int run = pre - s + (w ? wsum[w - 1] : 0);
#pragma unroll
    for (int i = 0; i < 12; i++) {
        d_off[base + i]  = run;
        d_fill[base + i] = run;
        run += loc[i];
    }
    if (t == 1023) d_off[NN] = run;
}

__global__ void k_scatter(const void* __restrict__ ei) {
    int e = blockIdx.x * blockDim.x + threadIdx.x;
    if (e < NE) {
        int src, dst;
        if (d_is64) {
            src = (int)((const long long*)ei)[e];
            dst = (int)((const long long*)ei)[NE + e];
        } else {
            src = ((const int*)ei)[e];
            dst = ((const int*)ei)[NE + e];
        }
        int p = atomicAdd(&d_fill[clampn(dst)], 1);
        if (p < TOTE) d_csr[p] = clampn(src);
    } else if (e < TOTE) {
        int n = e - NE;
        int p = atomicAdd(&d_fill[n], 1);
        if (p < TOTE) d_csr[p] = n;
    }
}

// ---------------- split kernels (vectorized: 8 elems/thread) ----------------
__device__ __forceinline__ void split8(const float* __restrict__ src,
                                       __nv_bfloat16* __restrict__ hi,
                                       __nv_bfloat16* __restrict__ lo, size_t base) {
    float4 v0 = *(const float4*)&src[base];
    float4 v1 = *(const float4*)&src[base + 4];
    float f[8] = {v0.x, v0.y, v0.z, v0.w, v1.x, v1.y, v1.z, v1.w};
    __nv_bfloat16 h[8], l[8];
#pragma unroll
    for (int i = 0; i < 8; i++) {
        h[i] = __float2bfloat16(f[i]);
        l[i] = __float2bfloat16(f[i] - __bfloat162float(h[i]));
    }
    *(uint4*)&hi[base] = *(uint4*)h;
    *(uint4*)&lo[base] = *(uint4*)l;
}
__global__ void k_splitw1(const float* __restrict__ W) {
    size_t base = (size_t)(blockIdx.x * blockDim.x + threadIdx.x) * 8;
    split8(W, d_w1hi, d_w1lo, base);
}
__global__ void k_splitwa1(const float* __restrict__ W) {
    size_t base = (size_t)(blockIdx.x * blockDim.x + threadIdx.x) * 8;
    split8(W, d_wa1hi, d_wa1lo, base);
}
__global__ void k_splitwg(const float* __restrict__ W) {
    size_t base = (size_t)(blockIdx.x * blockDim.x + threadIdx.x) * 8;
    split8(W, d_wghi, d_wglo, base);
}
__global__ void k_split() {
    size_t base = (size_t)(blockIdx.x * blockDim.x + threadIdx.x) * 8;
    split8(d_h, d_hhi, d_hlo, base);
}
__global__ void k_splitxa() {
    size_t base = (size_t)(blockIdx.x * blockDim.x + threadIdx.x) * 8;
    split8(d_xa, d_xahi, d_xalo, base);
}

// ---------------- transpose+split x: fills BOTH row-major (d_xhi/lo) AND x^T (d_xThi/lo) ----------------
__global__ __launch_bounds__(256) void k_tsplit(const float* __restrict__ x) {
    __shared__ __nv_bfloat16 shhi[64 * 68];
    __shared__ __nv_bfloat16 shlo[64 * 68];
    int k0 = blockIdx.x * 64, d0 = blockIdx.y * 64;
    int tid = threadIdx.x;
#pragma unroll
    for (int i = 0; i < 4; i++) {
        int slot = tid + i * 256;
        int kk = slot >> 4, q = slot & 15;
        float4 v = *(const float4*)&x[(size_t)(k0 + kk) * 512 + d0 + q * 4];
        __nv_bfloat16 h[4], l[4];
        float f[4] = {v.x, v.y, v.z, v.w};
#pragma unroll
        for (int u = 0; u < 4; u++) {
            h[u] = __float2bfloat16(f[u]);
            l[u] = __float2bfloat16(f[u] - __bfloat162float(h[u]));
        }
        // row-major outputs (replaces k_splitx)
        *(uint2*)&d_xhi[(size_t)(k0 + kk) * 512 + d0 + q * 4] = *(uint2*)h;
        *(uint2*)&d_xlo[(size_t)(k0 + kk) * 512 + d0 + q * 4] = *(uint2*)l;
        // transpose staging
        *(uint2*)&shhi[kk * 68 + q * 4] = *(uint2*)h;
        *(uint2*)&shlo[kk * 68 + q * 4] = *(uint2*)l;
    }
    __syncthreads();
#pragma unroll
    for (int i = 0; i < 4; i++) {
        int slot = tid + i * 256;
        int arr = slot >> 9;
        int s2 = slot & 511;
        int dd = s2 >> 3, qc = s2 & 7;
        const __nv_bfloat16* sh = arr ? shlo : shhi;
        __nv_bfloat16 vals[8];
#pragma unroll
        for (int u = 0; u < 8; u++) vals[u] = sh[(qc * 8 + u) * 68 + dd];
        __nv_bfloat16* dst = arr ? d_xTlo : d_xThi;
        *(uint4*)&dst[(size_t)(d0 + dd) * NN + k0 + qc * 8] = *(uint4*)vals;
    }
}

#define SP 72    // operand smem pitch (halves)

// ---------------- x1 = relu(x @ W_s1^T + b) via bf16-split mma (outputs bf16 hi/lo) ----------------
__global__ __launch_bounds__(256) void k_fc1_tc(const float* __restrict__ b) {
    extern __shared__ __nv_bfloat16 sm[];
    __nv_bfloat16* sAh = sm;
    __nv_bfloat16* sAl = sm + 9216;
    __nv_bfloat16* sBh = sm + 18432;
    __nv_bfloat16* sBl = sm + 27648;

    int m0 = blockIdx.x * 128;
    int tid = threadIdx.x;
    int wid = tid >> 5, lane = tid & 31;
    int warp_m = (wid & 1) * 64;
    int warp_n = (wid >> 1) * 32;

    float acc[4][4][4];
#pragma unroll
    for (int i = 0; i < 4; i++)
#pragma unroll
        for (int j = 0; j < 4; j++)
#pragma unroll
            for (int c = 0; c < 4; c++) acc[i][j][c] = 0.0f;

    int a_row = lane & 15, a_kc = (lane >> 4) << 3;
    int b_row = (lane & 7) + (((lane >> 4) & 1) << 3);
    int b_kc  = (((lane >> 3) & 1) << 3);

    for (int kc = 0; kc < 512; kc += 64) {
#pragma unroll
        for (int r = 0; r < 4; r++) {
            int idx = tid + r * 256;
            int row = idx >> 3, ch = idx & 7;
            *(uint4*)&sAh[row * SP + ch * 8] =
                ((const uint4*)(d_xhi + (size_t)(m0 + row) * 512 + kc))[ch];
            *(uint4*)&sAl[row * SP + ch * 8] =
                ((const uint4*)(d_xlo + (size_t)(m0 + row) * 512 + kc))[ch];
            *(uint4*)&sBh[row * SP + ch * 8] =
                ((const uint4*)(d_w1hi + (size_t)row * 512 + kc))[ch];
            *(uint4*)&sBl[row * SP + ch * 8] =
                ((const uint4*)(d_w1lo + (size_t)row * 512 + kc))[ch];
        }
        __syncthreads();
#pragma unroll
        for (int ks = 0; ks < 4; ks++) {
            int k0 = ks * 16;
            uint32_t Bh[2][4], Bl[2][4];
#pragma unroll
            for (int nb = 0; nb < 2; nb++) {
                ldm_x4(Bh[nb][0], Bh[nb][1], Bh[nb][2], Bh[nb][3],
                       smem_u32(&sBh[(warp_n + nb * 16 + b_row) * SP + k0 + b_kc]));
                ldm_x4(Bl[nb][0], Bl[nb][1], Bl[nb][2], Bl[nb][3],
                       smem_u32(&sBl[(warp_n + nb * 16 + b_row) * SP + k0 + b_kc]));
            }
#pragma unroll
            for (int mt = 0; mt < 4; mt++) {
                uint32_t Ah[4], Al[4];
                ldm_x4(Ah[0], Ah[1], Ah[2], Ah[3],
                       smem_u32(&sAh[(warp_m + mt * 16 + a_row) * SP + k0 + a_kc]));
#pragma unroll
                for (int nt = 0; nt < 4; nt++)
                    mma_bf16(acc[mt][nt], Ah, &Bh[nt >> 1][(nt & 1) * 2]);
#pragma unroll
                for (int nt = 0; nt < 4; nt++)
                    mma_bf16(acc[mt][nt], Ah, &Bl[nt >> 1][(nt & 1) * 2]);
                ldm_x4(Al[0], Al[1], Al[2], Al[3],
                       smem_u32(&sAl[(warp_m + mt * 16 + a_row) * SP + k0 + a_kc]));
#pragma unroll
                for (int nt = 0; nt < 4; nt++)
                    mma_bf16(acc[mt][nt], Al, &Bh[nt >> 1][(nt & 1) * 2]);
            }
        }
        __syncthreads();
    }
#pragma unroll
    for (int mt = 0; mt < 4; mt++) {
        int r0 = m0 + warp_m + mt * 16 + (lane >> 2);
#pragma unroll
        for (int nt = 0; nt < 4; nt++) {
            int c = warp_n + nt * 8 + ((lane & 3) << 1);
            float b0 = b[c], b1 = b[c + 1];
            float v00 = fmaxf(acc[mt][nt][0] + b0, 0.0f);
            float v01 = fmaxf(acc[mt][nt][1] + b1, 0.0f);
            float v10 = fmaxf(acc[mt][nt][2] + b0, 0.0f);
            float v11 = fmaxf(acc[mt][nt][3] + b1, 0.0f);
            __nv_bfloat16 h00 = __float2bfloat16(v00), h01 = __float2bfloat16(v01);
            __nv_bfloat16 h10 = __float2bfloat16(v10), h11 = __float2bfloat16(v11);
            __nv_bfloat162 p;
            p.x = h00; p.y = h01;
            *(__nv_bfloat162*)&d_x1hi[(size_t)r0 * 128 + c] = p;
            p.x = __float2bfloat16(v00 - __bfloat162float(h00));
            p.y = __float2bfloat16(v01 - __bfloat162float(h01));
            *(__nv_bfloat162*)&d_x1lo[(size_t)r0 * 128 + c] = p;
            p.x = h10; p.y = h11;
            *(__nv_bfloat162*)&d_x1hi[(size_t)(r0 + 8) * 128 + c] = p;
            p.x = __float2bfloat16(v10 - __bfloat162float(h10));
            p.y = __float2bfloat16(v11 - __bfloat162float(h11));
            *(__nv_bfloat162*)&d_x1lo[(size_t)(r0 + 8) * 128 + c] = p;
        }
    }
}

// ---------------- g = x1 @ W_g^T via bf16-split mma (128x64 tile) ----------------
__global__ __launch_bounds__(256) void k_g_tc() {
    extern __shared__ __nv_bfloat16 sm[];
    __nv_bfloat16* sAh = sm;
    __nv_bfloat16* sAl = sm + 9216;
    __nv_bfloat16* sBh = sm + 18432;
    __nv_bfloat16* sBl = sm + 23040;

    int m0 = blockIdx.x * 128;
    int tid = threadIdx.x;
    int wid = tid >> 5, lane = tid & 31;
    int warp_m = (wid >> 2) * 64;
    int warp_n = (wid & 3) * 16;

    float acc[4][2][4];
#pragma unroll
    for (int a = 0; a < 4; a++)
#pragma unroll
        for (int b = 0; b < 2; b++)
#pragma unroll
            for (int c = 0; c < 4; c++) acc[a][b][c] = 0.0f;

    int a_row = lane & 15, a_kc = (lane >> 4) << 3;
    int b_row = (lane & 7) + (((lane >> 4) & 1) << 3);
    int b_kc  = (((lane >> 3) & 1) << 3);

    for (int kc = 0; kc < 128; kc += 64) {
#pragma unroll
        for (int r = 0; r < 4; r++) {
            int idx = tid + r * 256;
            int row = idx >> 3, ch = idx & 7;
            *(uint4*)&sAh[row * SP + ch * 8] =
                ((const uint4*)(d_x1hi + (size_t)(m0 + row) * 128 + kc))[ch];
            *(uint4*)&sAl[row * SP + ch * 8] =
                ((const uint4*)(d_x1lo + (size_t)(m0 + row) * 128 + kc))[ch];
        }
#pragma unroll
        for (int r = 0; r < 2; r++) {
            int idx = tid + r * 256;
            int row = idx >> 3, ch = idx & 7;
            *(uint4*)&sBh[row * SP + ch * 8] =
                ((const uint4*)(d_wghi + (size_t)row * 128 + kc))[ch];
            *(uint4*)&sBl[row * SP + ch * 8] =
                ((const uint4*)(d_wglo + (size_t)row * 128 + kc))[ch];
        }
        __syncthreads();
#pragma unroll
        for (int ks = 0; ks < 4; ks++) {
            int k0 = ks * 16;
            uint32_t Bh[4], Bl[4];
            ldm_x4(Bh[0], Bh[1], Bh[2], Bh[3],
                   smem_u32(&sBh[(warp_n + b_row) * SP + k0 + b_kc]));
            ldm_x4(Bl[0], Bl[1], Bl[2], Bl[3],
                   smem_u32(&sBl[(warp_n + b_row) * SP + k0 + b_kc]));
#pragma unroll
            for (int mt = 0; mt < 4; mt++) {
                uint32_t Ah[4], Al[4];
                ldm_x4(Ah[0], Ah[1], Ah[2], Ah[3],
                       smem_u32(&sAh[(warp_m + mt * 16 + a_row) * SP + k0 + a_kc]));
                mma_bf16(acc[mt][0], Ah, &Bh[0]);
                mma_bf16(acc[mt][1], Ah, &Bh[2]);
                mma_bf16(acc[mt][0], Ah, &Bl[0]);
                mma_bf16(acc[mt][1], Ah, &Bl[2]);
                ldm_x4(Al[0], Al[1], Al[2], Al[3],
                       smem_u32(&sAl[(warp_m + mt * 16 + a_row) * SP + k0 + a_kc]));
                mma_bf16(acc[mt][0], Al, &Bh[0]);
                mma_bf16(acc[mt][1], Al, &Bh[2]);
            }
        }
        __syncthreads();
    }
#pragma unroll
    for (int mt = 0; mt < 4; mt++) {
        int r0 = m0 + warp_m + mt * 16 + (lane >> 2);
#pragma unroll
        for (int nt = 0; nt < 2; nt++) {
            int c0 = warp_n + nt * 8 + ((lane & 3) << 1);
            d_g[(size_t)r0 * 64 + c0]           = acc[mt][nt][0];
            d_g[(size_t)r0 * 64 + c0 + 1]       = acc[mt][nt][1];
            d_g[(size_t)(r0 + 8) * 64 + c0]     = acc[mt][nt][2];
            d_g[(size_t)(r0 + 8) * 64 + c0 + 1] = acc[mt][nt][3];
        }
    }
}

// ---------------- attention scores ----------------
__global__ void k_sc(const float* __restrict__ asrc, const float* __restrict__ adst) {
    int warp = (blockIdx.x * blockDim.x + threadIdx.x) >> 5;
    int lane = threadIdx.x & 31;
    if (warp >= NN) return;
    float g0 = d_g[(size_t)warp * 64 + lane];
    float g1 = d_g[(size_t)warp * 64 + 32 + lane];
    float vs = g0 * asrc[lane] + g1 * asrc[32 + lane];
    float vd = g0 * adst[lane] + g1 * adst[32 + lane];
#pragma unroll
    for (int o = 16; o; o >>= 1) {
        vs += __shfl_xor_sync(0xffffffffu, vs, o);
        vd += __shfl_xor_sync(0xffffffffu, vd, o);
    }
    if (lane == 0) { d_scs[warp] = vs; d_scd[warp] = vd; }
}

// ---------------- GAT aggregation: merged sum+accumulate, chunked parallel exp ----------------
__global__ void k_gat(const float* __restrict__ bg) {
    int warp = (blockIdx.x * blockDim.x + threadIdx.x) >> 5;
    int lane = threadIdx.x & 31;
    if (warp >= NN) return;
    int s0 = d_off[warp], s1 = d_off[warp + 1];
    float scd = d_scd[warp];

    // pass 1: max
    float mx = -1e30f;
    for (int j = s0 + lane; j < s1; j += 32) {
        int s = d_csr[j];
        float e = d_scs[s] + scd;
        e = e > 0.0f ? e : NEG * e;
        mx = fmaxf(mx, e);
    }
#pragma unroll
    for (int o = 16; o; o >>= 1) mx = fmaxf(mx, __shfl_xor_sync(0xffffffffu, mx, o));

    // pass 2: unnormalized accumulate + sum (exp computed 32-wide, shfl-broadcast)
    float sum = 0.0f, a0 = 0.0f, a1 = 0.0f;
    for (int jb = s0; jb < s1; jb += 32) {
        int j = jb + lane;
        float w = 0.0f;
        int sidx = 0;
        if (j < s1) {
            sidx = d_csr[j];
            float e = d_scs[sidx] + scd;
            e = e > 0.0f ? e : NEG * e;
            w = __expf(e - mx);
        }
        sum += w;
        int cnt = s1 - jb;
        if (cnt > 32) cnt = 32;
        for (int u = 0; u < cnt; u++) {
            float wu = __shfl_sync(0xffffffffu, w, u);
            int su = __shfl_sync(0xffffffffu, sidx, u);
            a0 = fmaf(wu, d_g[(size_t)su * 64 + lane], a0);
            a1 = fmaf(wu, d_g[(size_t)su * 64 + 32 + lane], a1);
        }
    }
#pragma unroll
    for (int o = 16; o; o >>= 1) sum += __shfl_xor_sync(0xffffffffu, sum, o);
    float inv = __fdividef(1.0f, sum);

    d_h[(size_t)warp * 64 + lane]      = a0 * inv + bg[lane];
    d_h[(size_t)warp * 64 + 32 + lane] = a1 * inv + bg[32 + lane];
}

// ---------------- common bf16-split 128x128xK=64 mma body ----------------
__device__ __forceinline__ void mma_tile_128x128_k64(
    const __nv_bfloat16* pAh, const __nv_bfloat16* pAl,
    const __nv_bfloat16* pBh, const __nv_bfloat16* pBl,
    int i0, int j0, float acc[4][4][4],
    __nv_bfloat16* sAh, __nv_bfloat16* sAl, __nv_bfloat16* sBh, __nv_bfloat16* sBl,
    int tid, int warp_m, int warp_n, int lane)
{
#pragma unroll
    for (int r = 0; r < 4; r++) {
        int idx = tid + r * 256;
        int row = idx >> 3, ch = idx & 7;
        *(uint4*)&sAh[row * SP + ch * 8] = ((const uint4*)(pAh + (size_t)(i0 + row) * 64))[ch];
        *(uint4*)&sAl[row * SP + ch * 8] = ((const uint4*)(pAl + (size_t)(i0 + row) * 64))[ch];
        *(uint4*)&sBh[row * SP + ch * 8] = ((const uint4*)(pBh + (size_t)(j0 + row) * 64))[ch];
        *(uint4*)&sBl[row * SP + ch * 8] = ((const uint4*)(pBl + (size_t)(j0 + row) * 64))[ch];
    }
    __syncthreads();

    int a_row = lane & 15, a_kc = (lane >> 4) << 3;
    int b_row = (lane & 7) + (((lane >> 4) & 1) << 3);
    int b_kc  = (((lane >> 3) & 1) << 3);

#pragma unroll
    for (int ks = 0; ks < 4; ks++) {
        int k0 = ks * 16;
        uint32_t Bh[2][4], Bl[2][4];
#pragma unroll
        for (int nb = 0; nb < 2; nb++) {
            ldm_x4(Bh[nb][0], Bh[nb][1], Bh[nb][2], Bh[nb][3],
                   smem_u32(&sBh[(warp_n + nb * 16 + b_row) * SP + k0 + b_kc]));
            ldm_x4(Bl[nb][0], Bl[nb][1], Bl[nb][2], Bl[nb][3],
                   smem_u32(&sBl[(warp_n + nb * 16 + b_row) * SP + k0 + b_kc]));
        }
#pragma unroll
        for (int mt = 0; mt < 4; mt++) {
            uint32_t Ah[4], Al[4];
            ldm_x4(Ah[0], Ah[1], Ah[2], Ah[3],
                   smem_u32(&sAh[(warp_m + mt * 16 + a_row) * SP + k0 + a_kc]));
#pragma unroll
            for (int nt = 0; nt < 4; nt++)
                mma_bf16(acc[mt][nt], Ah, &Bh[nt >> 1][(nt & 1) * 2]);
#pragma unroll
            for (int nt = 0; nt < 4; nt++)
                mma_bf16(acc[mt][nt], Ah, &Bl[nt >> 1][(nt & 1) * 2]);
            ldm_x4(Al[0], Al[1], Al[2], Al[3],
                   smem_u32(&sAl[(warp_m + mt * 16 + a_row) * SP + k0 + a_kc]));
#pragma unroll
            for (int nt = 0; nt < 4; nt++)
                mma_bf16(acc[mt][nt], Al, &Bh[nt >> 1][(nt & 1) * 2]);
        }
    }
    __syncthreads();   // operand smem dead after this
}

// ---------------- s_ = sigmoid(h h^T): SYMMETRIC, triangular linearized grid ----------------
// 4656 blocks; Cs pitch 129 (==1 mod 32): conflict-free row AND column passes.
#define CP3 129
#define NTRI 4656
__global__ __launch_bounds__(256) void k_s_sym(float* __restrict__ out) {
    int p = blockIdx.x;
    int it = (int)((193.0f - sqrtf(193.0f * 193.0f - 8.0f * (float)p)) * 0.5f);
    while ((it + 1) * (193 - (it + 1)) / 2 <= p) it++;
    while (it * (193 - it) / 2 > p) it--;
    int jt = it + (p - it * (193 - it) / 2);

    extern __shared__ __nv_bfloat16 sm[];
    __nv_bfloat16* sAh = sm;
    __nv_bfloat16* sAl = sm + 9216;
    __nv_bfloat16* sBh = sm + 18432;
    __nv_bfloat16* sBl = sm + 27648;
    float* Cs = (float*)sm;             // [128][129] after compute

    int i0 = it * 128, j0 = jt * 128;
    int tid = threadIdx.x;
    int wid = tid >> 5, lane = tid & 31;
    int warp_m = (wid & 1) * 64;
    int warp_n = (wid >> 1) * 32;

    float acc[4][4][4];
#pragma unroll
    for (int i = 0; i < 4; i++)
#pragma unroll
        for (int j = 0; j < 4; j++)
#pragma unroll
            for (int c = 0; c < 4; c++) acc[i][j][c] = 0.0f;

    mma_tile_128x128_k64(d_hhi, d_hlo, d_hhi, d_hlo, i0, j0, acc,
                         sAh, sAl, sBh, sBl, tid, warp_m, warp_n, lane);

#pragma unroll
    for (int mt = 0; mt < 4; mt++) {
        int r0 = warp_m + mt * 16 + (lane >> 2);
#pragma unroll
        for (int nt = 0; nt < 4; nt++) {
            int c0 = warp_n + nt * 8 + ((lane & 3) << 1);
            Cs[r0 * CP3 + c0]           = sigf(acc[mt][nt][0]);
            Cs[r0 * CP3 + c0 + 1]       = sigf(acc[mt][nt][1]);
            Cs[(r0 + 8) * CP3 + c0]     = sigf(acc[mt][nt][2]);
            Cs[(r0 + 8) * CP3 + c0 + 1] = sigf(acc[mt][nt][3]);
        }
    }
    __syncthreads();

#pragma unroll 4
    for (int itr = 0; itr < 64; itr++) {
        int slot = tid + itr * 256;
        int row = slot >> 7, col = slot & 127;
        out[(size_t)(i0 + row) * NN + j0 + col] = Cs[row * CP3 + col];
    }
    if (jt > it) {
#pragma unroll 4
        for (int itr = 0; itr < 64; itr++) {
            int slot = tid + itr * 256;
            int c = slot >> 7, r = slot & 127;
            out[(size_t)(j0 + c) * NN + i0 + r] = Cs[r * CP3 + c];
        }
    }
}

// ---------------- x_ = h @ xa^T via bf16-split mma ----------------
__global__ __launch_bounds__(256) void k_xout_tc(float* __restrict__ out) {
    extern __shared__ __nv_bfloat16 sm[];
    __nv_bfloat16* sAh = sm;
    __nv_bfloat16* sAl = sm + 9216;
    __nv_bfloat16* sBh = sm + 18432;
    __nv_bfloat16* sBl = sm + 27648;
    float* Cs = (float*)sm;

    int i0 = blockIdx.y * 128, j0 = blockIdx.x * 128;
    int tid = threadIdx.x;
    int wid = tid >> 5, lane = tid & 31;
    int warp_m = (wid & 1) * 64;
    int warp_n = (wid >> 1) * 32;

    float acc[4][4][4];
#pragma unroll
    for (int i = 0; i < 4; i++)
#pragma unroll
        for (int j = 0; j < 4; j++)
#pragma unroll
            for (int c = 0; c < 4; c++) acc[i][j][c] = 0.0f;

    mma_tile_128x128_k64(d_hhi, d_hlo, d_xahi, d_xalo, i0, j0, acc,
                         sAh, sAl, sBh, sBl, tid, warp_m, warp_n, lane);

#pragma unroll
    for (int mt = 0; mt < 4; mt++) {
        int r0 = warp_m + mt * 16 + (lane >> 2);
#pragma unroll
        for (int nt = 0; nt < 4; nt++) {
            int c0 = warp_n + nt * 8 + ((lane & 3) << 1);
            Cs[r0 * CP3 + c0]           = acc[mt][nt][0];
            Cs[r0 * CP3 + c0 + 1]       = acc[mt][nt][1];
            Cs[(r0 + 8) * CP3 + c0]     = acc[mt][nt][2];
            Cs[(r0 + 8) * CP3 + c0 + 1] = acc[mt][nt][3];
        }
    }
    __syncthreads();
#pragma unroll 4
    for (int itr = 0; itr < 64; itr++) {
        int slot = tid + itr * 256;
        int row = slot >> 7, col = slot & 127;
        out[(size_t)(i0 + row) * 512 + j0 + col] = Cs[row * CP3 + col];
    }
}

// ---------------- xtraw = x^T @ W_a1^T via bf16-split mma (48 K-slabs, atomic accum) ----------------
__global__ __launch_bounds__(256) void k_att1_tc() {
    extern __shared__ __nv_bfloat16 sm[];
    __nv_bfloat16* sAh = sm;
    __nv_bfloat16* sAl = sm + 9216;
    __nv_bfloat16* sBh = sm + 18432;
    __nv_bfloat16* sBl = sm + 27648;

    int m0 = blockIdx.x * 128;
    int kbase = blockIdx.y * 256;
    int tid = threadIdx.x;
    int wid = tid >> 5, lane = tid & 31;
    int warp_m = (wid & 1) * 64;
    int warp_n = (wid >> 1) * 32;

    float acc[4][4][4];
#pragma unroll
    for (int i = 0; i < 4; i++)
#pragma unroll
        for (int j = 0; j < 4; j++)
#pragma unroll
            for (int c = 0; c < 4; c++) acc[i][j][c] = 0.0f;

    int a_row = lane & 15, a_kc = (lane >> 4) << 3;
    int b_row = (lane & 7) + (((lane >> 4) & 1) << 3);
    int b_kc  = (((lane >> 3) & 1) << 3);

    for (int kc = 0; kc < 256; kc += 64) {
        int kk = kbase + kc;
#pragma unroll
        for (int r = 0; r < 4; r++) {
            int idx = tid + r * 256;
            int row = idx >> 3, ch = idx & 7;
            *(uint4*)&sAh[row * SP + ch * 8] =
                ((const uint4*)(d_xThi + (size_t)(m0 + row) * NN + kk))[ch];
            *(uint4*)&sAl[row * SP + ch * 8] =
                ((const uint4*)(d_xTlo + (size_t)(m0 + row) * NN + kk))[ch];
            *(uint4*)&sBh[row * SP + ch * 8] =
                ((const uint4*)(d_wa1hi + (size_t)row * NN + kk))[ch];
            *(uint4*)&sBl[row * SP + ch * 8] =
                ((const uint4*)(d_wa1lo + (size_t)row * NN + kk))[ch];
        }
        __syncthreads();
#pragma unroll
        for (int ks = 0; ks < 4; ks++) {
            int k0 = ks * 16;
            uint32_t Bh[2][4], Bl[2][4];
#pragma unroll
            for (int nb = 0; nb < 2; nb++) {
                ldm_x4(Bh[nb][0], Bh[nb][1], Bh[nb][2], Bh[nb][3],
                       smem_u32(&sBh[(warp_n + nb * 16 + b_row) * SP + k0 + b_kc]));
                ldm_x4(Bl[nb][0], Bl[nb][1], Bl[nb][2], Bl[nb][3],
                       smem_u32(&sBl[(warp_n + nb * 16 + b_row) * SP + k0 + b_kc]));
            }
#pragma unroll
            for (int mt = 0; mt < 4; mt++) {
                uint32_t Ah[4], Al[4];
                ldm_x4(Ah[0], Ah[1], Ah[2], Ah[3],
                       smem_u32(&sAh[(warp_m + mt * 16 + a_row) * SP + k0 + a_kc]));
#pragma unroll
                for (int nt = 0; nt < 4; nt++)
                    mma_bf16(acc[mt][nt], Ah, &Bh[nt >> 1][(nt & 1) * 2]);
#pragma unroll
                for (int nt = 0; nt < 4; nt++)
                    mma_bf16(acc[mt][nt], Ah, &Bl[nt >> 1][(nt & 1) * 2]);
                ldm_x4(Al[0], Al[1], Al[2], Al[3],
                       smem_u32(&sAl[(warp_m + mt * 16 + a_row) * SP + k0 + a_kc]));
#pragma unroll
                for (int nt = 0; nt < 4; nt++)
                    mma_bf16(acc[mt][nt], Al, &Bh[nt >> 1][(nt & 1) * 2]);
            }
        }
        __syncthreads();
    }
#pragma unroll
    for (int mt = 0; mt < 4; mt++) {
        int r0 = m0 + warp_m + mt * 16 + (lane >> 2);
#pragma unroll
        for (int nt = 0; nt < 4; nt++) {
            int c = warp_n + nt * 8 + ((lane & 3) << 1);
            atomicAdd(&d_xtraw[(size_t)r0 * 128 + c],           acc[mt][nt][0]);
            atomicAdd(&d_xtraw[(size_t)r0 * 128 + c + 1],       acc[mt][nt][1]);
            atomicAdd(&d_xtraw[(size_t)(r0 + 8) * 128 + c],     acc[mt][nt][2]);
            atomicAdd(&d_xtraw[(size_t)(r0 + 8) * 128 + c + 1], acc[mt][nt][3]);
        }
    }
}

__global__ void k_xa(const float* __restrict__ ba1, const float* __restrict__ W2,
                     const float* __restrict__ ba2) {
    int t = blockIdx.x * blockDim.x + threadIdx.x;
    if (t >= DIN * DOUT) return;
    int d = t >> 6, o = t & 63;
    float s = 0.0f;
#pragma unroll 4
    for (int e = 0; e < 128; e++) {
        float v = d_xtraw[(size_t)d * 128 + e] + ba1[e];
        v = v > 0.0f ? v : 0.0f;
        s = fmaf(v, W2[(size_t)o * 128 + e], s);
    }
    d_xa[t] = s + ba2[o];
}

// ---------------- launch ----------------
extern "C" void kernel_launch(void* const* d_in, const int* in_sizes, int n_in,
                              void* d_out, int out_size) {
    const float* x     = (const float*)d_in[0];
    const float* Ws1   = (const float*)d_in[1];
    const float* bs1   = (const float*)d_in[2];
    const float* Wg    = (const float*)d_in[3];
    const float* asrc  = (const float*)d_in[4];
    const float* adst  = (const float*)d_in[5];
    const float* bg    = (const float*)d_in[6];
    const float* Wa1   = (const float*)d_in[7];
    const float* ba1   = (const float*)d_in[8];
    const float* Wa2   = (const float*)d_in[9];
    const float* ba2   = (const float*)d_in[10];
    const void*  ei    = d_in[11];

    float* out   = (float*)d_out;
    float* out_x = out;                          // [12288, 512]
    float* out_s = out + (size_t)NN * DIN;       // [12288, 12288]

    const int SMEM_BIG = 73728;
    const int SMEM_G   = 55296;
    static int smem_set = 0;
    if (!smem_set) {
        cudaFuncSetAttribute(k_fc1_tc,  cudaFuncAttributeMaxDynamicSharedMemorySize, SMEM_BIG);
        cudaFuncSetAttribute(k_s_sym,   cudaFuncAttributeMaxDynamicSharedMemorySize, SMEM_BIG);
        cudaFuncSetAttribute(k_att1_tc, cudaFuncAttributeMaxDynamicSharedMemorySize, SMEM_BIG);
        cudaFuncSetAttribute(k_xout_tc, cudaFuncAttributeMaxDynamicSharedMemorySize, SMEM_BIG);
        cudaFuncSetAttribute(k_g_tc,    cudaFuncAttributeMaxDynamicSharedMemorySize, SMEM_G);
        smem_set = 1;
    }

    // CSR build + input splits
    k_detect<<<1, 256>>>((const int*)ei);
    k_init<<<256, 256>>>();
    k_count<<<NE / 256, 256>>>(ei);
    k_splitw1<<<DEMB * DIN / 2048, 256>>>(Ws1);
    k_splitwa1<<<DEMB * NN / 2048, 256>>>(Wa1);
    k_splitwg<<<DOUT * DEMB / 2048, 256>>>(Wg);
    k_tsplit<<<dim3(NN / 64, DIN / 64), 256>>>(x);   // also produces d_xhi/d_xlo
    k_scan<<<1, 1024>>>();
    k_scatter<<<TOTE / 256, 256>>>(ei);

    // encoder + GAT
    k_fc1_tc<<<NN / 128, 256, SMEM_BIG>>>(bs1);
    k_g_tc<<<NN / 128, 256, SMEM_G>>>();
    k_sc<<<NN / 8, 256>>>(asrc, adst);
    k_gat<<<NN / 8, 256>>>(bg);

    // structure decoder (tensor cores, symmetric, triangular grid)
    k_split<<<NN * DOUT / 2048, 256>>>();
    k_s_sym<<<NTRI, 256, SMEM_BIG>>>(out_s);

    // attribute decoder (tensor cores)
    k_att1_tc<<<dim3(DIN / 128, 48), 256, SMEM_BIG>>>();
    k_xa<<<(DIN * DOUT) / 256, 256>>>(ba1, Wa2, ba2);
    k_splitxa<<<DIN * DOUT / 2048, 256>>>();
    k_xout_tc<<<dim3(DIN / 128, NN / 128), 256, SMEM_BIG>>>(out_x);
}

// round 15
// speedup vs baseline: 2.7706x; 1.0782x over previous
#include <cuda_runtime.h>
#include <cuda_bf16.h>
#include <cstdint>

#define NN   12288
#define DIN  512
#define DEMB 128
#define DOUT 64
#define NE   393216
#define TOTE (NE + NN)     // 405504
#define NEG  0.2f

// ---------------- scratch (device globals; no allocation) ----------------
__device__ __nv_bfloat16 d_x1hi[NN * DEMB];
__device__ __nv_bfloat16 d_x1lo[NN * DEMB];
__device__ float d_g[NN * DOUT];
__device__ float d_scs[NN];
__device__ float d_scd[NN];
__device__ __nv_bfloat16 d_hhi[NN * DOUT];
__device__ __nv_bfloat16 d_hlo[NN * DOUT];
__device__ __nv_bfloat16 d_xhi[NN * DIN];
__device__ __nv_bfloat16 d_xlo[NN * DIN];
__device__ __nv_bfloat16 d_xThi[DIN * NN];   // x^T, bf16 hi
__device__ __nv_bfloat16 d_xTlo[DIN * NN];
__device__ __nv_bfloat16 d_w1hi[DEMB * DIN];
__device__ __nv_bfloat16 d_w1lo[DEMB * DIN];
__device__ __nv_bfloat16 d_wa1hi[DEMB * NN];
__device__ __nv_bfloat16 d_wa1lo[DEMB * NN];
__device__ __nv_bfloat16 d_wghi[DOUT * DEMB];
__device__ __nv_bfloat16 d_wglo[DOUT * DEMB];
__device__ __nv_bfloat16 d_xahi[DIN * DOUT];
__device__ __nv_bfloat16 d_xalo[DIN * DOUT];
__device__ float d_xtraw[DIN * DEMB];
__device__ int   d_deg[NN];
__device__ int   d_off[NN + 1];
__device__ int   d_fill[NN];
__device__ int   d_csr[TOTE];
__device__ int   d_is64;

// ---------------- helpers ----------------
__device__ __forceinline__ float sigf(float v) {
    return __fdividef(1.0f, 1.0f + __expf(-v));
}
__device__ __forceinline__ int clampn(int v) {
    v = v < 0 ? 0 : v;
    return v >= NN ? NN - 1 : v;
}
__device__ __forceinline__ uint32_t smem_u32(const void* p) {
    return (uint32_t)__cvta_generic_to_shared(p);
}
__device__ __forceinline__ void ldm_x4(uint32_t& r0, uint32_t& r1, uint32_t& r2,
                                       uint32_t& r3, uint32_t addr) {
    asm volatile("ldmatrix.sync.aligned.m8n8.x4.shared.b16 {%0,%1,%2,%3}, [%4];"
                 : "=r"(r0), "=r"(r1), "=r"(r2), "=r"(r3) : "r"(addr));
}
__device__ __forceinline__ void mma_bf16(float* c, const uint32_t* a, const uint32_t* b) {
    asm volatile(
        "mma.sync.aligned.m16n8k16.row.col.f32.bf16.bf16.f32 "
        "{%0,%1,%2,%3}, {%4,%5,%6,%7}, {%8,%9}, {%0,%1,%2,%3};"
        : "+f"(c[0]), "+f"(c[1]), "+f"(c[2]), "+f"(c[3])
        : "r"(a[0]), "r"(a[1]), "r"(a[2]), "r"(a[3]), "r"(b[0]), "r"(b[1]));
}

// ---------------- dtype probe ----------------
__global__ void k_detect(const int* __restrict__ ei32) {
    __shared__ int any;
    if (threadIdx.x == 0) any = 0;
    __syncthreads();
    if (ei32[threadIdx.x * 2 + 1] != 0) any = 1;
    __syncthreads();
    if (threadIdx.x == 0) d_is64 = (any == 0) ? 1 : 0;
}

__global__ void k_init() {
    int t = blockIdx.x * blockDim.x + threadIdx.x;
    if (t < DIN * DEMB) d_xtraw[t] = 0.0f;
    if (t < NN) d_deg[t] = 1;
}

__global__ void k_count(const void* __restrict__ ei) {
    int e = blockIdx.x * blockDim.x + threadIdx.x;
    if (e < NE) {
        int dst;
        if (d_is64) dst = (int)((const long long*)ei)[NE + e];
        else        dst = ((const int*)ei)[NE + e];
        atomicAdd(&d_deg[clampn(dst)], 1);
    }
}

// warp-shuffle scan (12 values/thread via 3x int4, 1024 threads)
__global__ void k_scan() {
    __shared__ int wsum[32];
    int t = threadIdx.x, lane = t & 31, w = t >> 5;
    int base = t * 12;
    int loc[12];
#pragma unroll
    for (int q = 0; q < 3; q++) {
        int4 v = *(const int4*)&d_deg[base + q * 4];
        loc[q * 4 + 0] = v.x; loc[q * 4 + 1] = v.y;
        loc[q * 4 + 2] = v.z; loc[q * 4 + 3] = v.w;
    }
    int s = 0;
#pragma unroll
    for (int i = 0; i < 12; i++) s += loc[i];
    int pre = s;
#pragma unroll
    for (int o = 1; o < 32; o <<= 1) {
        int v = __shfl_up_sync(0xffffffffu, pre, o);
        if (lane >= o) pre += v;
    }
    if (lane == 31) wsum[w] = pre;
    __syncthreads();
    if (w == 0) {
        int v = wsum[lane];
#pragma unroll
        for (int o = 1; o < 32; o <<= 1) {
            int u = __shfl_up_sync(0xffffffffu, v, o);
            if (lane >= o) v += u;
        }
        wsum[lane] = v;
    }
    __syncthreads();
    int run = pre - s + (w ? wsum[w - 1] : 0);
#pragma unroll
    for (int i = 0; i < 12; i++) {
        d_off[base + i]  = run;
        d_fill[base + i] = run;
        run += loc[i];
    }
    if (t == 1023) d_off[NN] = run;
}

__global__ void k_scatter(const void* __restrict__ ei) {
    int e = blockIdx.x * blockDim.x + threadIdx.x;
    if (e < NE) {
        int src, dst;
        if (d_is64) {
            src = (int)((const long long*)ei)[e];
            dst = (int)((const long long*)ei)[NE + e];
        } else {
            src = ((const int*)ei)[e];
            dst = ((const int*)ei)[NE + e];
        }
        int p = atomicAdd(&d_fill[clampn(dst)], 1);
        if (p < TOTE) d_csr[p] = clampn(src);
    } else if (e < TOTE) {
        int n = e - NE;
        int p = atomicAdd(&d_fill[n], 1);
        if (p < TOTE) d_csr[p] = n;
    }
}

// ---------------- split kernels (vectorized: 8 elems/thread) ----------------
__device__ __forceinline__ void split8(const float* __restrict__ src,
                                       __nv_bfloat16* __restrict__ hi,
                                       __nv_bfloat16* __restrict__ lo, size_t base) {
    float4 v0 = *(const float4*)&src[base];
    float4 v1 = *(const float4*)&src[base + 4];
    float f[8] = {v0.x, v0.y, v0.z, v0.w, v1.x, v1.y, v1.z, v1.w};
    __nv_bfloat16 h[8], l[8];
#pragma unroll
    for (int i = 0; i < 8; i++) {
        h[i] = __float2bfloat16(f[i]);
        l[i] = __float2bfloat16(f[i] - __bfloat162float(h[i]));
    }
    *(uint4*)&hi[base] = *(uint4*)h;
    *(uint4*)&lo[base] = *(uint4*)l;
}
__global__ void k_splitw1(const float* __restrict__ W) {
    size_t base = (size_t)(blockIdx.x * blockDim.x + threadIdx.x) * 8;
    split8(W, d_w1hi, d_w1lo, base);
}
__global__ void k_splitwa1(const float* __restrict__ W) {
    size_t base = (size_t)(blockIdx.x * blockDim.x + threadIdx.x) * 8;
    split8(W, d_wa1hi, d_wa1lo, base);
}
__global__ void k_splitwg(const float* __restrict__ W) {
    size_t base = (size_t)(blockIdx.x * blockDim.x + threadIdx.x) * 8;
    split8(W, d_wghi, d_wglo, base);
}

// ---------------- transpose+split x: fills BOTH row-major (d_xhi/lo) AND x^T (d_xThi/lo) ----------------
__global__ __launch_bounds__(256) void k_tsplit(const float* __restrict__ x) {
    __shared__ __nv_bfloat16 shhi[64 * 68];
    __shared__ __nv_bfloat16 shlo[64 * 68];
    int k0 = blockIdx.x * 64, d0 = blockIdx.y * 64;
    int tid = threadIdx.x;
#pragma unroll
    for (int i = 0; i < 4; i++) {
        int slot = tid + i * 256;
        int kk = slot >> 4, q = slot & 15;
        float4 v = *(const float4*)&x[(size_t)(k0 + kk) * 512 + d0 + q * 4];
        __nv_bfloat16 h[4], l[4];
        float f[4] = {v.x, v.y, v.z, v.w};
#pragma unroll
        for (int u = 0; u < 4; u++) {
            h[u] = __float2bfloat16(f[u]);
            l[u] = __float2bfloat16(f[u] - __bfloat162float(h[u]));
        }
        *(uint2*)&d_xhi[(size_t)(k0 + kk) * 512 + d0 + q * 4] = *(uint2*)h;
        *(uint2*)&d_xlo[(size_t)(k0 + kk) * 512 + d0 + q * 4] = *(uint2*)l;
        *(uint2*)&shhi[kk * 68 + q * 4] = *(uint2*)h;
        *(uint2*)&shlo[kk * 68 + q * 4] = *(uint2*)l;
    }
    __syncthreads();
#pragma unroll
    for (int i = 0; i < 4; i++) {
        int slot = tid + i * 256;
        int arr = slot >> 9;
        int s2 = slot & 511;
        int dd = s2 >> 3, qc = s2 & 7;
        const __nv_bfloat16* sh = arr ? shlo : shhi;
        __nv_bfloat16 vals[8];
#pragma unroll
        for (int u = 0; u < 8; u++) vals[u] = sh[(qc * 8 + u) * 68 + dd];
        __nv_bfloat16* dst = arr ? d_xTlo : d_xThi;
        *(uint4*)&dst[(size_t)(d0 + dd) * NN + k0 + qc * 8] = *(uint4*)vals;
    }
}

#define SP 72    // operand smem pitch (halves)

// ---------------- x1 = relu(x @ W_s1^T + b) via bf16-split mma (outputs bf16 hi/lo) ----------------
__global__ __launch_bounds__(256) void k_fc1_tc(const float* __restrict__ b) {
    extern __shared__ __nv_bfloat16 sm[];
    __nv_bfloat16* sAh = sm;
    __nv_bfloat16* sAl = sm + 9216;
    __nv_bfloat16* sBh = sm + 18432;
    __nv_bfloat16* sBl = sm + 27648;

    int m0 = blockIdx.x * 128;
    int tid = threadIdx.x;
    int wid = tid >> 5, lane = tid & 31;
    int warp_m = (wid & 1) * 64;
    int warp_n = (wid >> 1) * 32;

    float acc[4][4][4];
#pragma unroll
    for (int i = 0; i < 4; i++)
#pragma unroll
        for (int j = 0; j < 4; j++)
#pragma unroll
            for (int c = 0; c < 4; c++) acc[i][j][c] = 0.0f;

    int a_row = lane & 15, a_kc = (lane >> 4) << 3;
    int b_row = (lane & 7) + (((lane >> 4) & 1) << 3);
    int b_kc  = (((lane >> 3) & 1) << 3);

    for (int kc = 0; kc < 512; kc += 64) {
#pragma unroll
        for (int r = 0; r < 4; r++) {
            int idx = tid + r * 256;
            int row = idx >> 3, ch = idx & 7;
            *(uint4*)&sAh[row * SP + ch * 8] =
                ((const uint4*)(d_xhi + (size_t)(m0 + row) * 512 + kc))[ch];
            *(uint4*)&sAl[row * SP + ch * 8] =
                ((const uint4*)(d_xlo + (size_t)(m0 + row) * 512 + kc))[ch];
            *(uint4*)&sBh[row * SP + ch * 8] =
                ((const uint4*)(d_w1hi + (size_t)row * 512 + kc))[ch];
            *(uint4*)&sBl[row * SP + ch * 8] =
                ((const uint4*)(d_w1lo + (size_t)row * 512 + kc))[ch];
        }
        __syncthreads();
#pragma unroll
        for (int ks = 0; ks < 4; ks++) {
            int k0 = ks * 16;
            uint32_t Bh[2][4], Bl[2][4];
#pragma unroll
            for (int nb = 0; nb < 2; nb++) {
                ldm_x4(Bh[nb][0], Bh[nb][1], Bh[nb][2], Bh[nb][3],
                       smem_u32(&sBh[(warp_n + nb * 16 + b_row) * SP + k0 + b_kc]));
                ldm_x4(Bl[nb][0], Bl[nb][1], Bl[nb][2], Bl[nb][3],
                       smem_u32(&sBl[(warp_n + nb * 16 + b_row) * SP + k0 + b_kc]));
            }
#pragma unroll
            for (int mt = 0; mt < 4; mt++) {
                uint32_t Ah[4], Al[4];
                ldm_x4(Ah[0], Ah[1], Ah[2], Ah[3],
                       smem_u32(&sAh[(warp_m + mt * 16 + a_row) * SP + k0 + a_kc]));
#pragma unroll
                for (int nt = 0; nt < 4; nt++)
                    mma_bf16(acc[mt][nt], Ah, &Bh[nt >> 1][(nt & 1) * 2]);
#pragma unroll
                for (int nt = 0; nt < 4; nt++)
                    mma_bf16(acc[mt][nt], Ah, &Bl[nt >> 1][(nt & 1) * 2]);
                ldm_x4(Al[0], Al[1], Al[2], Al[3],
                       smem_u32(&sAl[(warp_m + mt * 16 + a_row) * SP + k0 + a_kc]));
#pragma unroll
                for (int nt = 0; nt < 4; nt++)
                    mma_bf16(acc[mt][nt], Al, &Bh[nt >> 1][(nt & 1) * 2]);
            }
        }
        __syncthreads();
    }
#pragma unroll
    for (int mt = 0; mt < 4; mt++) {
        int r0 = m0 + warp_m + mt * 16 + (lane >> 2);
#pragma unroll
        for (int nt = 0; nt < 4; nt++) {
            int c = warp_n + nt * 8 + ((lane & 3) << 1);
            float b0 = b[c], b1 = b[c + 1];
            float v00 = fmaxf(acc[mt][nt][0] + b0, 0.0f);
            float v01 = fmaxf(acc[mt][nt][1] + b1, 0.0f);
            float v10 = fmaxf(acc[mt][nt][2] + b0, 0.0f);
            float v11 = fmaxf(acc[mt][nt][3] + b1, 0.0f);
            __nv_bfloat16 h00 = __float2bfloat16(v00), h01 = __float2bfloat16(v01);
            __nv_bfloat16 h10 = __float2bfloat16(v10), h11 = __float2bfloat16(v11);
            __nv_bfloat162 p;
            p.x = h00; p.y = h01;
            *(__nv_bfloat162*)&d_x1hi[(size_t)r0 * 128 + c] = p;
            p.x = __float2bfloat16(v00 - __bfloat162float(h00));
            p.y = __float2bfloat16(v01 - __bfloat162float(h01));
            *(__nv_bfloat162*)&d_x1lo[(size_t)r0 * 128 + c] = p;
            p.x = h10; p.y = h11;
            *(__nv_bfloat162*)&d_x1hi[(size_t)(r0 + 8) * 128 + c] = p;
            p.x = __float2bfloat16(v10 - __bfloat162float(h10));
            p.y = __float2bfloat16(v11 - __bfloat162float(h11));
            *(__nv_bfloat162*)&d_x1lo[(size_t)(r0 + 8) * 128 + c] = p;
        }
    }
}

// ---------------- g = x1 @ W_g^T via bf16-split mma (128x64 tile) ----------------
__global__ __launch_bounds__(256) void k_g_tc() {
    extern __shared__ __nv_bfloat16 sm[];
    __nv_bfloat16* sAh = sm;
    __nv_bfloat16* sAl = sm + 9216;
    __nv_bfloat16* sBh = sm + 18432;
    __nv_bfloat16* sBl = sm + 23040;

    int m0 = blockIdx.x * 128;
    int tid = threadIdx.x;
    int wid = tid >> 5, lane = tid & 31;
    int warp_m = (wid >> 2) * 64;
    int warp_n = (wid & 3) * 16;

    float acc[4][2][4];
#pragma unroll
    for (int a = 0; a < 4; a++)
#pragma unroll
        for (int b = 0; b < 2; b++)
#pragma unroll
            for (int c = 0; c < 4; c++) acc[a][b][c] = 0.0f;

    int a_row = lane & 15, a_kc = (lane >> 4) << 3;
    int b_row = (lane & 7) + (((lane >> 4) & 1) << 3);
    int b_kc  = (((lane >> 3) & 1) << 3);

    for (int kc = 0; kc < 128; kc += 64) {
#pragma unroll
        for (int r = 0; r < 4; r++) {
            int idx = tid + r * 256;
            int row = idx >> 3, ch = idx & 7;
            *(uint4*)&sAh[row * SP + ch * 8] =
                ((const uint4*)(d_x1hi + (size_t)(m0 + row) * 128 + kc))[ch];
            *(uint4*)&sAl[row * SP + ch * 8] =
                ((const uint4*)(d_x1lo + (size_t)(m0 + row) * 128 + kc))[ch];
        }
#pragma unroll
        for (int r = 0; r < 2; r++) {
            int idx = tid + r * 256;
            int row = idx >> 3, ch = idx & 7;
            *(uint4*)&sBh[row * SP + ch * 8] =
                ((const uint4*)(d_wghi + (size_t)row * 128 + kc))[ch];
            *(uint4*)&sBl[row * SP + ch * 8] =
                ((const uint4*)(d_wglo + (size_t)row * 128 + kc))[ch];
        }
        __syncthreads();
#pragma unroll
        for (int ks = 0; ks < 4; ks++) {
            int k0 = ks * 16;
            uint32_t Bh[4], Bl[4];
            ldm_x4(Bh[0], Bh[1], Bh[2], Bh[3],
                   smem_u32(&sBh[(warp_n + b_row) * SP + k0 + b_kc]));
            ldm_x4(Bl[0], Bl[1], Bl[2], Bl[3],
                   smem_u32(&sBl[(warp_n + b_row) * SP + k0 + b_kc]));
#pragma unroll
            for (int mt = 0; mt < 4; mt++) {
                uint32_t Ah[4], Al[4];
                ldm_x4(Ah[0], Ah[1], Ah[2], Ah[3],
                       smem_u32(&sAh[(warp_m + mt * 16 + a_row) * SP + k0 + a_kc]));
                mma_bf16(acc[mt][0], Ah, &Bh[0]);
                mma_bf16(acc[mt][1], Ah, &Bh[2]);
                mma_bf16(acc[mt][0], Ah, &Bl[0]);
                mma_bf16(acc[mt][1], Ah, &Bl[2]);
                ldm_x4(Al[0], Al[1], Al[2], Al[3],
                       smem_u32(&sAl[(warp_m + mt * 16 + a_row) * SP + k0 + a_kc]));
                mma_bf16(acc[mt][0], Al, &Bh[0]);
                mma_bf16(acc[mt][1], Al, &Bh[2]);
            }
        }
        __syncthreads();
    }
#pragma unroll
    for (int mt = 0; mt < 4; mt++) {
        int r0 = m0 + warp_m + mt * 16 + (lane >> 2);
#pragma unroll
        for (int nt = 0; nt < 2; nt++) {
            int c0 = warp_n + nt * 8 + ((lane & 3) << 1);
            d_g[(size_t)r0 * 64 + c0]           = acc[mt][nt][0];
            d_g[(size_t)r0 * 64 + c0 + 1]       = acc[mt][nt][1];
            d_g[(size_t)(r0 + 8) * 64 + c0]     = acc[mt][nt][2];
            d_g[(size_t)(r0 + 8) * 64 + c0 + 1] = acc[mt][nt][3];
        }
    }
}

// ---------------- attention scores ----------------
__global__ void k_sc(const float* __restrict__ asrc, const float* __restrict__ adst) {
    int warp = (blockIdx.x * blockDim.x + threadIdx.x) >> 5;
    int lane = threadIdx.x & 31;
    if (warp >= NN) return;
    float g0 = d_g[(size_t)warp * 64 + lane];
    float g1 = d_g[(size_t)warp * 64 + 32 + lane];
    float vs = g0 * asrc[lane] + g1 * asrc[32 + lane];
    float vd = g0 * adst[lane] + g1 * adst[32 + lane];
#pragma unroll
    for (int o = 16; o; o >>= 1) {
        vs += __shfl_xor_sync(0xffffffffu, vs, o);
        vd += __shfl_xor_sync(0xffffffffu, vd, o);
    }
    if (lane == 0) { d_scs[warp] = vs; d_scd[warp] = vd; }
}

// ---------------- GAT aggregation (fused h-split: writes d_hhi/d_hlo directly) ----------------
__global__ void k_gat(const float* __restrict__ bg) {
    int warp = (blockIdx.x * blockDim.x + threadIdx.x) >> 5;
    int lane = threadIdx.x & 31;
    if (warp >= NN) return;
    int s0 = d_off[warp], s1 = d_off[warp + 1];
    float scd = d_scd[warp];

    float mx = -1e30f;
    for (int j = s0 + lane; j < s1; j += 32) {
        int s = d_csr[j];
        float e = d_scs[s] + scd;
        e = e > 0.0f ? e : NEG * e;
        mx = fmaxf(mx, e);
    }
#pragma unroll
    for (int o = 16; o; o >>= 1) mx = fmaxf(mx, __shfl_xor_sync(0xffffffffu, mx, o));

    float sum = 0.0f, a0 = 0.0f, a1 = 0.0f;
    for (int jb = s0; jb < s1; jb += 32) {
        int j = jb + lane;
        float w = 0.0f;
        int sidx = 0;
        if (j < s1) {
            sidx = d_csr[j];
            float e = d_scs[sidx] + scd;
            e = e > 0.0f ? e : NEG * e;
            w = __expf(e - mx);
        }
        sum += w;
        int cnt = s1 - jb;
        if (cnt > 32) cnt = 32;
        for (int u = 0; u < cnt; u++) {
            float wu = __shfl_sync(0xffffffffu, w, u);
            int su = __shfl_sync(0xffffffffu, sidx, u);
            a0 = fmaf(wu, d_g[(size_t)su * 64 + lane], a0);
            a1 = fmaf(wu, d_g[(size_t)su * 64 + 32 + lane], a1);
        }
    }
#pragma unroll
    for (int o = 16; o; o >>= 1) sum += __shfl_xor_sync(0xffffffffu, sum, o);
    float inv = __fdividef(1.0f, sum);

    float h0 = a0 * inv + bg[lane];
    float h1 = a1 * inv + bg[32 + lane];
    __nv_bfloat16 p0 = __float2bfloat16(h0);
    __nv_bfloat16 p1 = __float2bfloat16(h1);
    d_hhi[(size_t)warp * 64 + lane]      = p0;
    d_hlo[(size_t)warp * 64 + lane]      = __float2bfloat16(h0 - __bfloat162float(p0));
    d_hhi[(size_t)warp * 64 + 32 + lane] = p1;
    d_hlo[(size_t)warp * 64 + 32 + lane] = __float2bfloat16(h1 - __bfloat162float(p1));
}

// ---------------- common bf16-split 128x128xK=64 mma body ----------------
__device__ __forceinline__ void mma_tile_128x128_k64(
    const __nv_bfloat16* pAh, const __nv_bfloat16* pAl,
    const __nv_bfloat16* pBh, const __nv_bfloat16* pBl,
    int i0, int j0, float acc[4][4][4],
    __nv_bfloat16* sAh, __nv_bfloat16* sAl, __nv_bfloat16* sBh, __nv_bfloat16* sBl,
    int tid, int warp_m, int warp_n, int lane)
{
#pragma unroll
    for (int r = 0; r < 4; r++) {
        int idx = tid + r * 256;
        int row = idx >> 3, ch = idx & 7;
        *(uint4*)&sAh[row * SP + ch * 8] = ((const uint4*)(pAh + (size_t)(i0 + row) * 64))[ch];
        *(uint4*)&sAl[row * SP + ch * 8] = ((const uint4*)(pAl + (size_t)(i0 + row) * 64))[ch];
        *(uint4*)&sBh[row * SP + ch * 8] = ((const uint4*)(pBh + (size_t)(j0 + row) * 64))[ch];
        *(uint4*)&sBl[row * SP + ch * 8] = ((const uint4*)(pBl + (size_t)(j0 + row) * 64))[ch];
    }
    __syncthreads();

    int a_row = lane & 15, a_kc = (lane >> 4) << 3;
    int b_row = (lane & 7) + (((lane >> 4) & 1) << 3);
    int b_kc  = (((lane >> 3) & 1) << 3);

#pragma unroll
    for (int ks = 0; ks < 4; ks++) {
        int k0 = ks * 16;
        uint32_t Bh[2][4], Bl[2][4];
#pragma unroll
        for (int nb = 0; nb < 2; nb++) {
            ldm_x4(Bh[nb][0], Bh[nb][1], Bh[nb][2], Bh[nb][3],
                   smem_u32(&sBh[(warp_n + nb * 16 + b_row) * SP + k0 + b_kc]));
            ldm_x4(Bl[nb][0], Bl[nb][1], Bl[nb][2], Bl[nb][3],
                   smem_u32(&sBl[(warp_n + nb * 16 + b_row) * SP + k0 + b_kc]));
        }
#pragma unroll
        for (int mt = 0; mt < 4; mt++) {
            uint32_t Ah[4], Al[4];
            ldm_x4(Ah[0], Ah[1], Ah[2], Ah[3],
                   smem_u32(&sAh[(warp_m + mt * 16 + a_row) * SP + k0 + a_kc]));
#pragma unroll
            for (int nt = 0; nt < 4; nt++)
                mma_bf16(acc[mt][nt], Ah, &Bh[nt >> 1][(nt & 1) * 2]);
#pragma unroll
            for (int nt = 0; nt < 4; nt++)
                mma_bf16(acc[mt][nt], Ah, &Bl[nt >> 1][(nt & 1) * 2]);
            ldm_x4(Al[0], Al[1], Al[2], Al[3],
                   smem_u32(&sAl[(warp_m + mt * 16 + a_row) * SP + k0 + a_kc]));
#pragma unroll
            for (int nt = 0; nt < 4; nt++)
                mma_bf16(acc[mt][nt], Al, &Bh[nt >> 1][(nt & 1) * 2]);
        }
    }
    __syncthreads();   // operand smem dead after this
}

// ---------------- s_ = sigmoid(h h^T): SYMMETRIC, triangular linearized grid ----------------
#define CP3 129
#define NTRI 4656
__global__ __launch_bounds__(256) void k_s_sym(float* __restrict__ out) {
    int p = blockIdx.x;
    int it = (int)((193.0f - sqrtf(193.0f * 193.0f - 8.0f * (float)p)) * 0.5f);
    while ((it + 1) * (193 - (it + 1)) / 2 <= p) it++;
    while (it * (193 - it) / 2 > p) it--;
    int jt = it + (p - it * (193 - it) / 2);

    extern __shared__ __nv_bfloat16 sm[];
    __nv_bfloat16* sAh = sm;
    __nv_bfloat16* sAl = sm + 9216;
    __nv_bfloat16* sBh = sm + 18432;
    __nv_bfloat16* sBl = sm + 27648;
    float* Cs = (float*)sm;             // [128][129] after compute

    int i0 = it * 128, j0 = jt * 128;
    int tid = threadIdx.x;
    int wid = tid >> 5, lane = tid & 31;
    int warp_m = (wid & 1) * 64;
    int warp_n = (wid >> 1) * 32;

    float acc[4][4][4];
#pragma unroll
    for (int i = 0; i < 4; i++)
#pragma unroll
        for (int j = 0; j < 4; j++)
#pragma unroll
            for (int c = 0; c < 4; c++) acc[i][j][c] = 0.0f;

    mma_tile_128x128_k64(d_hhi, d_hlo, d_hhi, d_hlo, i0, j0, acc,
                         sAh, sAl, sBh, sBl, tid, warp_m, warp_n, lane);

#pragma unroll
    for (int mt = 0; mt < 4; mt++) {
        int r0 = warp_m + mt * 16 + (lane >> 2);
#pragma unroll
        for (int nt = 0; nt < 4; nt++) {
            int c0 = warp_n + nt * 8 + ((lane & 3) << 1);
            Cs[r0 * CP3 + c0]           = sigf(acc[mt][nt][0]);
            Cs[r0 * CP3 + c0 + 1]       = sigf(acc[mt][nt][1]);
            Cs[(r0 + 8) * CP3 + c0]     = sigf(acc[mt][nt][2]);
            Cs[(r0 + 8) * CP3 + c0 + 1] = sigf(acc[mt][nt][3]);
        }
    }
    __syncthreads();

#pragma unroll 4
    for (int itr = 0; itr < 64; itr++) {
        int slot = tid + itr * 256;
        int row = slot >> 7, col = slot & 127;
        out[(size_t)(i0 + row) * NN + j0 + col] = Cs[row * CP3 + col];
    }
    if (jt > it) {
#pragma unroll 4
        for (int itr = 0; itr < 64; itr++) {
            int slot = tid + itr * 256;
            int c = slot >> 7, r = slot & 127;
            out[(size_t)(j0 + c) * NN + i0 + r] = Cs[r * CP3 + c];
        }
    }
}

// ---------------- x_ = h @ xa^T via bf16-split mma ----------------
__global__ __launch_bounds__(256) void k_xout_tc(float* __restrict__ out) {
    extern __shared__ __nv_bfloat16 sm[];
    __nv_bfloat16* sAh = sm;
    __nv_bfloat16* sAl = sm + 9216;
    __nv_bfloat16* sBh = sm + 18432;
    __nv_bfloat16* sBl = sm + 27648;
    float* Cs = (float*)sm;

    int i0 = blockIdx.y * 128, j0 = blockIdx.x * 128;
    int tid = threadIdx.x;
    int wid = tid >> 5, lane = tid & 31;
    int warp_m = (wid & 1) * 64;
    int warp_n = (wid >> 1) * 32;

    float acc[4][4][4];
#pragma unroll
    for (int i = 0; i < 4; i++)
#pragma unroll
        for (int j = 0; j < 4; j++)
#pragma unroll
            for (int c = 0; c < 4; c++) acc[i][j][c] = 0.0f;

    mma_tile_128x128_k64(d_hhi, d_hlo, d_xahi, d_xalo, i0, j0, acc,
                         sAh, sAl, sBh, sBl, tid, warp_m, warp_n, lane);

#pragma unroll
    for (int mt = 0; mt < 4; mt++) {
        int r0 = warp_m + mt * 16 + (lane >> 2);
#pragma unroll
        for (int nt = 0; nt < 4; nt++) {
            int c0 = warp_n + nt * 8 + ((lane & 3) << 1);
            Cs[r0 * CP3 + c0]           = acc[mt][nt][0];
            Cs[r0 * CP3 + c0 + 1]       = acc[mt][nt][1];
            Cs[(r0 + 8) * CP3 + c0]     = acc[mt][nt][2];
            Cs[(r0 + 8) * CP3 + c0 + 1] = acc[mt][nt][3];
        }
    }
    __syncthreads();
#pragma unroll 4
    for (int itr = 0; itr < 64; itr++) {
        int slot = tid + itr * 256;
        int row = slot >> 7, col = slot & 127;
        out[(size_t)(i0 + row) * 512 + j0 + col] = Cs[row * CP3 + col];
    }
}

// ---------------- xtraw = x^T @ W_a1^T via bf16-split mma (48 K-slabs, atomic accum) ----------------
__global__ __launch_bounds__(256) void k_att1_tc() {
    extern __shared__ __nv_bfloat16 sm[];
    __nv_bfloat16* sAh = sm;
    __nv_bfloat16* sAl = sm + 9216;
    __nv_bfloat16* sBh = sm + 18432;
    __nv_bfloat16* sBl = sm + 27648;

    int m0 = blockIdx.x * 128;
    int kbase = blockIdx.y * 256;
    int tid = threadIdx.x;
    int wid = tid >> 5, lane = tid & 31;
    int warp_m = (wid & 1) * 64;
    int warp_n = (wid >> 1) * 32;

    float acc[4][4][4];
#pragma unroll
    for (int i = 0; i < 4; i++)
#pragma unroll
        for (int j = 0; j < 4; j++)
#pragma unroll
            for (int c = 0; c < 4; c++) acc[i][j][c] = 0.0f;

    int a_row = lane & 15, a_kc = (lane >> 4) << 3;
    int b_row = (lane & 7) + (((lane >> 4) & 1) << 3);
    int b_kc  = (((lane >> 3) & 1) << 3);

    for (int kc = 0; kc < 256; kc += 64) {
        int kk = kbase + kc;
#pragma unroll
        for (int r = 0; r < 4; r++) {
            int idx = tid + r * 256;
            int row = idx >> 3, ch = idx & 7;
            *(uint4*)&sAh[row * SP + ch * 8] =
                ((const uint4*)(d_xThi + (size_t)(m0 + row) * NN + kk))[ch];
            *(uint4*)&sAl[row * SP + ch * 8] =
                ((const uint4*)(d_xTlo + (size_t)(m0 + row) * NN + kk))[ch];
            *(uint4*)&sBh[row * SP + ch * 8] =
                ((const uint4*)(d_wa1hi + (size_t)row * NN + kk))[ch];
            *(uint4*)&sBl[row * SP + ch * 8] =
                ((const uint4*)(d_wa1lo + (size_t)row * NN + kk))[ch];
        }
        __syncthreads();
#pragma unroll
        for (int ks = 0; ks < 4; ks++) {
            int k0 = ks * 16;
            uint32_t Bh[2][4], Bl[2][4];
#pragma unroll
            for (int nb = 0; nb < 2; nb++) {
                ldm_x4(Bh[nb][0], Bh[nb][1], Bh[nb][2], Bh[nb][3],
                       smem_u32(&sBh[(warp_n + nb * 16 + b_row) * SP + k0 + b_kc]));
                ldm_x4(Bl[nb][0], Bl[nb][1], Bl[nb][2], Bl[nb][3],
                       smem_u32(&sBl[(warp_n + nb * 16 + b_row) * SP + k0 + b_kc]));
            }
#pragma unroll
            for (int mt = 0; mt < 4; mt++) {
                uint32_t Ah[4], Al[4];
                ldm_x4(Ah[0], Ah[1], Ah[2], Ah[3],
                       smem_u32(&sAh[(warp_m + mt * 16 + a_row) * SP + k0 + a_kc]));
#pragma unroll
                for (int nt = 0; nt < 4; nt++)
                    mma_bf16(acc[mt][nt], Ah, &Bh[nt >> 1][(nt & 1) * 2]);
#pragma unroll
                for (int nt = 0; nt < 4; nt++)
                    mma_bf16(acc[mt][nt], Ah, &Bl[nt >> 1][(nt & 1) * 2]);
                ldm_x4(Al[0], Al[1], Al[2], Al[3],
                       smem_u32(&sAl[(warp_m + mt * 16 + a_row) * SP + k0 + a_kc]));
#pragma unroll
                for (int nt = 0; nt < 4; nt++)
                    mma_bf16(acc[mt][nt], Al, &Bh[nt >> 1][(nt & 1) * 2]);
            }
        }
        __syncthreads();
    }
#pragma unroll
    for (int mt = 0; mt < 4; mt++) {
        int r0 = m0 + warp_m + mt * 16 + (lane >> 2);
#pragma unroll
        for (int nt = 0; nt < 4; nt++) {
            int c = warp_n + nt * 8 + ((lane & 3) << 1);
            atomicAdd(&d_xtraw[(size_t)r0 * 128 + c],           acc[mt][nt][0]);
            atomicAdd(&d_xtraw[(size_t)r0 * 128 + c + 1],       acc[mt][nt][1]);
            atomicAdd(&d_xtraw[(size_t)(r0 + 8) * 128 + c],     acc[mt][nt][2]);
            atomicAdd(&d_xtraw[(size_t)(r0 + 8) * 128 + c + 1], acc[mt][nt][3]);
        }
    }
}

// ---------------- xa = relu(xtraw + ba1) @ W2^T + ba2, fused bf16 split ----------------
__global__ void k_xa(const float* __restrict__ ba1, const float* __restrict__ W2,
                     const float* __restrict__ ba2) {
    int t = blockIdx.x * blockDim.x + threadIdx.x;
    if (t >= DIN * DOUT) return;
    int d = t >> 6, o = t & 63;
    float s = 0.0f;
#pragma unroll 4
    for (int e = 0; e < 128; e++) {
        float v = d_xtraw[(size_t)d * 128 + e] + ba1[e];
        v = v > 0.0f ? v : 0.0f;
        s = fmaf(v, W2[(size_t)o * 128 + e], s);
    }
    s += ba2[o];
    __nv_bfloat16 hi = __float2bfloat16(s);
    d_xahi[t] = hi;
    d_xalo[t] = __float2bfloat16(s - __bfloat162float(hi));
}

// ---------------- launch (multi-stream graph DAG) ----------------
extern "C" void kernel_launch(void* const* d_in, const int* in_sizes, int n_in,
                              void* d_out, int out_size) {
    const float* x     = (const float*)d_in[0];
    const float* Ws1   = (const float*)d_in[1];
    const float* bs1   = (const float*)d_in[2];
    const float* Wg    = (const float*)d_in[3];
    const float* asrc  = (const float*)d_in[4];
    const float* adst  = (const float*)d_in[5];
    const float* bg    = (const float*)d_in[6];
    const float* Wa1   = (const float*)d_in[7];
    const float* ba1   = (const float*)d_in[8];
    const float* Wa2   = (const float*)d_in[9];
    const float* ba2   = (const float*)d_in[10];
    const void*  ei    = d_in[11];

    float* out   = (float*)d_out;
    float* out_x = out;                          // [12288, 512]
    float* out_s = out + (size_t)NN * DIN;       // [12288, 12288]

    const int SMEM_BIG = 73728;
    const int SMEM_G   = 55296;
    static int inited = 0;
    static cudaStream_t s1, s2;
    static cudaEvent_t e_scan, e_scat, e_tsplit, e_gat, e_xout;
    if (!inited) {
        cudaFuncSetAttribute(k_fc1_tc,  cudaFuncAttributeMaxDynamicSharedMemorySize, SMEM_BIG);
        cudaFuncSetAttribute(k_s_sym,   cudaFuncAttributeMaxDynamicSharedMemorySize, SMEM_BIG);
        cudaFuncSetAttribute(k_att1_tc, cudaFuncAttributeMaxDynamicSharedMemorySize, SMEM_BIG);
        cudaFuncSetAttribute(k_xout_tc, cudaFuncAttributeMaxDynamicSharedMemorySize, SMEM_BIG);
        cudaFuncSetAttribute(k_g_tc,    cudaFuncAttributeMaxDynamicSharedMemorySize, SMEM_G);
        cudaStreamCreateWithFlags(&s1, cudaStreamNonBlocking);
        cudaStreamCreateWithFlags(&s2, cudaStreamNonBlocking);
        cudaEventCreateWithFlags(&e_scan,   cudaEventDisableTiming);
        cudaEventCreateWithFlags(&e_scat,   cudaEventDisableTiming);
        cudaEventCreateWithFlags(&e_tsplit, cudaEventDisableTiming);
        cudaEventCreateWithFlags(&e_gat,    cudaEventDisableTiming);
        cudaEventCreateWithFlags(&e_xout,   cudaEventDisableTiming);
        inited = 1;
    }

    // ---- stream 0: CSR head ----
    k_detect<<<1, 256>>>((const int*)ei);
    k_init<<<256, 256>>>();
    k_count<<<NE / 256, 256>>>(ei);
    k_scan<<<1, 1024>>>();
    cudaEventRecord(e_scan, 0);

    // ---- s1: scatter branch (overlaps with splits/fc1) ----
    cudaStreamWaitEvent(s1, e_scan, 0);
    k_scatter<<<TOTE / 256, 256, 0, s1>>>(ei);
    cudaEventRecord(e_scat, s1);

    // ---- stream 0: splits + encoder ----
    k_splitw1<<<DEMB * DIN / 2048, 256>>>(Ws1);
    k_splitwg<<<DOUT * DEMB / 2048, 256>>>(Wg);
    k_splitwa1<<<DEMB * NN / 2048, 256>>>(Wa1);
    k_tsplit<<<dim3(NN / 64, DIN / 64), 256>>>(x);   // d_xhi/lo + d_xThi/lo
    cudaEventRecord(e_tsplit, 0);

    // ---- s2: attribute branch (overlaps with fc1/g/sc/gat) ----
    cudaStreamWaitEvent(s2, e_tsplit, 0);
    k_att1_tc<<<dim3(DIN / 128, 48), 256, SMEM_BIG, s2>>>();
    k_xa<<<(DIN * DOUT) / 256, 256, 0, s2>>>(ba1, Wa2, ba2);

    // ---- stream 0: encoder + GAT ----
    k_fc1_tc<<<NN / 128, 256, SMEM_BIG>>>(bs1);
    k_g_tc<<<NN / 128, 256, SMEM_G>>>();
    k_sc<<<NN / 8, 256>>>(asrc, adst);
    cudaStreamWaitEvent(0, e_scat, 0);
    k_gat<<<NN / 8, 256>>>(bg);                      // writes d_hhi/d_hlo
    cudaEventRecord(e_gat, 0);

    // ---- s2: xout (needs h + xa), concurrent with s_sym ----
    cudaStreamWaitEvent(s2, e_gat, 0);
    k_xout_tc<<<dim3(DIN / 128, NN / 128), 256, SMEM_BIG, s2>>>(out_x);
    cudaEventRecord(e_xout, s2);

    // ---- stream 0: structure decoder (dominant) ----
    k_s_sym<<<NTRI, 256, SMEM_BIG>>>(out_s);

    // join all branches back onto stream 0
    cudaStreamWaitEvent(0, e_xout, 0);
}

// round 16
// speedup vs baseline: 3.0694x; 1.1079x over previous
#include <cuda_runtime.h>
#include <cuda_bf16.h>
#include <cstdint>

#define NN   12288
#define DIN  512
#define DEMB 128
#define DOUT 64
#define NE   393216
#define TOTE (NE + NN)     // 405504
#define NEG  0.2f

// ---------------- scratch (device globals; no allocation) ----------------
__device__ __nv_bfloat16 d_x1hi[NN * DEMB];
__device__ __nv_bfloat16 d_x1lo[NN * DEMB];
__device__ float d_g[NN * DOUT];
__device__ float d_scs[NN];
__device__ float d_scd[NN];
__device__ __nv_bfloat16 d_hhi[NN * DOUT];
__device__ __nv_bfloat16 d_hlo[NN * DOUT];
__device__ __nv_bfloat16 d_xhi[NN * DIN];
__device__ __nv_bfloat16 d_xlo[NN * DIN];
__device__ __nv_bfloat16 d_xThi[DIN * NN];   // x^T, bf16 hi
__device__ __nv_bfloat16 d_xTlo[DIN * NN];
__device__ __nv_bfloat16 d_w1hi[DEMB * DIN];
__device__ __nv_bfloat16 d_w1lo[DEMB * DIN];
__device__ __nv_bfloat16 d_wa1hi[DEMB * NN];
__device__ __nv_bfloat16 d_wa1lo[DEMB * NN];
__device__ __nv_bfloat16 d_wghi[DOUT * DEMB];
__device__ __nv_bfloat16 d_wglo[DOUT * DEMB];
__device__ __nv_bfloat16 d_xahi[DIN * DOUT];
__device__ __nv_bfloat16 d_xalo[DIN * DOUT];
__device__ float d_xtraw[DIN * DEMB];
__device__ int   d_deg[NN];
__device__ int   d_off[NN + 1];
__device__ int   d_fill[NN];
__device__ int   d_csr[TOTE];
__device__ int   d_is64;

// ---------------- helpers ----------------
__device__ __forceinline__ float sigf(float v) {
    return __fdividef(1.0f, 1.0f + __expf(-v));
}
__device__ __forceinline__ int clampn(int v) {
    v = v < 0 ? 0 : v;
    return v >= NN ? NN - 1 : v;
}
__device__ __forceinline__ uint32_t smem_u32(const void* p) {
    return (uint32_t)__cvta_generic_to_shared(p);
}
__device__ __forceinline__ void ldm_x4(uint32_t& r0, uint32_t& r1, uint32_t& r2,
                                       uint32_t& r3, uint32_t addr) {
    asm volatile("ldmatrix.sync.aligned.m8n8.x4.shared.b16 {%0,%1,%2,%3}, [%4];"
                 : "=r"(r0), "=r"(r1), "=r"(r2), "=r"(r3) : "r"(addr));
}
__device__ __forceinline__ void mma_bf16(float* c, const uint32_t* a, const uint32_t* b) {
    asm volatile(
        "mma.sync.aligned.m16n8k16.row.col.f32.bf16.bf16.f32 "
        "{%0,%1,%2,%3}, {%4,%5,%6,%7}, {%8,%9}, {%0,%1,%2,%3};"
        : "+f"(c[0]), "+f"(c[1]), "+f"(c[2]), "+f"(c[3])
        : "r"(a[0]), "r"(a[1]), "r"(a[2]), "r"(a[3]), "r"(b[0]), "r"(b[1]));
}

// ---------------- dtype probe ----------------
__global__ void k_detect(const int* __restrict__ ei32) {
    __shared__ int any;
    if (threadIdx.x == 0) any = 0;
    __syncthreads();
    if (ei32[threadIdx.x * 2 + 1] != 0) any = 1;
    __syncthreads();
    if (threadIdx.x == 0) d_is64 = (any == 0) ? 1 : 0;
}

__global__ void k_init() {
    int t = blockIdx.x * blockDim.x + threadIdx.x;
    if (t < DIN * DEMB) d_xtraw[t] = 0.0f;
    if (t < NN) d_deg[t] = 1;
}

__global__ void k_count(const void* __restrict__ ei) {
    int e = blockIdx.x * blockDim.x + threadIdx.x;
    if (e < NE) {
        int dst;
        if (d_is64) dst = (int)((const long long*)ei)[NE + e];
        else        dst = ((const int*)ei)[NE + e];
        atomicAdd(&d_deg[clampn(dst)], 1);
    }
}

// warp-shuffle scan (12 values/thread via 3x int4, 1024 threads)
__global__ void k_scan() {
    __shared__ int wsum[32];
    int t = threadIdx.x, lane = t & 31, w = t >> 5;
    int base = t * 12;
    int loc[12];
#pragma unroll
    for (int q = 0; q < 3; q++) {
        int4 v = *(const int4*)&d_deg[base + q * 4];
        loc[q * 4 + 0] = v.x; loc[q * 4 + 1] = v.y;
        loc[q * 4 + 2] = v.z; loc[q * 4 + 3] = v.w;
    }
    int s = 0;
#pragma unroll
    for (int i = 0; i < 12; i++) s += loc[i];
    int pre = s;
#pragma unroll
    for (int o = 1; o < 32; o <<= 1) {
        int v = __shfl_up_sync(0xffffffffu, pre, o);
        if (lane >= o) pre += v;
    }
    if (lane == 31) wsum[w] = pre;
    __syncthreads();
    if (w == 0) {
        int v = wsum[lane];
#pragma unroll
        for (int o = 1; o < 32; o <<= 1) {
            int u = __shfl_up_sync(0xffffffffu, v, o);
            if (lane >= o) v += u;
        }
        wsum[lane] = v;
    }
    __syncthreads();
    int run = pre - s + (w ? wsum[w - 1] : 0);
#pragma unroll
    for (int i = 0; i < 12; i++) {
        d_off[base + i]  = run;
        d_fill[base + i] = run;
        run += loc[i];
    }
    if (t == 1023) d_off[NN] = run;
}

__global__ void k_scatter(const void* __restrict__ ei) {
    int e = blockIdx.x * blockDim.x + threadIdx.x;
    if (e < NE) {
        int src, dst;
        if (d_is64) {
            src = (int)((const long long*)ei)[e];
            dst = (int)((const long long*)ei)[NE + e];
        } else {
            src = ((const int*)ei)[e];
            dst = ((const int*)ei)[NE + e];
        }
        int p = atomicAdd(&d_fill[clampn(dst)], 1);
        if (p < TOTE) d_csr[p] = clampn(src);
    } else if (e < TOTE) {
        int n = e - NE;
        int p = atomicAdd(&d_fill[n], 1);
        if (p < TOTE) d_csr[p] = n;
    }
}

// ---------------- split kernels (vectorized: 8 elems/thread) ----------------
__device__ __forceinline__ void split8(const float* __restrict__ src,
                                       __nv_bfloat16* __restrict__ hi,
                                       __nv_bfloat16* __restrict__ lo, size_t base) {
    float4 v0 = *(const float4*)&src[base];
    float4 v1 = *(const float4*)&src[base + 4];
    float f[8] = {v0.x, v0.y, v0.z, v0.w, v1.x, v1.y, v1.z, v1.w};
    __nv_bfloat16 h[8], l[8];
#pragma unroll
    for (int i = 0; i < 8; i++) {
        h[i] = __float2bfloat16(f[i]);
        l[i] = __float2bfloat16(f[i] - __bfloat162float(h[i]));
    }
    *(uint4*)&hi[base] = *(uint4*)h;
    *(uint4*)&lo[base] = *(uint4*)l;
}
__global__ void k_splitw1(const float* __restrict__ W) {
    size_t base = (size_t)(blockIdx.x * blockDim.x + threadIdx.x) * 8;
    split8(W, d_w1hi, d_w1lo, base);
}
__global__ void k_splitwa1(const float* __restrict__ W) {
    size_t base = (size_t)(blockIdx.x * blockDim.x + threadIdx.x) * 8;
    split8(W, d_wa1hi, d_wa1lo, base);
}
__global__ void k_splitwg(const float* __restrict__ W) {
    size_t base = (size_t)(blockIdx.x * blockDim.x + threadIdx.x) * 8;
    split8(W, d_wghi, d_wglo, base);
}

// ---------------- transpose+split x: fills BOTH row-major (d_xhi/lo) AND x^T (d_xThi/lo) ----------------
__global__ __launch_bounds__(256) void k_tsplit(const float* __restrict__ x) {
    __shared__ __nv_bfloat16 shhi[64 * 68];
    __shared__ __nv_bfloat16 shlo[64 * 68];
    int k0 = blockIdx.x * 64, d0 = blockIdx.y * 64;
    int tid = threadIdx.x;
#pragma unroll
    for (int i = 0; i < 4; i++) {
        int slot = tid + i * 256;
        int kk = slot >> 4, q = slot & 15;
        float4 v = *(const float4*)&x[(size_t)(k0 + kk) * 512 + d0 + q * 4];
        __nv_bfloat16 h[4], l[4];
        float f[4] = {v.x, v.y, v.z, v.w};
#pragma unroll
        for (int u = 0; u < 4; u++) {
            h[u] = __float2bfloat16(f[u]);
            l[u] = __float2bfloat16(f[u] - __bfloat162float(h[u]));
        }
        *(uint2*)&d_xhi[(size_t)(k0 + kk) * 512 + d0 + q * 4] = *(uint2*)h;
        *(uint2*)&d_xlo[(size_t)(k0 + kk) * 512 + d0 + q * 4] = *(uint2*)l;
        *(uint2*)&shhi[kk * 68 + q * 4] = *(uint2*)h;
        *(uint2*)&shlo[kk * 68 + q * 4] = *(uint2*)l;
    }
    __syncthreads();
#pragma unroll
    for (int i = 0; i < 4; i++) {
        int slot = tid + i * 256;
        int arr = slot >> 9;
        int s2 = slot & 511;
        int dd = s2 >> 3, qc = s2 & 7;
        const __nv_bfloat16* sh = arr ? shlo : shhi;
        __nv_bfloat16 vals[8];
#pragma unroll
        for (int u = 0; u < 8; u++) vals[u] = sh[(qc * 8 + u) * 68 + dd];
        __nv_bfloat16* dst = arr ? d_xTlo : d_xThi;
        *(uint4*)&dst[(size_t)(d0 + dd) * NN + k0 + qc * 8] = *(uint4*)vals;
    }
}

#define SP 72    // operand smem pitch (halves)

// ---------------- x1 = relu(x @ W_s1^T + b) via bf16-split mma (outputs bf16 hi/lo) ----------------
__global__ __launch_bounds__(256) void k_fc1_tc(const float* __restrict__ b) {
    extern __shared__ __nv_bfloat16 sm[];
    __nv_bfloat16* sAh = sm;
    __nv_bfloat16* sAl = sm + 9216;
    __nv_bfloat16* sBh = sm + 18432;
    __nv_bfloat16* sBl = sm + 27648;

    int m0 = blockIdx.x * 128;
    int tid = threadIdx.x;
    int wid = tid >> 5, lane = tid & 31;
    int warp_m = (wid & 1) * 64;
    int warp_n = (wid >> 1) * 32;

    float acc[4][4][4];
#pragma unroll
    for (int i = 0; i < 4; i++)
#pragma unroll
        for (int j = 0; j < 4; j++)
#pragma unroll
            for (int c = 0; c < 4; c++) acc[i][j][c] = 0.0f;

    int a_row = lane & 15, a_kc = (lane >> 4) << 3;
    int b_row = (lane & 7) + (((lane >> 4) & 1) << 3);
    int b_kc  = (((lane >> 3) & 1) << 3);

    for (int kc = 0; kc < 512; kc += 64) {
#pragma unroll
        for (int r = 0; r < 4; r++) {
            int idx = tid + r * 256;
            int row = idx >> 3, ch = idx & 7;
            *(uint4*)&sAh[row * SP + ch * 8] =
                ((const uint4*)(d_xhi + (size_t)(m0 + row) * 512 + kc))[ch];
            *(uint4*)&sAl[row * SP + ch * 8] =
                ((const uint4*)(d_xlo + (size_t)(m0 + row) * 512 + kc))[ch];
            *(uint4*)&sBh[row * SP + ch * 8] =
                ((const uint4*)(d_w1hi + (size_t)row * 512 + kc))[ch];
            *(uint4*)&sBl[row * SP + ch * 8] =
                ((const uint4*)(d_w1lo + (size_t)row * 512 + kc))[ch];
        }
        __syncthreads();
#pragma unroll
        for (int ks = 0; ks < 4; ks++) {
            int k0 = ks * 16;
            uint32_t Bh[2][4], Bl[2][4];
#pragma unroll
            for (int nb = 0; nb < 2; nb++) {
                ldm_x4(Bh[nb][0], Bh[nb][1], Bh[nb][2], Bh[nb][3],
                       smem_u32(&sBh[(warp_n + nb * 16 + b_row) * SP + k0 + b_kc]));
                ldm_x4(Bl[nb][0], Bl[nb][1], Bl[nb][2], Bl[nb][3],
                       smem_u32(&sBl[(warp_n + nb * 16 + b_row) * SP + k0 + b_kc]));
            }
#pragma unroll
            for (int mt = 0; mt < 4; mt++) {
                uint32_t Ah[4], Al[4];
                ldm_x4(Ah[0], Ah[1], Ah[2], Ah[3],
                       smem_u32(&sAh[(warp_m + mt * 16 + a_row) * SP + k0 + a_kc]));
#pragma unroll
                for (int nt = 0; nt < 4; nt++)
                    mma_bf16(acc[mt][nt], Ah, &Bh[nt >> 1][(nt & 1) * 2]);
#pragma unroll
                for (int nt = 0; nt < 4; nt++)
                    mma_bf16(acc[mt][nt], Ah, &Bl[nt >> 1][(nt & 1) * 2]);
                ldm_x4(Al[0], Al[1], Al[2], Al[3],
                       smem_u32(&sAl[(warp_m + mt * 16 + a_row) * SP + k0 + a_kc]));
#pragma unroll
                for (int nt = 0; nt < 4; nt++)
                    mma_bf16(acc[mt][nt], Al, &Bh[nt >> 1][(nt & 1) * 2]);
            }
        }
        __syncthreads();
    }
#pragma unroll
    for (int mt = 0; mt < 4; mt++) {
        int r0 = m0 + warp_m + mt * 16 + (lane >> 2);
#pragma unroll
        for (int nt = 0; nt < 4; nt++) {
            int c = warp_n + nt * 8 + ((lane & 3) << 1);
            float b0 = b[c], b1 = b[c + 1];
            float v00 = fmaxf(acc[mt][nt][0] + b0, 0.0f);
            float v01 = fmaxf(acc[mt][nt][1] + b1, 0.0f);
            float v10 = fmaxf(acc[mt][nt][2] + b0, 0.0f);
            float v11 = fmaxf(acc[mt][nt][3] + b1, 0.0f);
            __nv_bfloat16 h00 = __float2bfloat16(v00), h01 = __float2bfloat16(v01);
            __nv_bfloat16 h10 = __float2bfloat16(v10), h11 = __float2bfloat16(v11);
            __nv_bfloat162 p;
            p.x = h00; p.y = h01;
            *(__nv_bfloat162*)&d_x1hi[(size_t)r0 * 128 + c] = p;
            p.x = __float2bfloat16(v00 - __bfloat162float(h00));
            p.y = __float2bfloat16(v01 - __bfloat162float(h01));
            *(__nv_bfloat162*)&d_x1lo[(size_t)r0 * 128 + c] = p;
            p.x = h10; p.y = h11;
            *(__nv_bfloat162*)&d_x1hi[(size_t)(r0 + 8) * 128 + c] = p;
            p.x = __float2bfloat16(v10 - __bfloat162float(h10));
            p.y = __float2bfloat16(v11 - __bfloat162float(h11));
            *(__nv_bfloat162*)&d_x1lo[(size_t)(r0 + 8) * 128 + c] = p;
        }
    }
}

// ---------------- g = x1 @ W_g^T via bf16-split mma (128x64 tile) ----------------
__global__ __launch_bounds__(256) void k_g_tc() {
    extern __shared__ __nv_bfloat16 sm[];
    __nv_bfloat16* sAh = sm;
    __nv_bfloat16* sAl = sm + 9216;
    __nv_bfloat16* sBh = sm + 18432;
    __nv_bfloat16* sBl = sm + 23040;

    int m0 = blockIdx.x * 128;
    int tid = threadIdx.x;
    int wid = tid >> 5, lane = tid & 31;
    int warp_m = (wid >> 2) * 64;
    int warp_n = (wid & 3) * 16;

    float acc[4][2][4];
#pragma unroll
    for (int a = 0; a < 4; a++)
#pragma unroll
        for (int b = 0; b < 2; b++)
#pragma unroll
            for (int c = 0; c < 4; c++) acc[a][b][c] = 0.0f;

    int a_row = lane & 15, a_kc = (lane >> 4) << 3;
    int b_row = (lane & 7) + (((lane >> 4) & 1) << 3);
    int b_kc  = (((lane >> 3) & 1) << 3);

    for (int kc = 0; kc < 128; kc += 64) {
#pragma unroll
        for (int r = 0; r < 4; r++) {
            int idx = tid + r * 256;
            int row = idx >> 3, ch = idx & 7;
            *(uint4*)&sAh[row * SP + ch * 8] =
                ((const uint4*)(d_x1hi + (size_t)(m0 + row) * 128 + kc))[ch];
            *(uint4*)&sAl[row * SP + ch * 8] =
                ((const uint4*)(d_x1lo + (size_t)(m0 + row) * 128 + kc))[ch];
        }
#pragma unroll
        for (int r = 0; r < 2; r++) {
            int idx = tid + r * 256;
            int row = idx >> 3, ch = idx & 7;
            *(uint4*)&sBh[row * SP + ch * 8] =
                ((const uint4*)(d_wghi + (size_t)row * 128 + kc))[ch];
            *(uint4*)&sBl[row * SP + ch * 8] =
                ((const uint4*)(d_wglo + (size_t)row * 128 + kc))[ch];
        }
        __syncthreads();
#pragma unroll
        for (int ks = 0; ks < 4; ks++) {
            int k0 = ks * 16;
            uint32_t Bh[4], Bl[4];
            ldm_x4(Bh[0], Bh[1], Bh[2], Bh[3],
                   smem_u32(&sBh[(warp_n + b_row) * SP + k0 + b_kc]));
            ldm_x4(Bl[0], Bl[1], Bl[2], Bl[3],
                   smem_u32(&sBl[(warp_n + b_row) * SP + k0 + b_kc]));
#pragma unroll
            for (int mt = 0; mt < 4; mt++) {
                uint32_t Ah[4], Al[4];
                ldm_x4(Ah[0], Ah[1], Ah[2], Ah[3],
                       smem_u32(&sAh[(warp_m + mt * 16 + a_row) * SP + k0 + a_kc]));
                mma_bf16(acc[mt][0], Ah, &Bh[0]);
                mma_bf16(acc[mt][1], Ah, &Bh[2]);
                mma_bf16(acc[mt][0], Ah, &Bl[0]);
                mma_bf16(acc[mt][1], Ah, &Bl[2]);
                ldm_x4(Al[0], Al[1], Al[2], Al[3],
                       smem_u32(&sAl[(warp_m + mt * 16 + a_row) * SP + k0 + a_kc]));
                mma_bf16(acc[mt][0], Al, &Bh[0]);
                mma_bf16(acc[mt][1], Al, &Bh[2]);
            }
        }
        __syncthreads();
    }
#pragma unroll
    for (int mt = 0; mt < 4; mt++) {
        int r0 = m0 + warp_m + mt * 16 + (lane >> 2);
#pragma unroll
        for (int nt = 0; nt < 2; nt++) {
            int c0 = warp_n + nt * 8 + ((lane & 3) << 1);
            d_g[(size_t)r0 * 64 + c0]           = acc[mt][nt][0];
            d_g[(size_t)r0 * 64 + c0 + 1]       = acc[mt][nt][1];
            d_g[(size_t)(r0 + 8) * 64 + c0]     = acc[mt][nt][2];
            d_g[(size_t)(r0 + 8) * 64 + c0 + 1] = acc[mt][nt][3];
        }
    }
}

// ---------------- attention scores ----------------
__global__ void k_sc(const float* __restrict__ asrc, const float* __restrict__ adst) {
    int warp = (blockIdx.x * blockDim.x + threadIdx.x) >> 5;
    int lane = threadIdx.x & 31;
    if (warp >= NN) return;
    float g0 = d_g[(size_t)warp * 64 + lane];
    float g1 = d_g[(size_t)warp * 64 + 32 + lane];
    float vs = g0 * asrc[lane] + g1 * asrc[32 + lane];
    float vd = g0 * adst[lane] + g1 * adst[32 + lane];
#pragma unroll
    for (int o = 16; o; o >>= 1) {
        vs += __shfl_xor_sync(0xffffffffu, vs, o);
        vd += __shfl_xor_sync(0xffffffffu, vd, o);
    }
    if (lane == 0) { d_scs[warp] = vs; d_scd[warp] = vd; }
}

// ---------------- GAT aggregation (fused h-split: writes d_hhi/d_hlo directly) ----------------
__global__ void k_gat(const float* __restrict__ bg) {
    int warp = (blockIdx.x * blockDim.x + threadIdx.x) >> 5;
    int lane = threadIdx.x & 31;
    if (warp >= NN) return;
    int s0 = d_off[warp], s1 = d_off[warp + 1];
    float scd = d_scd[warp];

    float mx = -1e30f;
    for (int j = s0 + lane; j < s1; j += 32) {
        int s = d_csr[j];
        float e = d_scs[s] + scd;
        e = e > 0.0f ? e : NEG * e;
        mx = fmaxf(mx, e);
    }
#pragma unroll
    for (int o = 16; o; o >>= 1) mx = fmaxf(mx, __shfl_xor_sync(0xffffffffu, mx, o));

    float sum = 0.0f, a0 = 0.0f, a1 = 0.0f;
    for (int jb = s0; jb < s1; jb += 32) {
        int j = jb + lane;
        float w = 0.0f;
        int sidx = 0;
        if (j < s1) {
            sidx = d_csr[j];
            float e = d_scs[sidx] + scd;
            e = e > 0.0f ? e : NEG * e;
            w = __expf(e - mx);
        }
        sum += w;
        int cnt = s1 - jb;
        if (cnt > 32) cnt = 32;
        for (int u = 0; u < cnt; u++) {
            float wu = __shfl_sync(0xffffffffu, w, u);
            int su = __shfl_sync(0xffffffffu, sidx, u);
            a0 = fmaf(wu, d_g[(size_t)su * 64 + lane], a0);
            a1 = fmaf(wu, d_g[(size_t)su * 64 + 32 + lane], a1);
        }
    }
#pragma unroll
    for (int o = 16; o; o >>= 1) sum += __shfl_xor_sync(0xffffffffu, sum, o);
    float inv = __fdividef(1.0f, sum);

    float h0 = a0 * inv + bg[lane];
    float h1 = a1 * inv + bg[32 + lane];
    __nv_bfloat16 p0 = __float2bfloat16(h0);
    __nv_bfloat16 p1 = __float2bfloat16(h1);
    d_hhi[(size_t)warp * 64 + lane]      = p0;
    d_hlo[(size_t)warp * 64 + lane]      = __float2bfloat16(h0 - __bfloat162float(p0));
    d_hhi[(size_t)warp * 64 + 32 + lane] = p1;
    d_hlo[(size_t)warp * 64 + 32 + lane] = __float2bfloat16(h1 - __bfloat162float(p1));
}

// ---------------- common bf16-split 128x128xK=64 mma body ----------------
__device__ __forceinline__ void mma_tile_128x128_k64(
    const __nv_bfloat16* pAh, const __nv_bfloat16* pAl,
    const __nv_bfloat16* pBh, const __nv_bfloat16* pBl,
    int i0, int j0, float acc[4][4][4],
    __nv_bfloat16* sAh, __nv_bfloat16* sAl, __nv_bfloat16* sBh, __nv_bfloat16* sBl,
    int tid, int warp_m, int warp_n, int lane)
{
#pragma unroll
    for (int r = 0; r < 4; r++) {
        int idx = tid + r * 256;
        int row = idx >> 3, ch = idx & 7;
        *(uint4*)&sAh[row * SP + ch * 8] = ((const uint4*)(pAh + (size_t)(i0 + row) * 64))[ch];
        *(uint4*)&sAl[row * SP + ch * 8] = ((const uint4*)(pAl + (size_t)(i0 + row) * 64))[ch];
        *(uint4*)&sBh[row * SP + ch * 8] = ((const uint4*)(pBh + (size_t)(j0 + row) * 64))[ch];
        *(uint4*)&sBl[row * SP + ch * 8] = ((const uint4*)(pBl + (size_t)(j0 + row) * 64))[ch];
    }
    __syncthreads();

    int a_row = lane & 15, a_kc = (lane >> 4) << 3;
    int b_row = (lane & 7) + (((lane >> 4) & 1) << 3);
    int b_kc  = (((lane >> 3) & 1) << 3);

#pragma unroll
    for (int ks = 0; ks < 4; ks++) {
        int k0 = ks * 16;
        uint32_t Bh[2][4], Bl[2][4];
#pragma unroll
        for (int nb = 0; nb < 2; nb++) {
            ldm_x4(Bh[nb][0], Bh[nb][1], Bh[nb][2], Bh[nb][3],
                   smem_u32(&sBh[(warp_n + nb * 16 + b_row) * SP + k0 + b_kc]));
            ldm_x4(Bl[nb][0], Bl[nb][1], Bl[nb][2], Bl[nb][3],
                   smem_u32(&sBl[(warp_n + nb * 16 + b_row) * SP + k0 + b_kc]));
        }
#pragma unroll
        for (int mt = 0; mt < 4; mt++) {
            uint32_t Ah[4], Al[4];
            ldm_x4(Ah[0], Ah[1], Ah[2], Ah[3],
                   smem_u32(&sAh[(warp_m + mt * 16 + a_row) * SP + k0 + a_kc]));
#pragma unroll
            for (int nt = 0; nt < 4; nt++)
                mma_bf16(acc[mt][nt], Ah, &Bh[nt >> 1][(nt & 1) * 2]);
#pragma unroll
            for (int nt = 0; nt < 4; nt++)
                mma_bf16(acc[mt][nt], Ah, &Bl[nt >> 1][(nt & 1) * 2]);
            ldm_x4(Al[0], Al[1], Al[2], Al[3],
                   smem_u32(&sAl[(warp_m + mt * 16 + a_row) * SP + k0 + a_kc]));
#pragma unroll
            for (int nt = 0; nt < 4; nt++)
                mma_bf16(acc[mt][nt], Al, &Bh[nt >> 1][(nt & 1) * 2]);
        }
    }
    __syncthreads();   // operand smem dead after this
}

// ---------------- s_ = sigmoid(h h^T): SYMMETRIC, triangular linearized grid ----------------
#define CP3 129
#define NTRI 4656
__global__ __launch_bounds__(256) void k_s_sym(float* __restrict__ out) {
    int p = blockIdx.x;
    int it = (int)((193.0f - sqrtf(193.0f * 193.0f - 8.0f * (float)p)) * 0.5f);
    while ((it + 1) * (193 - (it + 1)) / 2 <= p) it++;
    while (it * (193 - it) / 2 > p) it--;
    int jt = it + (p - it * (193 - it) / 2);

    extern __shared__ __nv_bfloat16 sm[];
    __nv_bfloat16* sAh = sm;
    __nv_bfloat16* sAl = sm + 9216;
    __nv_bfloat16* sBh = sm + 18432;
    __nv_bfloat16* sBl = sm + 27648;
    float* Cs = (float*)sm;             // [128][129] after compute

    int i0 = it * 128, j0 = jt * 128;
    int tid = threadIdx.x;
    int wid = tid >> 5, lane = tid & 31;
    int warp_m = (wid & 1) * 64;
    int warp_n = (wid >> 1) * 32;

    float acc[4][4][4];
#pragma unroll
    for (int i = 0; i < 4; i++)
#pragma unroll
        for (int j = 0; j < 4; j++)
#pragma unroll
            for (int c = 0; c < 4; c++) acc[i][j][c] = 0.0f;

    mma_tile_128x128_k64(d_hhi, d_hlo, d_hhi, d_hlo, i0, j0, acc,
                         sAh, sAl, sBh, sBl, tid, warp_m, warp_n, lane);

#pragma unroll
    for (int mt = 0; mt < 4; mt++) {
        int r0 = warp_m + mt * 16 + (lane >> 2);
#pragma unroll
        for (int nt = 0; nt < 4; nt++) {
            int c0 = warp_n + nt * 8 + ((lane & 3) << 1);
            Cs[r0 * CP3 + c0]           = sigf(acc[mt][nt][0]);
            Cs[r0 * CP3 + c0 + 1]       = sigf(acc[mt][nt][1]);
            Cs[(r0 + 8) * CP3 + c0]     = sigf(acc[mt][nt][2]);
            Cs[(r0 + 8) * CP3 + c0 + 1] = sigf(acc[mt][nt][3]);
        }
    }
    __syncthreads();

#pragma unroll 4
    for (int itr = 0; itr < 64; itr++) {
        int slot = tid + itr * 256;
        int row = slot >> 7, col = slot & 127;
        out[(size_t)(i0 + row) * NN + j0 + col] = Cs[row * CP3 + col];
    }
    if (jt > it) {
#pragma unroll 4
        for (int itr = 0; itr < 64; itr++) {
            int slot = tid + itr * 256;
            int c = slot >> 7, r = slot & 127;
            out[(size_t)(j0 + c) * NN + i0 + r] = Cs[r * CP3 + c];
        }
    }
}

// ---------------- x_ = h @ xa^T via bf16-split mma ----------------
__global__ __launch_bounds__(256) void k_xout_tc(float* __restrict__ out) {
    extern __shared__ __nv_bfloat16 sm[];
    __nv_bfloat16* sAh = sm;
    __nv_bfloat16* sAl = sm + 9216;
    __nv_bfloat16* sBh = sm + 18432;
    __nv_bfloat16* sBl = sm + 27648;
    float* Cs = (float*)sm;

    int i0 = blockIdx.y * 128, j0 = blockIdx.x * 128;
    int tid = threadIdx.x;
    int wid = tid >> 5, lane = tid & 31;
    int warp_m = (wid & 1) * 64;
    int warp_n = (wid >> 1) * 32;

    float acc[4][4][4];
#pragma unroll
    for (int i = 0; i < 4; i++)
#pragma unroll
        for (int j = 0; j < 4; j++)
#pragma unroll
            for (int c = 0; c < 4; c++) acc[i][j][c] = 0.0f;

    mma_tile_128x128_k64(d_hhi, d_hlo, d_xahi, d_xalo, i0, j0, acc,
                         sAh, sAl, sBh, sBl, tid, warp_m, warp_n, lane);

#pragma unroll
    for (int mt = 0; mt < 4; mt++) {
        int r0 = warp_m + mt * 16 + (lane >> 2);
#pragma unroll
        for (int nt = 0; nt < 4; nt++) {
            int c0 = warp_n + nt * 8 + ((lane & 3) << 1);
            Cs[r0 * CP3 + c0]           = acc[mt][nt][0];
            Cs[r0 * CP3 + c0 + 1]       = acc[mt][nt][1];
            Cs[(r0 + 8) * CP3 + c0]     = acc[mt][nt][2];
            Cs[(r0 + 8) * CP3 + c0 + 1] = acc[mt][nt][3];
        }
    }
    __syncthreads();
#pragma unroll 4
    for (int itr = 0; itr < 64; itr++) {
        int slot = tid + itr * 256;
        int row = slot >> 7, col = slot & 127;
        out[(size_t)(i0 + row) * 512 + j0 + col] = Cs[row * CP3 + col];
    }
}

// ---------------- xtraw = x^T @ W_a1^T via bf16-split mma (48 K-slabs, atomic accum) ----------------
__global__ __launch_bounds__(256) void k_att1_tc() {
    extern __shared__ __nv_bfloat16 sm[];
    __nv_bfloat16* sAh = sm;
    __nv_bfloat16* sAl = sm + 9216;
    __nv_bfloat16* sBh = sm + 18432;
    __nv_bfloat16* sBl = sm + 27648;

    int m0 = blockIdx.x * 128;
    int kbase = blockIdx.y * 256;
    int tid = threadIdx.x;
    int wid = tid >> 5, lane = tid & 31;
    int warp_m = (wid & 1) * 64;
    int warp_n = (wid >> 1) * 32;

    float acc[4][4][4];
#pragma unroll
    for (int i = 0; i < 4; i++)
#pragma unroll
        for (int j = 0; j < 4; j++)
#pragma unroll
            for (int c = 0; c < 4; c++) acc[i][j][c] = 0.0f;

    int a_row = lane & 15, a_kc = (lane >> 4) << 3;
    int b_row = (lane & 7) + (((lane >> 4) & 1) << 3);
    int b_kc  = (((lane >> 3) & 1) << 3);

    for (int kc = 0; kc < 256; kc += 64) {
        int kk = kbase + kc;
#pragma unroll
        for (int r = 0; r < 4; r++) {
            int idx = tid + r * 256;
            int row = idx >> 3, ch = idx & 7;
            *(uint4*)&sAh[row * SP + ch * 8] =
                ((const uint4*)(d_xThi + (size_t)(m0 + row) * NN + kk))[ch];
            *(uint4*)&sAl[row * SP + ch * 8] =
                ((const uint4*)(d_xTlo + (size_t)(m0 + row) * NN + kk))[ch];
            *(uint4*)&sBh[row * SP + ch * 8] =
                ((const uint4*)(d_wa1hi + (size_t)row * NN + kk))[ch];
            *(uint4*)&sBl[row * SP + ch * 8] =
                ((const uint4*)(d_wa1lo + (size_t)row * NN + kk))[ch];
        }
        __syncthreads();
#pragma unroll
        for (int ks = 0; ks < 4; ks++) {
            int k0 = ks * 16;
            uint32_t Bh[2][4], Bl[2][4];
#pragma unroll
            for (int nb = 0; nb < 2; nb++) {
                ldm_x4(Bh[nb][0], Bh[nb][1], Bh[nb][2], Bh[nb][3],
                       smem_u32(&sBh[(warp_n + nb * 16 + b_row) * SP + k0 + b_kc]));
                ldm_x4(Bl[nb][0], Bl[nb][1], Bl[nb][2], Bl[nb][3],
                       smem_u32(&sBl[(warp_n + nb * 16 + b_row) * SP + k0 + b_kc]));
            }
#pragma unroll
            for (int mt = 0; mt < 4; mt++) {
                uint32_t Ah[4], Al[4];
                ldm_x4(Ah[0], Ah[1], Ah[2], Ah[3],
                       smem_u32(&sAh[(warp_m + mt * 16 + a_row) * SP + k0 + a_kc]));
#pragma unroll
                for (int nt = 0; nt < 4; nt++)
                    mma_bf16(acc[mt][nt], Ah, &Bh[nt >> 1][(nt & 1) * 2]);
#pragma unroll
                for (int nt = 0; nt < 4; nt++)
                    mma_bf16(acc[mt][nt], Ah, &Bl[nt >> 1][(nt & 1) * 2]);
                ldm_x4(Al[0], Al[1], Al[2], Al[3],
                       smem_u32(&sAl[(warp_m + mt * 16 + a_row) * SP + k0 + a_kc]));
#pragma unroll
                for (int nt = 0; nt < 4; nt++)
                    mma_bf16(acc[mt][nt], Al, &Bh[nt >> 1][(nt & 1) * 2]);
            }
        }
        __syncthreads();
    }
#pragma unroll
    for (int mt = 0; mt < 4; mt++) {
        int r0 = m0 + warp_m + mt * 16 + (lane >> 2);
#pragma unroll
        for (int nt = 0; nt < 4; nt++) {
            int c = warp_n + nt * 8 + ((lane & 3) << 1);
            atomicAdd(&d_xtraw[(size_t)r0 * 128 + c],           acc[mt][nt][0]);
            atomicAdd(&d_xtraw[(size_t)r0 * 128 + c + 1],       acc[mt][nt][1]);
            atomicAdd(&d_xtraw[(size_t)(r0 + 8) * 128 + c],     acc[mt][nt][2]);
            atomicAdd(&d_xtraw[(size_t)(r0 + 8) * 128 + c + 1], acc[mt][nt][3]);
        }
    }
}

// ---------------- xa = relu(xtraw + ba1) @ W2^T + ba2, fused bf16 split ----------------
__global__ void k_xa(const float* __restrict__ ba1, const float* __restrict__ W2,
                     const float* __restrict__ ba2) {
    int t = blockIdx.x * blockDim.x + threadIdx.x;
    if (t >= DIN * DOUT) return;
    int d = t >> 6, o = t & 63;
    float s = 0.0f;
#pragma unroll 4
    for (int e = 0; e < 128; e++) {
        float v = d_xtraw[(size_t)d * 128 + e] + ba1[e];
        v = v > 0.0f ? v : 0.0f;
        s = fmaf(v, W2[(size_t)o * 128 + e], s);
    }
    s += ba2[o];
    __nv_bfloat16 hi = __float2bfloat16(s);
    d_xahi[t] = hi;
    d_xalo[t] = __float2bfloat16(s - __bfloat162float(hi));
}

// ---------------- launch (multi-stream graph DAG) ----------------
extern "C" void kernel_launch(void* const* d_in, const int* in_sizes, int n_in,
                              void* d_out, int out_size) {
    const float* x     = (const float*)d_in[0];
    const float* Ws1   = (const float*)d_in[1];
    const float* bs1   = (const float*)d_in[2];
    const float* Wg    = (const float*)d_in[3];
    const float* asrc  = (const float*)d_in[4];
    const float* adst  = (const float*)d_in[5];
    const float* bg    = (const float*)d_in[6];
    const float* Wa1   = (const float*)d_in[7];
    const float* ba1   = (const float*)d_in[8];
    const float* Wa2   = (const float*)d_in[9];
    const float* ba2   = (const float*)d_in[10];
    const void*  ei    = d_in[11];

    float* out   = (float*)d_out;
    float* out_x = out;                          // [12288, 512]
    float* out_s = out + (size_t)NN * DIN;       // [12288, 12288]

    const int SMEM_BIG = 73728;
    const int SMEM_G   = 55296;
    static int inited = 0;
    static cudaStream_t s1, s2;
    static cudaEvent_t e_head, e_scat, e_tsplit, e_gat, e_xout;
    if (!inited) {
        cudaFuncSetAttribute(k_fc1_tc,  cudaFuncAttributeMaxDynamicSharedMemorySize, SMEM_BIG);
        cudaFuncSetAttribute(k_s_sym,   cudaFuncAttributeMaxDynamicSharedMemorySize, SMEM_BIG);
        cudaFuncSetAttribute(k_att1_tc, cudaFuncAttributeMaxDynamicSharedMemorySize, SMEM_BIG);
        cudaFuncSetAttribute(k_xout_tc, cudaFuncAttributeMaxDynamicSharedMemorySize, SMEM_BIG);
        cudaFuncSetAttribute(k_g_tc,    cudaFuncAttributeMaxDynamicSharedMemorySize, SMEM_G);
        cudaStreamCreateWithFlags(&s1, cudaStreamNonBlocking);
        cudaStreamCreateWithFlags(&s2, cudaStreamNonBlocking);
        cudaEventCreateWithFlags(&e_head,   cudaEventDisableTiming);
        cudaEventCreateWithFlags(&e_scat,   cudaEventDisableTiming);
        cudaEventCreateWithFlags(&e_tsplit, cudaEventDisableTiming);
        cudaEventCreateWithFlags(&e_gat,    cudaEventDisableTiming);
        cudaEventCreateWithFlags(&e_xout,   cudaEventDisableTiming);
        inited = 1;
    }

    // ---- stream 0: tiny head (detect for all edge readers, init for count/att1) ----
    k_detect<<<1, 256>>>((const int*)ei);
    k_init<<<256, 256>>>();
    cudaEventRecord(e_head, 0);

    // ---- s1: full CSR branch (count -> scan -> scatter) off the critical path ----
    cudaStreamWaitEvent(s1, e_head, 0);
    k_count<<<NE / 256, 256, 0, s1>>>(ei);
    k_scan<<<1, 1024, 0, s1>>>();
    k_scatter<<<TOTE / 256, 256, 0, s1>>>(ei);
    cudaEventRecord(e_scat, s1);

    // ---- stream 0: critical-path splits + encoder ----
    k_splitw1<<<DEMB * DIN / 2048, 256>>>(Ws1);
    k_tsplit<<<dim3(NN / 64, DIN / 64), 256>>>(x);   // d_xhi/lo + d_xThi/lo
    cudaEventRecord(e_tsplit, 0);
    k_splitwg<<<DOUT * DEMB / 2048, 256>>>(Wg);

    // ---- s2: attribute branch (overlaps with fc1/g/sc/gat) ----
    cudaStreamWaitEvent(s2, e_head, 0);      // needs d_xtraw zeroed
    k_splitwa1<<<DEMB * NN / 2048, 256, 0, s2>>>(Wa1);
    cudaStreamWaitEvent(s2, e_tsplit, 0);    // needs d_xThi/lo
    k_att1_tc<<<dim3(DIN / 128, 48), 256, SMEM_BIG, s2>>>();
    k_xa<<<(DIN * DOUT) / 256, 256, 0, s2>>>(ba1, Wa2, ba2);

    // ---- stream 0: encoder + GAT ----
    k_fc1_tc<<<NN / 128, 256, SMEM_BIG>>>(bs1);
    k_g_tc<<<NN / 128, 256, SMEM_G>>>();
    k_sc<<<NN / 8, 256>>>(asrc, adst);
    cudaStreamWaitEvent(0, e_scat, 0);
    k_gat<<<NN / 8, 256>>>(bg);                      // writes d_hhi/d_hlo
    cudaEventRecord(e_gat, 0);

    // ---- s2: xout (needs h + xa), concurrent with s_sym ----
    cudaStreamWaitEvent(s2, e_gat, 0);
    k_xout_tc<<<dim3(DIN / 128, NN / 128), 256, SMEM_BIG, s2>>>(out_x);
    cudaEventRecord(e_xout, s2);

    // ---- stream 0: structure decoder (dominant) ----
    k_s_sym<<<NTRI, 256, SMEM_BIG>>>(out_s);

    // join all branches back onto stream 0
    cudaStreamWaitEvent(0, e_xout, 0);
}